// round 1
// baseline (speedup 1.0000x reference)
#include <cuda_runtime.h>
#include <math.h>

// Problem dims
#define BB   4
#define SS   512
#define DD   1024
#define HH   16
#define LL   6
#define FFD  4096
#define VV   32000
#define DKK  64
#define NTOK (BB*SS)   // 2048

// Scratch (device globals — no allocation allowed)
__device__ float g_x[NTOK*DD];
__device__ float g_h[NTOK*DD];
__device__ float g_q[NTOK*DD];
__device__ float g_k[NTOK*DD];
__device__ float g_v[NTOK*DD];
__device__ float g_attn[NTOK*DD];
__device__ float g_ff[NTOK*FFD];

// ---------------------------------------------------------------------------
// Embedding + (batch-indexed!) positional encoding:
//   x[b,s,:] = emb[ids[b,s],:] + pe[b,:]   (reference indexes pe by BATCH)
// ---------------------------------------------------------------------------
__global__ void embed_kernel(const int* __restrict__ ids,
                             const float* __restrict__ emb,
                             const float* __restrict__ pe,
                             float* __restrict__ x) {
    int row = blockIdx.x;           // 0..NTOK-1
    int b   = row / SS;
    int id  = ids[row];
    const float* er = emb + (size_t)id * DD;
    const float* pr = pe  + (size_t)b  * DD;
    float* xr = x + (size_t)row * DD;
    for (int d = threadIdx.x; d < DD; d += 256)
        xr[d] = er[d] + pr[d];
}

// ---------------------------------------------------------------------------
// LayerNorm: one block per row of D=1024
// ---------------------------------------------------------------------------
__global__ void ln_kernel(const float* __restrict__ x,
                          const float* __restrict__ s,
                          const float* __restrict__ b,
                          float* __restrict__ y) {
    int row = blockIdx.x;
    int t = threadIdx.x;
    const float* xr = x + (size_t)row * DD;
    float s1 = 0.f, s2 = 0.f;
    for (int i = t; i < DD; i += 256) {
        float v = xr[i];
        s1 += v; s2 += v * v;
    }
    __shared__ float r1[256], r2[256];
    r1[t] = s1; r2[t] = s2;
    __syncthreads();
    for (int st = 128; st > 0; st >>= 1) {
        if (t < st) { r1[t] += r1[t + st]; r2[t] += r2[t + st]; }
        __syncthreads();
    }
    __shared__ float sm_mean, sm_rstd;
    if (t == 0) {
        float mean = r1[0] * (1.0f / DD);
        float var  = r2[0] * (1.0f / DD) - mean * mean;
        sm_mean = mean;
        sm_rstd = rsqrtf(var + 1e-5f);
    }
    __syncthreads();
    float mean = sm_mean, rstd = sm_rstd;
    float* yr = y + (size_t)row * DD;
    for (int i = t; i < DD; i += 256)
        yr[i] = (xr[i] - mean) * rstd * s[i] + b[i];
}

// ---------------------------------------------------------------------------
// SGEMM: C[M,N] = A[M,K] @ B (+bias).  TB=false: B is [K,N]; TB=true: B is [N,K].
// All M,N multiples of 128; K multiple of 16 (true for all call sites).
// 128x128 block tile, BK=16, 256 threads, 8x8 microtile.
// ---------------------------------------------------------------------------
template <bool TB>
__global__ __launch_bounds__(256)
void gemm_kernel(const float* __restrict__ A, const float* __restrict__ B,
                 const float* __restrict__ bias, float* __restrict__ C,
                 int M, int N, int K) {
    const int BM = 128, BN = 128, BK = 16;
    __shared__ float As[BK][BM];
    __shared__ float Bs[BK][BN];
    int t  = threadIdx.x;
    int m0 = blockIdx.y * BM;
    int n0 = blockIdx.x * BN;
    int tx = t & 15;     // 0..15  -> n
    int ty = t >> 4;     // 0..15  -> m
    float acc[8][8];
    #pragma unroll
    for (int i = 0; i < 8; i++)
        #pragma unroll
        for (int j = 0; j < 8; j++) acc[i][j] = 0.f;

    for (int k0 = 0; k0 < K; k0 += BK) {
        // Load A tile (2048 elems, 8/thread), consecutive threads read consecutive k
        #pragma unroll
        for (int i = 0; i < 8; i++) {
            int lin = t + i * 256;
            int m  = lin >> 4;
            int kk = lin & 15;
            As[kk][m] = A[(size_t)(m0 + m) * K + k0 + kk];
        }
        // Load B tile
        #pragma unroll
        for (int i = 0; i < 8; i++) {
            int lin = t + i * 256;
            if (!TB) {
                int kk = lin >> 7;      // 0..15
                int n  = lin & 127;
                Bs[kk][n] = B[(size_t)(k0 + kk) * N + n0 + n];
            } else {
                int n  = lin >> 4;
                int kk = lin & 15;
                Bs[kk][n] = B[(size_t)(n0 + n) * K + k0 + kk];
            }
        }
        __syncthreads();
        #pragma unroll
        for (int kk = 0; kk < BK; kk++) {
            float ra[8], rb[8];
            #pragma unroll
            for (int i = 0; i < 8; i++) ra[i] = As[kk][ty * 8 + i];
            #pragma unroll
            for (int j = 0; j < 8; j++) rb[j] = Bs[kk][tx * 8 + j];
            #pragma unroll
            for (int i = 0; i < 8; i++)
                #pragma unroll
                for (int j = 0; j < 8; j++)
                    acc[i][j] += ra[i] * rb[j];
        }
        __syncthreads();
    }

    #pragma unroll
    for (int i = 0; i < 8; i++) {
        int m = m0 + ty * 8 + i;
        #pragma unroll
        for (int j = 0; j < 8; j++) {
            int n = n0 + tx * 8 + j;
            float v = acc[i][j];
            if (bias) v += bias[n];
            C[(size_t)m * N + n] = v;
        }
    }
}

// ---------------------------------------------------------------------------
// Causal attention, one block (128 thr) per (b,h,q). Exact softmax over k<=q.
// Q/K/V layout: [B,S,H*DK] (contiguous reshape of [B,S,D]).
// ---------------------------------------------------------------------------
__global__ __launch_bounds__(128)
void attn_kernel(const float* __restrict__ Q, const float* __restrict__ K,
                 const float* __restrict__ V, float* __restrict__ O) {
    int idx  = blockIdx.x;
    int qpos = idx % SS;
    int bh   = idx / SS;
    int h    = bh % HH;
    int b    = bh / HH;
    int t    = threadIdx.x;

    __shared__ float qs[DKK];
    __shared__ float sc[SS];
    __shared__ float red[128];

    const float* qr = Q + ((size_t)(b * SS + qpos)) * DD + h * DKK;
    if (t < DKK) qs[t] = qr[t];
    __syncthreads();

    int nk = qpos + 1;
    const float scale = 0.125f;  // 1/sqrt(64)

    float lmax = -1e30f;
    for (int kp = t; kp < nk; kp += 128) {
        const float* kr = K + ((size_t)(b * SS + kp)) * DD + h * DKK;
        float dot = 0.f;
        #pragma unroll
        for (int d = 0; d < DKK; d++) dot += qs[d] * kr[d];
        dot *= scale;
        sc[kp] = dot;
        lmax = fmaxf(lmax, dot);
    }
    red[t] = lmax;
    __syncthreads();
    for (int st = 64; st > 0; st >>= 1) {
        if (t < st) red[t] = fmaxf(red[t], red[t + st]);
        __syncthreads();
    }
    float mx = red[0];
    __syncthreads();

    float lsum = 0.f;
    for (int kp = t; kp < nk; kp += 128) {
        float e = expf(sc[kp] - mx);
        sc[kp] = e;
        lsum += e;
    }
    red[t] = lsum;
    __syncthreads();
    for (int st = 64; st > 0; st >>= 1) {
        if (t < st) red[t] += red[t + st];
        __syncthreads();
    }
    float denom = red[0];
    __syncthreads();

    // o[d] = sum_k p[k] * V[k,d]; 2 k-partitions x 64 dims
    int part = t >> 6;
    int d    = t & 63;
    float o = 0.f;
    for (int kp = part; kp < nk; kp += 2)
        o += sc[kp] * V[((size_t)(b * SS + kp)) * DD + h * DKK + d];
    red[t] = o;
    __syncthreads();
    if (part == 0)
        O[((size_t)(b * SS + qpos)) * DD + h * DKK + d] = (red[t] + red[t + 64]) / denom;
}

// ---------------------------------------------------------------------------
// Elementwise
// ---------------------------------------------------------------------------
__global__ void add_kernel(float* __restrict__ y, const float* __restrict__ t, int n) {
    int i = blockIdx.x * blockDim.x + threadIdx.x;
    if (i < n) y[i] += t[i];
}

__global__ void gelu_kernel(float* __restrict__ x, int n) {
    int i = blockIdx.x * blockDim.x + threadIdx.x;
    if (i < n) {
        float v = x[i];
        x[i] = v * 0.5f * (1.0f + erff(v * 0.70710678118654752f));
    }
}

// ---------------------------------------------------------------------------
// Launch
// ---------------------------------------------------------------------------
extern "C" void kernel_launch(void* const* d_in, const int* in_sizes, int n_in,
                              void* d_out, int out_size) {
    (void)in_sizes; (void)n_in; (void)out_size;

    const int*   ids   = (const int*)  d_in[0];
    const float* emb   = (const float*)d_in[1];
    const float* pe    = (const float*)d_in[2];
    const float* Wq    = (const float*)d_in[3];
    const float* Wk    = (const float*)d_in[4];
    const float* Wv    = (const float*)d_in[5];
    const float* Wo    = (const float*)d_in[6];
    const float* bo    = (const float*)d_in[7];
    const float* ln1s  = (const float*)d_in[8];
    const float* ln1b  = (const float*)d_in[9];
    const float* ln2s  = (const float*)d_in[10];
    const float* ln2b  = (const float*)d_in[11];
    const float* W1    = (const float*)d_in[12];
    const float* b1    = (const float*)d_in[13];
    const float* W2    = (const float*)d_in[14];
    const float* b2    = (const float*)d_in[15];
    const float* lnfs  = (const float*)d_in[16];
    const float* lnfb  = (const float*)d_in[17];
    float* out = (float*)d_out;

    float *x, *h, *q, *k, *v, *attn, *ff;
    cudaGetSymbolAddress((void**)&x,    g_x);
    cudaGetSymbolAddress((void**)&h,    g_h);
    cudaGetSymbolAddress((void**)&q,    g_q);
    cudaGetSymbolAddress((void**)&k,    g_k);
    cudaGetSymbolAddress((void**)&v,    g_v);
    cudaGetSymbolAddress((void**)&attn, g_attn);
    cudaGetSymbolAddress((void**)&ff,   g_ff);

    const int EW = 256;
    dim3 gD(DD / 128, NTOK / 128);    // [2048 x 1024] gemms
    dim3 gF(FFD / 128, NTOK / 128);   // [2048 x 4096]
    dim3 gV(VV / 128, NTOK / 128);    // [2048 x 32000]

    embed_kernel<<<NTOK, EW>>>(ids, emb, pe, x);

    for (int l = 0; l < LL; l++) {
        const float* wq = Wq + (size_t)l * DD * DD;
        const float* wk = Wk + (size_t)l * DD * DD;
        const float* wv = Wv + (size_t)l * DD * DD;
        const float* wo = Wo + (size_t)l * DD * DD;

        ln_kernel<<<NTOK, 256>>>(x, ln1s + l * DD, ln1b + l * DD, h);
        gemm_kernel<false><<<gD, 256>>>(h, wq, nullptr, q, NTOK, DD, DD);
        gemm_kernel<false><<<gD, 256>>>(h, wk, nullptr, k, NTOK, DD, DD);
        gemm_kernel<false><<<gD, 256>>>(h, wv, nullptr, v, NTOK, DD, DD);
        attn_kernel<<<BB * HH * SS, 128>>>(q, k, v, attn);
        gemm_kernel<false><<<gD, 256>>>(attn, wo, bo + l * DD, h, NTOK, DD, DD);
        add_kernel<<<(NTOK * DD + 255) / 256, 256>>>(x, h, NTOK * DD);

        ln_kernel<<<NTOK, 256>>>(x, ln2s + l * DD, ln2b + l * DD, h);
        gemm_kernel<false><<<gF, 256>>>(h, W1 + (size_t)l * DD * FFD, b1 + l * FFD,
                                        ff, NTOK, FFD, DD);
        gelu_kernel<<<(NTOK * FFD + 255) / 256, 256>>>(ff, NTOK * FFD);
        gemm_kernel<false><<<gD, 256>>>(ff, W2 + (size_t)l * FFD * DD, b2 + l * DD,
                                        h, NTOK, DD, FFD);
        add_kernel<<<(NTOK * DD + 255) / 256, 256>>>(x, h, NTOK * DD);
    }

    ln_kernel<<<NTOK, 256>>>(x, lnfs, lnfb, h);
    // logits = h @ emb^T   (emb is [V, D] row-major -> NT gemm)
    gemm_kernel<true><<<gV, 256>>>(h, emb, nullptr, out, NTOK, VV, DD);
}

// round 3
// speedup vs baseline: 3.8566x; 3.8566x over previous
#include <cuda_runtime.h>
#include <cuda_bf16.h>
#include <math.h>

// Problem dims
#define BB   4
#define SS   512
#define DD   1024
#define HH   16
#define LL   6
#define FFD  4096
#define VV   32000
#define DKK  64
#define NTOK (BB*SS)   // 2048
#define QT   8         // queries per attention block

typedef __nv_bfloat16 bf16;

// ---------------------------------------------------------------------------
// Scratch (device globals — no runtime allocation allowed)
// ---------------------------------------------------------------------------
__device__ float g_x[NTOK*DD];
__device__ float g_q[NTOK*DD];
__device__ float g_k[NTOK*DD];
__device__ float g_v[NTOK*DD];
__device__ bf16  g_hh[NTOK*DD];
__device__ bf16  g_hl[NTOK*DD];
__device__ bf16  g_ah[NTOK*DD];
__device__ bf16  g_al[NTOK*DD];
__device__ bf16  g_ffh[NTOK*FFD];
__device__ bf16  g_ffl[NTOK*FFD];

#define WLAYER (4*DD*DD + 2*DD*FFD)          // 12582912 elems per layer
__device__ bf16  g_wth[(size_t)LL*WLAYER];
__device__ bf16  g_wtl[(size_t)LL*WLAYER];
__device__ bf16  g_eh[(size_t)VV*DD];
__device__ bf16  g_el[(size_t)VV*DD];

__device__ __forceinline__ void split2(float v, bf16& h, bf16& l) {
    h = __float2bfloat16(v);
    l = __float2bfloat16(v - __bfloat162float(h));
}

// ---------------------------------------------------------------------------
// Embedding + batch-indexed positional encoding (faithful to reference):
//   x[b,s,:] = emb[ids[b,s],:] + pe[b,:]
// ---------------------------------------------------------------------------
__global__ void embed_kernel(const int* __restrict__ ids,
                             const float* __restrict__ emb,
                             const float* __restrict__ pe,
                             float* __restrict__ x) {
    int row = blockIdx.x;
    int b   = row / SS;
    int id  = ids[row];
    const float* er = emb + (size_t)id * DD;
    const float* pr = pe  + (size_t)b  * DD;
    float* xr = x + (size_t)row * DD;
    for (int d = threadIdx.x; d < DD; d += 256)
        xr[d] = er[d] + pr[d];
}

// ---------------------------------------------------------------------------
// Weight transpose + split:  W[K][N] fp32  ->  Th[N][K], Tl[N][K] bf16
// ---------------------------------------------------------------------------
__global__ void wsplit_t_kernel(const float* __restrict__ W,
                                bf16* __restrict__ Th, bf16* __restrict__ Tl,
                                int K, int N) {
    __shared__ float tile[32][33];
    int n0 = blockIdx.x * 32, k0 = blockIdx.y * 32;
    int tx = threadIdx.x, ty = threadIdx.y;   // 32 x 8
    #pragma unroll
    for (int i = 0; i < 4; i++)
        tile[ty + i*8][tx] = W[(size_t)(k0 + ty + i*8) * N + n0 + tx];
    __syncthreads();
    #pragma unroll
    for (int i = 0; i < 4; i++) {
        float v = tile[tx][ty + i*8];
        size_t o = (size_t)(n0 + ty + i*8) * K + k0 + tx;
        bf16 h, l; split2(v, h, l);
        Th[o] = h; Tl[o] = l;
    }
}

// Elementwise split (no transpose) — for the weight-tied LM head (emb is [V,D])
__global__ void esplit_kernel(const float* __restrict__ X,
                              bf16* __restrict__ Xh, bf16* __restrict__ Xl, int n) {
    int i = blockIdx.x * 256 + threadIdx.x;
    if (i < n) { bf16 h, l; split2(X[i], h, l); Xh[i] = h; Xl[i] = l; }
}

// ---------------------------------------------------------------------------
// LayerNorm with split-bf16 output (GEMM A-operand format)
// ---------------------------------------------------------------------------
__global__ void ln_split_kernel(const float* __restrict__ x,
                                const float* __restrict__ s,
                                const float* __restrict__ b,
                                bf16* __restrict__ yh, bf16* __restrict__ yl) {
    int row = blockIdx.x;
    int t = threadIdx.x;
    const float* xr = x + (size_t)row * DD;
    float s1 = 0.f, s2 = 0.f;
    for (int i = t; i < DD; i += 256) {
        float v = xr[i];
        s1 += v; s2 += v * v;
    }
    __shared__ float r1[256], r2[256];
    r1[t] = s1; r2[t] = s2;
    __syncthreads();
    for (int st = 128; st > 0; st >>= 1) {
        if (t < st) { r1[t] += r1[t + st]; r2[t] += r2[t + st]; }
        __syncthreads();
    }
    __shared__ float sm_mean, sm_rstd;
    if (t == 0) {
        float mean = r1[0] * (1.0f / DD);
        float var  = r2[0] * (1.0f / DD) - mean * mean;
        sm_mean = mean;
        sm_rstd = rsqrtf(var + 1e-5f);
    }
    __syncthreads();
    float mean = sm_mean, rstd = sm_rstd;
    for (int i = t; i < DD; i += 256) {
        float y = (xr[i] - mean) * rstd * s[i] + b[i];
        bf16 h, l; split2(y, h, l);
        yh[(size_t)row * DD + i] = h;
        yl[(size_t)row * DD + i] = l;
    }
}

// ---------------------------------------------------------------------------
// Split-bf16 tensor-core GEMM (NT): C[M,N] = (Ah+Al)[M,K] @ (Bh+Bl)[N,K]^T
// 3-product compensation: hi*hi + hi*lo + lo*hi  (fp32 accumulate)
// 128x128 block tile, BK=32, 256 threads (8 warps as 4m x 2n, warp = 32x64)
// EPI 0: C = AB (+bias)            -> fp32
// EPI 1: C = Cin + AB (+bias)      -> fp32 (residual)
// EPI 2: gelu(AB + bias)           -> split bf16 (Oh, Ol)
// ---------------------------------------------------------------------------
__device__ __forceinline__ void mma16816(float* c, const unsigned* a, const unsigned* b) {
    asm volatile(
        "mma.sync.aligned.m16n8k16.row.col.f32.bf16.bf16.f32 "
        "{%0,%1,%2,%3}, {%4,%5,%6,%7}, {%8,%9}, {%0,%1,%2,%3};\n"
        : "+f"(c[0]), "+f"(c[1]), "+f"(c[2]), "+f"(c[3])
        : "r"(a[0]), "r"(a[1]), "r"(a[2]), "r"(a[3]), "r"(b[0]), "r"(b[1]));
}

template <int EPI>
__global__ __launch_bounds__(256)
void gemm_bf16s(const bf16* __restrict__ Ah, const bf16* __restrict__ Al,
                const bf16* __restrict__ Bh, const bf16* __restrict__ Bl,
                const float* __restrict__ bias, const float* __restrict__ Cin,
                float* __restrict__ Cout, bf16* __restrict__ Oh, bf16* __restrict__ Ol,
                int M, int N, int K) {
    const int PAD = 40;                         // bf16 elems per smem row (32 + 8 pad)
    __shared__ bf16 sAh[128 * PAD];
    __shared__ bf16 sAl[128 * PAD];
    __shared__ bf16 sBh[128 * PAD];
    __shared__ bf16 sBl[128 * PAD];

    int t = threadIdx.x;
    int m0 = blockIdx.y * 128, n0 = blockIdx.x * 128;
    int wid = t >> 5, lane = t & 31;
    int wm = wid >> 1, wn = wid & 1;            // 4 x 2 warp grid
    int group = lane >> 2, tig = lane & 3;

    float acc[2][8][4];
    #pragma unroll
    for (int i = 0; i < 2; i++)
        #pragma unroll
        for (int j = 0; j < 8; j++)
            #pragma unroll
            for (int k = 0; k < 4; k++) acc[i][j][k] = 0.f;

    for (int k0 = 0; k0 < K; k0 += 32) {
        // Load tiles: 128 rows x 32 bf16 per array, as uint4 (8 bf16)
        #pragma unroll
        for (int i = 0; i < 2; i++) {
            int lin = t + i * 256;              // 0..511
            int row = lin >> 2, qq = lin & 3;
            size_t ga = (size_t)(m0 + row) * K + k0 + qq * 8;
            size_t gb = (size_t)(n0 + row) * K + k0 + qq * 8;
            int so = row * PAD + qq * 8;
            *(uint4*)&sAh[so] = *(const uint4*)&Ah[ga];
            *(uint4*)&sAl[so] = *(const uint4*)&Al[ga];
            *(uint4*)&sBh[so] = *(const uint4*)&Bh[gb];
            *(uint4*)&sBl[so] = *(const uint4*)&Bl[gb];
        }
        __syncthreads();

        #pragma unroll
        for (int ks = 0; ks < 32; ks += 16) {
            unsigned afh[2][4], afl[2][4], bfh[8][2], bfl[8][2];
            #pragma unroll
            for (int mt = 0; mt < 2; mt++) {
                int ar = (wm * 32 + mt * 16 + group) * PAD + ks + tig * 2;
                afh[mt][0] = *(unsigned*)&sAh[ar];
                afh[mt][1] = *(unsigned*)&sAh[ar + 8 * PAD];
                afh[mt][2] = *(unsigned*)&sAh[ar + 8];
                afh[mt][3] = *(unsigned*)&sAh[ar + 8 * PAD + 8];
                afl[mt][0] = *(unsigned*)&sAl[ar];
                afl[mt][1] = *(unsigned*)&sAl[ar + 8 * PAD];
                afl[mt][2] = *(unsigned*)&sAl[ar + 8];
                afl[mt][3] = *(unsigned*)&sAl[ar + 8 * PAD + 8];
            }
            #pragma unroll
            for (int nt = 0; nt < 8; nt++) {
                int br = (wn * 64 + nt * 8 + group) * PAD + ks + tig * 2;
                bfh[nt][0] = *(unsigned*)&sBh[br];
                bfh[nt][1] = *(unsigned*)&sBh[br + 8];
                bfl[nt][0] = *(unsigned*)&sBl[br];
                bfl[nt][1] = *(unsigned*)&sBl[br + 8];
            }
            #pragma unroll
            for (int mt = 0; mt < 2; mt++)
                #pragma unroll
                for (int nt = 0; nt < 8; nt++) {
                    mma16816(acc[mt][nt], afh[mt], bfh[nt]);
                    mma16816(acc[mt][nt], afh[mt], bfl[nt]);
                    mma16816(acc[mt][nt], afl[mt], bfh[nt]);
                }
        }
        __syncthreads();
    }

    // Epilogue
    #pragma unroll
    for (int mt = 0; mt < 2; mt++) {
        #pragma unroll
        for (int nt = 0; nt < 8; nt++) {
            int col = n0 + wn * 64 + nt * 8 + tig * 2;
            float b0 = 0.f, b1v = 0.f;
            if (bias) { b0 = bias[col]; b1v = bias[col + 1]; }
            #pragma unroll
            for (int half = 0; half < 2; half++) {
                int row = m0 + wm * 32 + mt * 16 + group + half * 8;
                float v0 = acc[mt][nt][half * 2 + 0] + b0;
                float v1 = acc[mt][nt][half * 2 + 1] + b1v;
                size_t o = (size_t)row * N + col;
                if (EPI == 0) {
                    Cout[o] = v0; Cout[o + 1] = v1;
                } else if (EPI == 1) {
                    Cout[o] = Cin[o] + v0; Cout[o + 1] = Cin[o + 1] + v1;
                } else {
                    float g0 = 0.5f * v0 * (1.0f + erff(v0 * 0.70710678118654752f));
                    float g1 = 0.5f * v1 * (1.0f + erff(v1 * 0.70710678118654752f));
                    bf16 h, l;
                    split2(g0, h, l); Oh[o] = h;     Ol[o] = l;
                    split2(g1, h, l); Oh[o + 1] = h; Ol[o + 1] = l;
                }
            }
        }
    }
}

// ---------------------------------------------------------------------------
// Causal attention: one block = (b, h, 8 queries). K tiled through smem
// (coalesced), exact softmax, V pass with per-thread accumulators.
// Writes split-bf16 output (A operand of the Wo GEMM).
// ---------------------------------------------------------------------------
__global__ __launch_bounds__(128)
void attn_kernel(const float* __restrict__ Q, const float* __restrict__ Kg,
                 const float* __restrict__ Vg,
                 bf16* __restrict__ Oh, bf16* __restrict__ Ol) {
    const int NQB = SS / QT;  // 64 q-blocks per (b,h)
    int qt0 = (blockIdx.x % NQB) * QT;
    int bh  = blockIdx.x / NQB;
    int h   = bh % HH, b = bh / HH;
    int t   = threadIdx.x;

    __shared__ float qs[QT][DKK];
    __shared__ float Ks[64][DKK + 1];
    __shared__ float sc[QT][SS + 16];
    __shared__ float red[128];
    __shared__ float mx[QT], dn[QT];

    for (int i = t; i < QT * DKK; i += 128) {
        int qi = i >> 6, d = i & 63;
        qs[qi][d] = Q[(size_t)(b * SS + qt0 + qi) * DD + h * DKK + d];
    }
    __syncthreads();

    const int nkmax = qt0 + QT;
    const float scale = 0.125f;  // 1/sqrt(64)

    for (int kt = 0; kt < nkmax; kt += 64) {
        int rows = min(64, nkmax - kt);
        for (int i = t; i < rows * DKK; i += 128) {
            int r = i >> 6, d = i & 63;
            Ks[r][d] = Kg[(size_t)(b * SS + kt + r) * DD + h * DKK + d];
        }
        __syncthreads();
        int j = t & 63, qh = t >> 6;
        if (j < rows) {
            int kglob = kt + j;
            for (int qi = qh; qi < QT; qi += 2) {
                float dot = 0.f;
                #pragma unroll
                for (int d = 0; d < DKK; d++) dot += qs[qi][d] * Ks[j][d];
                sc[qi][kglob] = (kglob <= qt0 + qi) ? dot * scale : -1e30f;
            }
        }
        __syncthreads();
    }

    // softmax: 16 threads per query
    int tq = t >> 4, r = t & 15;
    float m = -1e30f;
    for (int k = r; k < nkmax; k += 16) m = fmaxf(m, sc[tq][k]);
    red[t] = m;
    __syncthreads();
    for (int st = 8; st > 0; st >>= 1) {
        if (r < st) red[t] = fmaxf(red[t], red[t + st]);
        __syncthreads();
    }
    if (r == 0) mx[tq] = red[t];
    __syncthreads();
    float mval = mx[tq];
    float s = 0.f;
    for (int k = r; k < nkmax; k += 16) {
        float e = expf(sc[tq][k] - mval);
        sc[tq][k] = e;
        s += e;
    }
    red[t] = s;
    __syncthreads();
    for (int st = 8; st > 0; st >>= 1) {
        if (r < st) red[t] += red[t + st];
        __syncthreads();
    }
    if (r == 0) dn[tq] = red[t];
    __syncthreads();

    // V pass: thread = (part 0/1 over k) x (d 0..63)
    int d = t & 63, part = t >> 6;
    float acc[QT];
    #pragma unroll
    for (int qi = 0; qi < QT; qi++) acc[qi] = 0.f;
    for (int k = part; k < nkmax; k += 2) {
        float v = Vg[(size_t)(b * SS + k) * DD + h * DKK + d];
        #pragma unroll
        for (int qi = 0; qi < QT; qi++) acc[qi] += sc[qi][k] * v;
    }
    for (int qi = 0; qi < QT; qi++) {
        red[t] = acc[qi];
        __syncthreads();
        if (part == 0) {
            float o = (red[t] + red[t + 64]) / dn[qi];
            bf16 hh, ll; split2(o, hh, ll);
            size_t off = (size_t)(b * SS + qt0 + qi) * DD + h * DKK + d;
            Oh[off] = hh; Ol[off] = ll;
        }
        __syncthreads();
    }
}

// ---------------------------------------------------------------------------
// Launch
// ---------------------------------------------------------------------------
extern "C" void kernel_launch(void* const* d_in, const int* in_sizes, int n_in,
                              void* d_out, int out_size) {
    (void)in_sizes; (void)n_in; (void)out_size;

    const int*   ids  = (const int*)  d_in[0];
    const float* emb  = (const float*)d_in[1];
    const float* pe   = (const float*)d_in[2];
    const float* Wq   = (const float*)d_in[3];
    const float* Wk   = (const float*)d_in[4];
    const float* Wv   = (const float*)d_in[5];
    const float* Wo   = (const float*)d_in[6];
    const float* bo   = (const float*)d_in[7];
    const float* ln1s = (const float*)d_in[8];
    const float* ln1b = (const float*)d_in[9];
    const float* ln2s = (const float*)d_in[10];
    const float* ln2b = (const float*)d_in[11];
    const float* W1   = (const float*)d_in[12];
    const float* b1   = (const float*)d_in[13];
    const float* W2   = (const float*)d_in[14];
    const float* b2   = (const float*)d_in[15];
    const float* lnfs = (const float*)d_in[16];
    const float* lnfb = (const float*)d_in[17];
    float* out = (float*)d_out;

    float *x, *q, *k, *v;
    bf16 *hh, *hl, *ah, *al, *ffh, *ffl, *wth, *wtl, *eh, *el;
    cudaGetSymbolAddress((void**)&x,   g_x);
    cudaGetSymbolAddress((void**)&q,   g_q);
    cudaGetSymbolAddress((void**)&k,   g_k);
    cudaGetSymbolAddress((void**)&v,   g_v);
    cudaGetSymbolAddress((void**)&hh,  g_hh);
    cudaGetSymbolAddress((void**)&hl,  g_hl);
    cudaGetSymbolAddress((void**)&ah,  g_ah);
    cudaGetSymbolAddress((void**)&al,  g_al);
    cudaGetSymbolAddress((void**)&ffh, g_ffh);
    cudaGetSymbolAddress((void**)&ffl, g_ffl);
    cudaGetSymbolAddress((void**)&wth, g_wth);
    cudaGetSymbolAddress((void**)&wtl, g_wtl);
    cudaGetSymbolAddress((void**)&eh,  g_eh);
    cudaGetSymbolAddress((void**)&el,  g_el);

    dim3 tb32(32, 8);
    // Weight conversion (transpose + hi/lo split), all layers
    for (int l = 0; l < LL; l++) {
        size_t base = (size_t)l * WLAYER;
        dim3 gDD(DD / 32, DD / 32);
        wsplit_t_kernel<<<gDD, tb32>>>(Wq + (size_t)l * DD * DD, wth + base,               wtl + base,               DD, DD);
        wsplit_t_kernel<<<gDD, tb32>>>(Wk + (size_t)l * DD * DD, wth + base + 1*DD*DD,     wtl + base + 1*DD*DD,     DD, DD);
        wsplit_t_kernel<<<gDD, tb32>>>(Wv + (size_t)l * DD * DD, wth + base + 2*DD*DD,     wtl + base + 2*DD*DD,     DD, DD);
        wsplit_t_kernel<<<gDD, tb32>>>(Wo + (size_t)l * DD * DD, wth + base + 3*DD*DD,     wtl + base + 3*DD*DD,     DD, DD);
        dim3 gW1(FFD / 32, DD / 32);
        wsplit_t_kernel<<<gW1, tb32>>>(W1 + (size_t)l * DD * FFD, wth + base + 4*DD*DD,    wtl + base + 4*DD*DD,     DD, FFD);
        dim3 gW2(DD / 32, FFD / 32);
        wsplit_t_kernel<<<gW2, tb32>>>(W2 + (size_t)l * FFD * DD, wth + base + 4*DD*DD + (size_t)DD*FFD,
                                                                  wtl + base + 4*DD*DD + (size_t)DD*FFD, FFD, DD);
    }
    esplit_kernel<<<((size_t)VV * DD + 255) / 256, 256>>>(emb, eh, el, VV * DD);

    embed_kernel<<<NTOK, 256>>>(ids, emb, pe, x);

    dim3 gD(DD / 128, NTOK / 128);    // 8 x 16
    dim3 gF(FFD / 128, NTOK / 128);   // 32 x 16
    dim3 gV(VV / 128, NTOK / 128);    // 250 x 16

    for (int l = 0; l < LL; l++) {
        size_t base = (size_t)l * WLAYER;
        bf16* wqh = wth + base;                 bf16* wql = wtl + base;
        bf16* wkh = wqh + DD * DD;              bf16* wkl = wql + DD * DD;
        bf16* wvh = wkh + DD * DD;              bf16* wvl = wkl + DD * DD;
        bf16* woh = wvh + DD * DD;              bf16* wol = wvl + DD * DD;
        bf16* w1h = woh + DD * DD;              bf16* w1l = wol + DD * DD;
        bf16* w2h = w1h + (size_t)DD * FFD;     bf16* w2l = w1l + (size_t)DD * FFD;

        ln_split_kernel<<<NTOK, 256>>>(x, ln1s + l * DD, ln1b + l * DD, hh, hl);
        gemm_bf16s<0><<<gD, 256>>>(hh, hl, wqh, wql, nullptr, nullptr, q, nullptr, nullptr, NTOK, DD, DD);
        gemm_bf16s<0><<<gD, 256>>>(hh, hl, wkh, wkl, nullptr, nullptr, k, nullptr, nullptr, NTOK, DD, DD);
        gemm_bf16s<0><<<gD, 256>>>(hh, hl, wvh, wvl, nullptr, nullptr, v, nullptr, nullptr, NTOK, DD, DD);
        attn_kernel<<<BB * HH * (SS / QT), 128>>>(q, k, v, ah, al);
        gemm_bf16s<1><<<gD, 256>>>(ah, al, woh, wol, bo + l * DD, x, x, nullptr, nullptr, NTOK, DD, DD);

        ln_split_kernel<<<NTOK, 256>>>(x, ln2s + l * DD, ln2b + l * DD, hh, hl);
        gemm_bf16s<2><<<gF, 256>>>(hh, hl, w1h, w1l, b1 + l * FFD, nullptr, nullptr, ffh, ffl, NTOK, FFD, DD);
        gemm_bf16s<1><<<gD, 256>>>(ffh, ffl, w2h, w2l, b2 + l * DD, x, x, nullptr, nullptr, NTOK, DD, FFD);
    }

    ln_split_kernel<<<NTOK, 256>>>(x, lnfs, lnfb, hh, hl);
    gemm_bf16s<0><<<gV, 256>>>(hh, hl, eh, el, nullptr, nullptr, out, nullptr, nullptr, NTOK, VV, DD);
}

// round 5
// speedup vs baseline: 4.9340x; 1.2794x over previous
#include <cuda_runtime.h>
#include <cuda_bf16.h>
#include <math.h>
#include <stdint.h>

// Problem dims
#define BB   4
#define SS   512
#define DD   1024
#define HH   16
#define LL   6
#define FFD  4096
#define VV   32000
#define DKK  64
#define NTOK (BB*SS)   // 2048
#define QT   8         // queries per attention block

typedef __nv_bfloat16 bf16;

// ---------------------------------------------------------------------------
// Scratch (device globals — no runtime allocation allowed)
// ---------------------------------------------------------------------------
__device__ float g_x[NTOK*DD];
__device__ float g_q[NTOK*DD];
__device__ float g_k[NTOK*DD];
__device__ float g_v[NTOK*DD];
__device__ bf16  g_hh[NTOK*DD];
__device__ bf16  g_hl[NTOK*DD];
__device__ bf16  g_ah[NTOK*DD];
__device__ bf16  g_al[NTOK*DD];
__device__ bf16  g_ffh[NTOK*FFD];
__device__ bf16  g_ffl[NTOK*FFD];

#define WLAYER (4*DD*DD + 2*DD*FFD)          // elems per layer
__device__ bf16  g_wth[(size_t)LL*WLAYER];
__device__ bf16  g_wtl[(size_t)LL*WLAYER];
__device__ bf16  g_eh[(size_t)VV*DD];
__device__ bf16  g_el[(size_t)VV*DD];

__device__ __forceinline__ void split2(float v, bf16& h, bf16& l) {
    h = __float2bfloat16(v);
    l = __float2bfloat16(v - __bfloat162float(h));
}

__device__ __forceinline__ uint32_t smem_u32(const void* p) {
    uint32_t a;
    asm("{ .reg .u64 tmp; cvta.to.shared.u64 tmp, %1; cvt.u32.u64 %0, tmp; }"
        : "=r"(a) : "l"(p));
    return a;
}

// cp.async helpers (legacy path — works on plain sm_103 target)
__device__ __forceinline__ void cp_async16(uint32_t dst, const void* src) {
    asm volatile("cp.async.cg.shared.global [%0], [%1], 16;" :: "r"(dst), "l"(src) : "memory");
}
__device__ __forceinline__ void cp_commit() {
    asm volatile("cp.async.commit_group;" ::: "memory");
}
template <int N>
__device__ __forceinline__ void cp_wait() {
    asm volatile("cp.async.wait_group %0;" :: "n"(N) : "memory");
}

__device__ __forceinline__ void ldsm_x4(unsigned& r0, unsigned& r1, unsigned& r2,
                                        unsigned& r3, uint32_t a) {
    asm volatile("ldmatrix.sync.aligned.m8n8.x4.shared.b16 {%0,%1,%2,%3}, [%4];"
                 : "=r"(r0), "=r"(r1), "=r"(r2), "=r"(r3) : "r"(a));
}

__device__ __forceinline__ void mma16816(float* c, const unsigned* a, const unsigned* b) {
    asm volatile(
        "mma.sync.aligned.m16n8k16.row.col.f32.bf16.bf16.f32 "
        "{%0,%1,%2,%3}, {%4,%5,%6,%7}, {%8,%9}, {%0,%1,%2,%3};\n"
        : "+f"(c[0]), "+f"(c[1]), "+f"(c[2]), "+f"(c[3])
        : "r"(a[0]), "r"(a[1]), "r"(a[2]), "r"(a[3]), "r"(b[0]), "r"(b[1]));
}

// ---------------------------------------------------------------------------
// Embedding + batch-indexed positional encoding (faithful to reference):
//   x[b,s,:] = emb[ids[b,s],:] + pe[b,:]
// ---------------------------------------------------------------------------
__global__ void embed_kernel(const int* __restrict__ ids,
                             const float* __restrict__ emb,
                             const float* __restrict__ pe,
                             float* __restrict__ x) {
    int row = blockIdx.x;
    int b   = row / SS;
    int id  = ids[row];
    const float* er = emb + (size_t)id * DD;
    const float* pr = pe  + (size_t)b  * DD;
    float* xr = x + (size_t)row * DD;
    for (int d = threadIdx.x; d < DD; d += 256)
        xr[d] = er[d] + pr[d];
}

// ---------------------------------------------------------------------------
// Weight transpose + split, merged over layers
// ---------------------------------------------------------------------------
__device__ __forceinline__ void wsplit_body(const float* __restrict__ W,
                                            bf16* __restrict__ Th, bf16* __restrict__ Tl,
                                            int K, int N) {
    __shared__ float tile[32][33];
    int n0 = blockIdx.x * 32, k0 = blockIdx.y * 32;
    int tx = threadIdx.x, ty = threadIdx.y;   // 32 x 8
    #pragma unroll
    for (int i = 0; i < 4; i++)
        tile[ty + i*8][tx] = W[(size_t)(k0 + ty + i*8) * N + n0 + tx];
    __syncthreads();
    #pragma unroll
    for (int i = 0; i < 4; i++) {
        float v = tile[tx][ty + i*8];
        size_t o = (size_t)(n0 + ty + i*8) * K + k0 + tx;
        bf16 h, l; split2(v, h, l);
        Th[o] = h; Tl[o] = l;
    }
}

__global__ void wsplit_qkvo_kernel(const float* __restrict__ Wq, const float* __restrict__ Wk,
                                   const float* __restrict__ Wv, const float* __restrict__ Wo,
                                   bf16* __restrict__ Th, bf16* __restrict__ Tl) {
    int z = blockIdx.z, l = z >> 2, widx = z & 3;
    const float* W = (widx == 0 ? Wq : widx == 1 ? Wk : widx == 2 ? Wv : Wo)
                     + (size_t)l * DD * DD;
    size_t ob = (size_t)l * WLAYER + (size_t)widx * DD * DD;
    wsplit_body(W, Th + ob, Tl + ob, DD, DD);
}

__global__ void wsplit_ff_kernel(const float* __restrict__ W,
                                 bf16* __restrict__ Th, bf16* __restrict__ Tl,
                                 int K, int N, size_t obase) {
    int l = blockIdx.z;
    const float* Wl = W + (size_t)l * K * N;
    size_t ob = (size_t)l * WLAYER + obase;
    wsplit_body(Wl, Th + ob, Tl + ob, K, N);
}

__global__ void esplit_kernel(const float* __restrict__ X,
                              bf16* __restrict__ Xh, bf16* __restrict__ Xl, int n) {
    int i = blockIdx.x * 256 + threadIdx.x;
    if (i < n) { bf16 h, l; split2(X[i], h, l); Xh[i] = h; Xl[i] = l; }
}

// ---------------------------------------------------------------------------
// LayerNorm with split-bf16 output
// ---------------------------------------------------------------------------
__global__ void ln_split_kernel(const float* __restrict__ x,
                                const float* __restrict__ s,
                                const float* __restrict__ b,
                                bf16* __restrict__ yh, bf16* __restrict__ yl) {
    int row = blockIdx.x;
    int t = threadIdx.x;
    const float* xr = x + (size_t)row * DD;
    float s1 = 0.f, s2 = 0.f;
    for (int i = t; i < DD; i += 256) {
        float v = xr[i];
        s1 += v; s2 += v * v;
    }
    __shared__ float r1[256], r2[256];
    r1[t] = s1; r2[t] = s2;
    __syncthreads();
    for (int st = 128; st > 0; st >>= 1) {
        if (t < st) { r1[t] += r1[t + st]; r2[t] += r2[t + st]; }
        __syncthreads();
    }
    __shared__ float sm_mean, sm_rstd;
    if (t == 0) {
        float mean = r1[0] * (1.0f / DD);
        float var  = r2[0] * (1.0f / DD) - mean * mean;
        sm_mean = mean;
        sm_rstd = rsqrtf(var + 1e-5f);
    }
    __syncthreads();
    float mean = sm_mean, rstd = sm_rstd;
    for (int i = t; i < DD; i += 256) {
        float y = (xr[i] - mean) * rstd * s[i] + b[i];
        bf16 h, l; split2(y, h, l);
        yh[(size_t)row * DD + i] = h;
        yl[(size_t)row * DD + i] = l;
    }
}

// ---------------------------------------------------------------------------
// Split-bf16 HMMA GEMM (NT): C[M,N] = (Ah+Al)[M,K] @ (Bh+Bl)[N,K]^T
// 3-product compensation: hh + hl + lh, fp32 accumulate.
// 128x128 CTA tile, BK=32, 256 threads (8 warps: 4m x 2n, warp = 32x64).
// cp.async double-buffered stages + ldmatrix fragment loads.
// Row stride 80B: 8 consecutive rows hit 8 distinct 16B bank groups.
// EPI 0: C = AB (+bias)            -> fp32
// EPI 1: C = Cin + AB (+bias)      -> fp32 (residual)
// EPI 2: gelu(AB + bias)           -> split bf16 (Oh, Ol)
// ---------------------------------------------------------------------------
#define ROWB 80                         // bytes per smem row (64 data + 16 pad)
#define MATB (128 * ROWB)               // 10240 bytes per matrix tile
#define STAGEB (4 * MATB)               // 40960 bytes per stage
#define SMEM_GEMM (2 * STAGEB)          // 81920 bytes

template <int EPI>
__global__ __launch_bounds__(256, 2)
void gemm_hmma(const bf16* __restrict__ Ah, const bf16* __restrict__ Al,
               const bf16* __restrict__ Bh, const bf16* __restrict__ Bl,
               const float* __restrict__ bias, const float* __restrict__ Cin,
               float* __restrict__ Cout, bf16* __restrict__ Oh, bf16* __restrict__ Ol,
               int M, int N, int K) {
    extern __shared__ char smem[];
    uint32_t sb = smem_u32(smem);

    int t = threadIdx.x;
    int wid = t >> 5, lane = t & 31;
    int wm = wid >> 1, wn = wid & 1;    // 4 x 2 warp grid
    int group = lane >> 2, tig = lane & 3;
    int m0 = blockIdx.y * 128, n0 = blockIdx.x * 128;

    float acc[2][8][4];
    #pragma unroll
    for (int i = 0; i < 2; i++)
        #pragma unroll
        for (int j = 0; j < 8; j++)
            #pragma unroll
            for (int kk = 0; kk < 4; kk++) acc[i][j][kk] = 0.f;

    // Loader indexing: 2048 16B-chunks/stage, 8 per thread
    // lin = t + j*256; mtx = lin>>9; c = lin&511; row = c>>2; q = c&3
    const bf16* srcs[4] = { Ah, Al, Bh, Bl };

    auto load_stage = [&](int stage, int kt) {
        uint32_t base = sb + stage * STAGEB;
        int kofs = kt << 5;
        #pragma unroll
        for (int j = 0; j < 8; j++) {
            int lin = t + j * 256;
            int mtx = lin >> 9;
            int c   = lin & 511;
            int row = c >> 2, q = c & 3;
            int rbase = (mtx < 2) ? m0 : n0;
            const bf16* src = srcs[mtx] + (size_t)(rbase + row) * K + kofs + q * 8;
            cp_async16(base + mtx * MATB + row * ROWB + q * 16, src);
        }
        cp_commit();
    };

    // per-thread ldmatrix address components
    // A x4: lanes 0-7 rows0-7@k0 | 8-15 rows8-15@k0 | 16-23 rows0-7@k8 | 24-31 rows8-15@k8
    uint32_t aRow = (uint32_t)(wm * 32 + (lane & 15)) * ROWB;
    uint32_t aCol = (uint32_t)((lane >> 4) << 3) * 2;
    // B x4 (two n-tiles): n_off = (lane&7) + ((lane>>4)<<3), khalf = ((lane>>3)&1)*8
    uint32_t bRowBase = (uint32_t)(wn * 64 + (lane & 7) + ((lane >> 4) << 3)) * ROWB;
    uint32_t bCol = (uint32_t)(((lane >> 3) & 1) << 3) * 2;

    const int nk = K >> 5;              // K-tiles of 32

    load_stage(0, 0);

    for (int i = 0; i < nk; i++) {
        if (i + 1 < nk) { load_stage((i + 1) & 1, i + 1); cp_wait<1>(); }
        else            { cp_wait<0>(); }
        __syncthreads();

        uint32_t stb = sb + (i & 1) * STAGEB;
        uint32_t pAh = stb + aRow + aCol;
        uint32_t pAl = stb + MATB + aRow + aCol;
        uint32_t pBh = stb + 2 * MATB + bRowBase + bCol;
        uint32_t pBl = stb + 3 * MATB + bRowBase + bCol;

        #pragma unroll
        for (int ks = 0; ks < 2; ks++) {
            uint32_t ko = ks * 32;      // 16 bf16 = 32 bytes
            unsigned afh[2][4], afl[2][4], bfh[8][2], bfl[8][2];
            #pragma unroll
            for (int mt = 0; mt < 2; mt++) {
                ldsm_x4(afh[mt][0], afh[mt][1], afh[mt][2], afh[mt][3],
                        pAh + (uint32_t)(mt * 16) * ROWB + ko);
                ldsm_x4(afl[mt][0], afl[mt][1], afl[mt][2], afl[mt][3],
                        pAl + (uint32_t)(mt * 16) * ROWB + ko);
            }
            #pragma unroll
            for (int jp = 0; jp < 4; jp++) {
                ldsm_x4(bfh[2*jp][0], bfh[2*jp][1], bfh[2*jp+1][0], bfh[2*jp+1][1],
                        pBh + (uint32_t)(jp * 16) * ROWB + ko);
                ldsm_x4(bfl[2*jp][0], bfl[2*jp][1], bfl[2*jp+1][0], bfl[2*jp+1][1],
                        pBl + (uint32_t)(jp * 16) * ROWB + ko);
            }
            #pragma unroll
            for (int mt = 0; mt < 2; mt++)
                #pragma unroll
                for (int nt = 0; nt < 8; nt++) {
                    mma16816(acc[mt][nt], afh[mt], bfh[nt]);
                    mma16816(acc[mt][nt], afh[mt], bfl[nt]);
                    mma16816(acc[mt][nt], afl[mt], bfh[nt]);
                }
        }
        __syncthreads();
    }

    // Epilogue
    #pragma unroll
    for (int mt = 0; mt < 2; mt++) {
        #pragma unroll
        for (int nt = 0; nt < 8; nt++) {
            int col = n0 + wn * 64 + nt * 8 + tig * 2;
            float b0 = 0.f, b1v = 0.f;
            if (bias) { b0 = bias[col]; b1v = bias[col + 1]; }
            #pragma unroll
            for (int half = 0; half < 2; half++) {
                int row = m0 + wm * 32 + mt * 16 + group + half * 8;
                float v0 = acc[mt][nt][half * 2 + 0] + b0;
                float v1 = acc[mt][nt][half * 2 + 1] + b1v;
                size_t o = (size_t)row * N + col;
                if (EPI == 0) {
                    Cout[o] = v0; Cout[o + 1] = v1;
                } else if (EPI == 1) {
                    Cout[o] = Cin[o] + v0; Cout[o + 1] = Cin[o + 1] + v1;
                } else {
                    float g0 = 0.5f * v0 * (1.0f + erff(v0 * 0.70710678118654752f));
                    float g1 = 0.5f * v1 * (1.0f + erff(v1 * 0.70710678118654752f));
                    bf16 h, l;
                    split2(g0, h, l); Oh[o] = h;     Ol[o] = l;
                    split2(g1, h, l); Oh[o + 1] = h; Ol[o + 1] = l;
                }
            }
        }
    }
}

// ---------------------------------------------------------------------------
// Causal attention: one block = (b, h, 8 queries). Exact softmax.
// Writes split-bf16 output (A operand of the Wo GEMM).
// ---------------------------------------------------------------------------
__global__ __launch_bounds__(128)
void attn_kernel(const float* __restrict__ Q, const float* __restrict__ Kg,
                 const float* __restrict__ Vg,
                 bf16* __restrict__ Oh, bf16* __restrict__ Ol) {
    const int NQB = SS / QT;
    int qt0 = (blockIdx.x % NQB) * QT;
    int bh  = blockIdx.x / NQB;
    int h   = bh % HH, b = bh / HH;
    int t   = threadIdx.x;

    __shared__ float qs[QT][DKK];
    __shared__ float Ks[64][DKK + 1];
    __shared__ float sc[QT][SS + 16];
    __shared__ float red[128];
    __shared__ float mx[QT], dn[QT];

    for (int i = t; i < QT * DKK; i += 128) {
        int qi = i >> 6, d = i & 63;
        qs[qi][d] = Q[(size_t)(b * SS + qt0 + qi) * DD + h * DKK + d];
    }
    __syncthreads();

    const int nkmax = qt0 + QT;
    const float scale = 0.125f;

    for (int kt = 0; kt < nkmax; kt += 64) {
        int rows = min(64, nkmax - kt);
        for (int i = t; i < rows * DKK; i += 128) {
            int r = i >> 6, d = i & 63;
            Ks[r][d] = Kg[(size_t)(b * SS + kt + r) * DD + h * DKK + d];
        }
        __syncthreads();
        int j = t & 63, qh = t >> 6;
        if (j < rows) {
            int kglob = kt + j;
            for (int qi = qh; qi < QT; qi += 2) {
                float dot = 0.f;
                #pragma unroll
                for (int d = 0; d < DKK; d++) dot += qs[qi][d] * Ks[j][d];
                sc[qi][kglob] = (kglob <= qt0 + qi) ? dot * scale : -1e30f;
            }
        }
        __syncthreads();
    }

    int tq = t >> 4, r = t & 15;
    float m = -1e30f;
    for (int k = r; k < nkmax; k += 16) m = fmaxf(m, sc[tq][k]);
    red[t] = m;
    __syncthreads();
    for (int st = 8; st > 0; st >>= 1) {
        if (r < st) red[t] = fmaxf(red[t], red[t + st]);
        __syncthreads();
    }
    if (r == 0) mx[tq] = red[t];
    __syncthreads();
    float mval = mx[tq];
    float s = 0.f;
    for (int k = r; k < nkmax; k += 16) {
        float e = expf(sc[tq][k] - mval);
        sc[tq][k] = e;
        s += e;
    }
    red[t] = s;
    __syncthreads();
    for (int st = 8; st > 0; st >>= 1) {
        if (r < st) red[t] += red[t + st];
        __syncthreads();
    }
    if (r == 0) dn[tq] = red[t];
    __syncthreads();

    int d = t & 63, part = t >> 6;
    float acc[QT];
    #pragma unroll
    for (int qi = 0; qi < QT; qi++) acc[qi] = 0.f;
    for (int k = part; k < nkmax; k += 2) {
        float v = Vg[(size_t)(b * SS + k) * DD + h * DKK + d];
        #pragma unroll
        for (int qi = 0; qi < QT; qi++) acc[qi] += sc[qi][k] * v;
    }
    for (int qi = 0; qi < QT; qi++) {
        red[t] = acc[qi];
        __syncthreads();
        if (part == 0) {
            float o = (red[t] + red[t + 64]) / dn[qi];
            bf16 hh, ll; split2(o, hh, ll);
            size_t off = (size_t)(b * SS + qt0 + qi) * DD + h * DKK + d;
            Oh[off] = hh; Ol[off] = ll;
        }
        __syncthreads();
    }
}

// ---------------------------------------------------------------------------
// Launch
// ---------------------------------------------------------------------------
extern "C" void kernel_launch(void* const* d_in, const int* in_sizes, int n_in,
                              void* d_out, int out_size) {
    (void)in_sizes; (void)n_in; (void)out_size;

    const int*   ids  = (const int*)  d_in[0];
    const float* emb  = (const float*)d_in[1];
    const float* pe   = (const float*)d_in[2];
    const float* Wq   = (const float*)d_in[3];
    const float* Wk   = (const float*)d_in[4];
    const float* Wv   = (const float*)d_in[5];
    const float* Wo   = (const float*)d_in[6];
    const float* bo   = (const float*)d_in[7];
    const float* ln1s = (const float*)d_in[8];
    const float* ln1b = (const float*)d_in[9];
    const float* ln2s = (const float*)d_in[10];
    const float* ln2b = (const float*)d_in[11];
    const float* W1   = (const float*)d_in[12];
    const float* b1   = (const float*)d_in[13];
    const float* W2   = (const float*)d_in[14];
    const float* b2   = (const float*)d_in[15];
    const float* lnfs = (const float*)d_in[16];
    const float* lnfb = (const float*)d_in[17];
    float* out = (float*)d_out;

    float *x, *q, *k, *v;
    bf16 *hh, *hl, *ah, *al, *ffh, *ffl, *wth, *wtl, *eh, *el;
    cudaGetSymbolAddress((void**)&x,   g_x);
    cudaGetSymbolAddress((void**)&q,   g_q);
    cudaGetSymbolAddress((void**)&k,   g_k);
    cudaGetSymbolAddress((void**)&v,   g_v);
    cudaGetSymbolAddress((void**)&hh,  g_hh);
    cudaGetSymbolAddress((void**)&hl,  g_hl);
    cudaGetSymbolAddress((void**)&ah,  g_ah);
    cudaGetSymbolAddress((void**)&al,  g_al);
    cudaGetSymbolAddress((void**)&ffh, g_ffh);
    cudaGetSymbolAddress((void**)&ffl, g_ffl);
    cudaGetSymbolAddress((void**)&wth, g_wth);
    cudaGetSymbolAddress((void**)&wtl, g_wtl);
    cudaGetSymbolAddress((void**)&eh,  g_eh);
    cudaGetSymbolAddress((void**)&el,  g_el);

    cudaFuncSetAttribute(gemm_hmma<0>, cudaFuncAttributeMaxDynamicSharedMemorySize, SMEM_GEMM);
    cudaFuncSetAttribute(gemm_hmma<1>, cudaFuncAttributeMaxDynamicSharedMemorySize, SMEM_GEMM);
    cudaFuncSetAttribute(gemm_hmma<2>, cudaFuncAttributeMaxDynamicSharedMemorySize, SMEM_GEMM);

    dim3 tb32(32, 8);
    // Weight conversion (transpose + hi/lo split), merged over layers
    {
        dim3 gQ(DD / 32, DD / 32, LL * 4);
        wsplit_qkvo_kernel<<<gQ, tb32>>>(Wq, Wk, Wv, Wo, wth, wtl);
        dim3 g1(FFD / 32, DD / 32, LL);
        wsplit_ff_kernel<<<g1, tb32>>>(W1, wth, wtl, DD, FFD, (size_t)4 * DD * DD);
        dim3 g2(DD / 32, FFD / 32, LL);
        wsplit_ff_kernel<<<g2, tb32>>>(W2, wth, wtl, FFD, DD,
                                       (size_t)4 * DD * DD + (size_t)DD * FFD);
    }
    esplit_kernel<<<((size_t)VV * DD + 255) / 256, 256>>>(emb, eh, el, VV * DD);

    embed_kernel<<<NTOK, 256>>>(ids, emb, pe, x);

    dim3 gD(DD / 128, NTOK / 128);    // 8 x 16
    dim3 gF(FFD / 128, NTOK / 128);   // 32 x 16
    dim3 gV(VV / 128, NTOK / 128);    // 250 x 16

    for (int l = 0; l < LL; l++) {
        size_t base = (size_t)l * WLAYER;
        bf16* wqh = wth + base;                 bf16* wql = wtl + base;
        bf16* wkh = wqh + DD * DD;              bf16* wkl = wql + DD * DD;
        bf16* wvh = wkh + DD * DD;              bf16* wvl = wkl + DD * DD;
        bf16* woh = wvh + DD * DD;              bf16* wol = wvl + DD * DD;
        bf16* w1h = woh + DD * DD;              bf16* w1l = wol + DD * DD;
        bf16* w2h = w1h + (size_t)DD * FFD;     bf16* w2l = w1l + (size_t)DD * FFD;

        ln_split_kernel<<<NTOK, 256>>>(x, ln1s + l * DD, ln1b + l * DD, hh, hl);
        gemm_hmma<0><<<gD, 256, SMEM_GEMM>>>(hh, hl, wqh, wql, nullptr, nullptr, q, nullptr, nullptr, NTOK, DD, DD);
        gemm_hmma<0><<<gD, 256, SMEM_GEMM>>>(hh, hl, wkh, wkl, nullptr, nullptr, k, nullptr, nullptr, NTOK, DD, DD);
        gemm_hmma<0><<<gD, 256, SMEM_GEMM>>>(hh, hl, wvh, wvl, nullptr, nullptr, v, nullptr, nullptr, NTOK, DD, DD);
        attn_kernel<<<BB * HH * (SS / QT), 128>>>(q, k, v, ah, al);
        gemm_hmma<1><<<gD, 256, SMEM_GEMM>>>(ah, al, woh, wol, bo + l * DD, x, x, nullptr, nullptr, NTOK, DD, DD);

        ln_split_kernel<<<NTOK, 256>>>(x, ln2s + l * DD, ln2b + l * DD, hh, hl);
        gemm_hmma<2><<<gF, 256, SMEM_GEMM>>>(hh, hl, w1h, w1l, b1 + l * FFD, nullptr, nullptr, ffh, ffl, NTOK, FFD, DD);
        gemm_hmma<1><<<gD, 256, SMEM_GEMM>>>(ffh, ffl, w2h, w2l, b2 + l * DD, x, x, nullptr, nullptr, NTOK, DD, FFD);
    }

    ln_split_kernel<<<NTOK, 256>>>(x, lnfs, lnfb, hh, hl);
    gemm_hmma<0><<<gV, 256, SMEM_GEMM>>>(hh, hl, eh, el, nullptr, nullptr, out, nullptr, nullptr, NTOK, VV, DD);
}

// round 6
// speedup vs baseline: 5.3738x; 1.0891x over previous
#include <cuda_runtime.h>
#include <cuda_bf16.h>
#include <cuda_fp16.h>
#include <math.h>
#include <stdint.h>

// Problem dims
#define BB   4
#define SS   512
#define DD   1024
#define HH   16
#define LL   6
#define FFD  4096
#define VV   32000
#define DKK  64
#define NTOK (BB*SS)   // 2048
#define QT   8         // queries per attention block
#define RS   (3*DD)    // fused qkv row stride

typedef __nv_bfloat16 bf16;

// ---------------------------------------------------------------------------
// Scratch (device globals — no runtime allocation allowed)
// ---------------------------------------------------------------------------
__device__ float g_x[NTOK*DD];
__device__ float g_qkv[NTOK*3*DD];
__device__ bf16  g_hh[NTOK*DD];
__device__ bf16  g_hl[NTOK*DD];
__device__ bf16  g_ah[NTOK*DD];
__device__ bf16  g_al[NTOK*DD];
__device__ bf16  g_ffh[NTOK*FFD];
__device__ bf16  g_ffl[NTOK*FFD];
__device__ __half g_hf[NTOK*DD];      // final LN out, fp16 hi
__device__ __half g_lf[NTOK*DD];      // final LN out, fp16 lo
__device__ __half g_ef[(size_t)VV*DD]; // emb as fp16 (head B operand)

#define WLAYER (4*DD*DD + 2*DD*FFD)          // elems per layer
__device__ bf16  g_wth[(size_t)LL*WLAYER];
__device__ bf16  g_wtl[(size_t)LL*WLAYER];

__device__ __forceinline__ void split2(float v, bf16& h, bf16& l) {
    h = __float2bfloat16(v);
    l = __float2bfloat16(v - __bfloat162float(h));
}
__device__ __forceinline__ void split2h(float v, __half& h, __half& l) {
    h = __float2half(v);
    l = __float2half(v - __half2float(h));
}

__device__ __forceinline__ uint32_t smem_u32(const void* p) {
    uint32_t a;
    asm("{ .reg .u64 tmp; cvta.to.shared.u64 tmp, %1; cvt.u32.u64 %0, tmp; }"
        : "=r"(a) : "l"(p));
    return a;
}

// cp.async helpers
__device__ __forceinline__ void cp_async16(uint32_t dst, const void* src) {
    asm volatile("cp.async.cg.shared.global [%0], [%1], 16;" :: "r"(dst), "l"(src) : "memory");
}
__device__ __forceinline__ void cp_commit() {
    asm volatile("cp.async.commit_group;" ::: "memory");
}
template <int N>
__device__ __forceinline__ void cp_wait() {
    asm volatile("cp.async.wait_group %0;" :: "n"(N) : "memory");
}

__device__ __forceinline__ void ldsm_x4(unsigned& r0, unsigned& r1, unsigned& r2,
                                        unsigned& r3, uint32_t a) {
    asm volatile("ldmatrix.sync.aligned.m8n8.x4.shared.b16 {%0,%1,%2,%3}, [%4];"
                 : "=r"(r0), "=r"(r1), "=r"(r2), "=r"(r3) : "r"(a));
}

__device__ __forceinline__ void mma16816(float* c, const unsigned* a, const unsigned* b) {
    asm volatile(
        "mma.sync.aligned.m16n8k16.row.col.f32.bf16.bf16.f32 "
        "{%0,%1,%2,%3}, {%4,%5,%6,%7}, {%8,%9}, {%0,%1,%2,%3};\n"
        : "+f"(c[0]), "+f"(c[1]), "+f"(c[2]), "+f"(c[3])
        : "r"(a[0]), "r"(a[1]), "r"(a[2]), "r"(a[3]), "r"(b[0]), "r"(b[1]));
}
__device__ __forceinline__ void mma16816h(float* c, const unsigned* a, const unsigned* b) {
    asm volatile(
        "mma.sync.aligned.m16n8k16.row.col.f32.f16.f16.f32 "
        "{%0,%1,%2,%3}, {%4,%5,%6,%7}, {%8,%9}, {%0,%1,%2,%3};\n"
        : "+f"(c[0]), "+f"(c[1]), "+f"(c[2]), "+f"(c[3])
        : "r"(a[0]), "r"(a[1]), "r"(a[2]), "r"(a[3]), "r"(b[0]), "r"(b[1]));
}

// ---------------------------------------------------------------------------
// Embedding + batch-indexed positional encoding (faithful to reference):
//   x[b,s,:] = emb[ids[b,s],:] + pe[b,:]
// ---------------------------------------------------------------------------
__global__ void embed_kernel(const int* __restrict__ ids,
                             const float* __restrict__ emb,
                             const float* __restrict__ pe,
                             float* __restrict__ x) {
    int row = blockIdx.x;
    int b   = row / SS;
    int id  = ids[row];
    const float4* er = (const float4*)(emb + (size_t)id * DD);
    const float4* pr = (const float4*)(pe  + (size_t)b  * DD);
    float4* xr = (float4*)(x + (size_t)row * DD);
    int i = threadIdx.x;           // 256 threads, 256 float4 per row
    float4 e = er[i], p = pr[i];
    xr[i] = make_float4(e.x + p.x, e.y + p.y, e.z + p.z, e.w + p.w);
}

// ---------------------------------------------------------------------------
// Weight transpose + split, merged over layers
// ---------------------------------------------------------------------------
__device__ __forceinline__ void wsplit_body(const float* __restrict__ W,
                                            bf16* __restrict__ Th, bf16* __restrict__ Tl,
                                            int K, int N) {
    __shared__ float tile[32][33];
    int n0 = blockIdx.x * 32, k0 = blockIdx.y * 32;
    int tx = threadIdx.x, ty = threadIdx.y;   // 32 x 8
    #pragma unroll
    for (int i = 0; i < 4; i++)
        tile[ty + i*8][tx] = W[(size_t)(k0 + ty + i*8) * N + n0 + tx];
    __syncthreads();
    #pragma unroll
    for (int i = 0; i < 4; i++) {
        float v = tile[tx][ty + i*8];
        size_t o = (size_t)(n0 + ty + i*8) * K + k0 + tx;
        bf16 h, l; split2(v, h, l);
        Th[o] = h; Tl[o] = l;
    }
}

__global__ void wsplit_qkvo_kernel(const float* __restrict__ Wq, const float* __restrict__ Wk,
                                   const float* __restrict__ Wv, const float* __restrict__ Wo,
                                   bf16* __restrict__ Th, bf16* __restrict__ Tl) {
    int z = blockIdx.z, l = z >> 2, widx = z & 3;
    const float* W = (widx == 0 ? Wq : widx == 1 ? Wk : widx == 2 ? Wv : Wo)
                     + (size_t)l * DD * DD;
    size_t ob = (size_t)l * WLAYER + (size_t)widx * DD * DD;
    wsplit_body(W, Th + ob, Tl + ob, DD, DD);
}

__global__ void wsplit_ff_kernel(const float* __restrict__ W,
                                 bf16* __restrict__ Th, bf16* __restrict__ Tl,
                                 int K, int N, size_t obase) {
    int l = blockIdx.z;
    const float* Wl = W + (size_t)l * K * N;
    size_t ob = (size_t)l * WLAYER + obase;
    wsplit_body(Wl, Th + ob, Tl + ob, K, N);
}

// emb -> fp16 (vectorized: 4 floats/thread)
__global__ void ehalf_kernel(const float* __restrict__ X, __half* __restrict__ Y, int n4) {
    int i = blockIdx.x * 256 + threadIdx.x;
    if (i < n4) {
        float4 v = ((const float4*)X)[i];
        __half2 a = __floats2half2_rn(v.x, v.y);
        __half2 b = __floats2half2_rn(v.z, v.w);
        ((__half2*)Y)[i * 2]     = a;
        ((__half2*)Y)[i * 2 + 1] = b;
    }
}

// ---------------------------------------------------------------------------
// LayerNorm with split output (bf16 pair for layers, fp16 pair for head)
// ---------------------------------------------------------------------------
template <int F16>
__global__ void ln_split_kernel(const float* __restrict__ x,
                                const float* __restrict__ s,
                                const float* __restrict__ b,
                                bf16* __restrict__ yh, bf16* __restrict__ yl,
                                __half* __restrict__ fh, __half* __restrict__ fl) {
    int row = blockIdx.x;
    int t = threadIdx.x;
    const float* xr = x + (size_t)row * DD;
    float s1 = 0.f, s2 = 0.f;
    for (int i = t; i < DD; i += 256) {
        float v = xr[i];
        s1 += v; s2 += v * v;
    }
    __shared__ float r1[256], r2[256];
    r1[t] = s1; r2[t] = s2;
    __syncthreads();
    for (int st = 128; st > 0; st >>= 1) {
        if (t < st) { r1[t] += r1[t + st]; r2[t] += r2[t + st]; }
        __syncthreads();
    }
    __shared__ float sm_mean, sm_rstd;
    if (t == 0) {
        float mean = r1[0] * (1.0f / DD);
        float var  = r2[0] * (1.0f / DD) - mean * mean;
        sm_mean = mean;
        sm_rstd = rsqrtf(var + 1e-5f);
    }
    __syncthreads();
    float mean = sm_mean, rstd = sm_rstd;
    for (int i = t; i < DD; i += 256) {
        float y = (xr[i] - mean) * rstd * s[i] + b[i];
        if (F16) {
            __half h, l; split2h(y, h, l);
            fh[(size_t)row * DD + i] = h;
            fl[(size_t)row * DD + i] = l;
        } else {
            bf16 h, l; split2(y, h, l);
            yh[(size_t)row * DD + i] = h;
            yl[(size_t)row * DD + i] = l;
        }
    }
}

// ---------------------------------------------------------------------------
// Split-bf16 HMMA GEMM (NT): C[M,N] = (Ah+Al)[M,K] @ (Bh+Bl)[N,K]^T
// 3-product compensation: hh + hl + lh, fp32 accumulate.
// 128x128 CTA tile, BK=32, 256 threads, cp.async double-buffer + ldmatrix.
// EPI 0: C = AB (+bias)            -> fp32
// EPI 1: C = Cin + AB (+bias)      -> fp32 (residual)
// EPI 2: gelu(AB + bias)           -> split bf16 (Oh, Ol)
// ---------------------------------------------------------------------------
#define ROWB 80                         // bytes per smem row (64 data + 16 pad)
#define MATB (128 * ROWB)               // 10240 bytes per matrix tile
#define STAGEB (4 * MATB)               // 40960 bytes per stage
#define SMEM_GEMM (2 * STAGEB)          // 81920 bytes

template <int EPI>
__global__ __launch_bounds__(256, 2)
void gemm_hmma(const bf16* __restrict__ Ah, const bf16* __restrict__ Al,
               const bf16* __restrict__ Bh, const bf16* __restrict__ Bl,
               const float* __restrict__ bias, const float* __restrict__ Cin,
               float* __restrict__ Cout, bf16* __restrict__ Oh, bf16* __restrict__ Ol,
               int M, int N, int K) {
    extern __shared__ char smem[];
    uint32_t sb = smem_u32(smem);

    int t = threadIdx.x;
    int wid = t >> 5, lane = t & 31;
    int wm = wid >> 1, wn = wid & 1;
    int group = lane >> 2, tig = lane & 3;
    int m0 = blockIdx.y * 128, n0 = blockIdx.x * 128;

    float acc[2][8][4];
    #pragma unroll
    for (int i = 0; i < 2; i++)
        #pragma unroll
        for (int j = 0; j < 8; j++)
            #pragma unroll
            for (int kk = 0; kk < 4; kk++) acc[i][j][kk] = 0.f;

    const bf16* srcs[4] = { Ah, Al, Bh, Bl };

    auto load_stage = [&](int stage, int kt) {
        uint32_t base = sb + stage * STAGEB;
        int kofs = kt << 5;
        #pragma unroll
        for (int j = 0; j < 8; j++) {
            int lin = t + j * 256;
            int mtx = lin >> 9;
            int c   = lin & 511;
            int row = c >> 2, q = c & 3;
            int rbase = (mtx < 2) ? m0 : n0;
            const bf16* src = srcs[mtx] + (size_t)(rbase + row) * K + kofs + q * 8;
            cp_async16(base + mtx * MATB + row * ROWB + q * 16, src);
        }
        cp_commit();
    };

    uint32_t aRow = (uint32_t)(wm * 32 + (lane & 15)) * ROWB;
    uint32_t aCol = (uint32_t)((lane >> 4) << 3) * 2;
    uint32_t bRowBase = (uint32_t)(wn * 64 + (lane & 7) + ((lane >> 4) << 3)) * ROWB;
    uint32_t bCol = (uint32_t)(((lane >> 3) & 1) << 3) * 2;

    const int nk = K >> 5;

    load_stage(0, 0);

    for (int i = 0; i < nk; i++) {
        if (i + 1 < nk) { load_stage((i + 1) & 1, i + 1); cp_wait<1>(); }
        else            { cp_wait<0>(); }
        __syncthreads();

        uint32_t stb = sb + (i & 1) * STAGEB;
        uint32_t pAh = stb + aRow + aCol;
        uint32_t pAl = stb + MATB + aRow + aCol;
        uint32_t pBh = stb + 2 * MATB + bRowBase + bCol;
        uint32_t pBl = stb + 3 * MATB + bRowBase + bCol;

        #pragma unroll
        for (int ks = 0; ks < 2; ks++) {
            uint32_t ko = ks * 32;
            unsigned afh[2][4], afl[2][4], bfh[8][2], bfl[8][2];
            #pragma unroll
            for (int mt = 0; mt < 2; mt++) {
                ldsm_x4(afh[mt][0], afh[mt][1], afh[mt][2], afh[mt][3],
                        pAh + (uint32_t)(mt * 16) * ROWB + ko);
                ldsm_x4(afl[mt][0], afl[mt][1], afl[mt][2], afl[mt][3],
                        pAl + (uint32_t)(mt * 16) * ROWB + ko);
            }
            #pragma unroll
            for (int jp = 0; jp < 4; jp++) {
                ldsm_x4(bfh[2*jp][0], bfh[2*jp][1], bfh[2*jp+1][0], bfh[2*jp+1][1],
                        pBh + (uint32_t)(jp * 16) * ROWB + ko);
                ldsm_x4(bfl[2*jp][0], bfl[2*jp][1], bfl[2*jp+1][0], bfl[2*jp+1][1],
                        pBl + (uint32_t)(jp * 16) * ROWB + ko);
            }
            #pragma unroll
            for (int mt = 0; mt < 2; mt++)
                #pragma unroll
                for (int nt = 0; nt < 8; nt++) {
                    mma16816(acc[mt][nt], afh[mt], bfh[nt]);
                    mma16816(acc[mt][nt], afh[mt], bfl[nt]);
                    mma16816(acc[mt][nt], afl[mt], bfh[nt]);
                }
        }
        __syncthreads();
    }

    #pragma unroll
    for (int mt = 0; mt < 2; mt++) {
        #pragma unroll
        for (int nt = 0; nt < 8; nt++) {
            int col = n0 + wn * 64 + nt * 8 + tig * 2;
            float b0 = 0.f, b1v = 0.f;
            if (bias) { b0 = bias[col]; b1v = bias[col + 1]; }
            #pragma unroll
            for (int half = 0; half < 2; half++) {
                int row = m0 + wm * 32 + mt * 16 + group + half * 8;
                float v0 = acc[mt][nt][half * 2 + 0] + b0;
                float v1 = acc[mt][nt][half * 2 + 1] + b1v;
                size_t o = (size_t)row * N + col;
                if (EPI == 0) {
                    Cout[o] = v0; Cout[o + 1] = v1;
                } else if (EPI == 1) {
                    Cout[o] = Cin[o] + v0; Cout[o + 1] = Cin[o + 1] + v1;
                } else {
                    float g0 = 0.5f * v0 * (1.0f + erff(v0 * 0.70710678118654752f));
                    float g1 = 0.5f * v1 * (1.0f + erff(v1 * 0.70710678118654752f));
                    bf16 h, l;
                    split2(g0, h, l); Oh[o] = h;     Ol[o] = l;
                    split2(g1, h, l); Oh[o + 1] = h; Ol[o + 1] = l;
                }
            }
        }
    }
}

// ---------------------------------------------------------------------------
// fp16 2-product head GEMM (NT): C = (Ah+Al)[M,K] @ Bh[N,K]^T
// products: ah*bh + al*bh = a*bh exactly. 3 smem matrices per stage.
// ---------------------------------------------------------------------------
#define H_STAGEB (3 * MATB)             // 30720 bytes per stage
#define SMEM_HEAD (2 * H_STAGEB)        // 61440 bytes

__global__ __launch_bounds__(256, 2)
void gemm_f16_head(const __half* __restrict__ Ah, const __half* __restrict__ Al,
                   const __half* __restrict__ Bh,
                   float* __restrict__ Cout, int M, int N, int K) {
    extern __shared__ char smem[];
    uint32_t sb = smem_u32(smem);

    int t = threadIdx.x;
    int wid = t >> 5, lane = t & 31;
    int wm = wid >> 1, wn = wid & 1;
    int group = lane >> 2, tig = lane & 3;
    int m0 = blockIdx.y * 128, n0 = blockIdx.x * 128;

    float acc[2][8][4];
    #pragma unroll
    for (int i = 0; i < 2; i++)
        #pragma unroll
        for (int j = 0; j < 8; j++)
            #pragma unroll
            for (int kk = 0; kk < 4; kk++) acc[i][j][kk] = 0.f;

    const __half* srcs[3] = { Ah, Al, Bh };

    auto load_stage = [&](int stage, int kt) {
        uint32_t base = sb + stage * H_STAGEB;
        int kofs = kt << 5;
        #pragma unroll
        for (int j = 0; j < 6; j++) {
            int lin = t + j * 256;           // 0..1535
            int mtx = lin >> 9;
            int c   = lin & 511;
            int row = c >> 2, q = c & 3;
            int rbase = (mtx < 2) ? m0 : n0;
            const __half* src = srcs[mtx] + (size_t)(rbase + row) * K + kofs + q * 8;
            cp_async16(base + mtx * MATB + row * ROWB + q * 16, src);
        }
        cp_commit();
    };

    uint32_t aRow = (uint32_t)(wm * 32 + (lane & 15)) * ROWB;
    uint32_t aCol = (uint32_t)((lane >> 4) << 3) * 2;
    uint32_t bRowBase = (uint32_t)(wn * 64 + (lane & 7) + ((lane >> 4) << 3)) * ROWB;
    uint32_t bCol = (uint32_t)(((lane >> 3) & 1) << 3) * 2;

    const int nk = K >> 5;

    load_stage(0, 0);

    for (int i = 0; i < nk; i++) {
        if (i + 1 < nk) { load_stage((i + 1) & 1, i + 1); cp_wait<1>(); }
        else            { cp_wait<0>(); }
        __syncthreads();

        uint32_t stb = sb + (i & 1) * H_STAGEB;
        uint32_t pAh = stb + aRow + aCol;
        uint32_t pAl = stb + MATB + aRow + aCol;
        uint32_t pBh = stb + 2 * MATB + bRowBase + bCol;

        #pragma unroll
        for (int ks = 0; ks < 2; ks++) {
            uint32_t ko = ks * 32;
            unsigned afh[2][4], afl[2][4], bfh[8][2];
            #pragma unroll
            for (int mt = 0; mt < 2; mt++) {
                ldsm_x4(afh[mt][0], afh[mt][1], afh[mt][2], afh[mt][3],
                        pAh + (uint32_t)(mt * 16) * ROWB + ko);
                ldsm_x4(afl[mt][0], afl[mt][1], afl[mt][2], afl[mt][3],
                        pAl + (uint32_t)(mt * 16) * ROWB + ko);
            }
            #pragma unroll
            for (int jp = 0; jp < 4; jp++) {
                ldsm_x4(bfh[2*jp][0], bfh[2*jp][1], bfh[2*jp+1][0], bfh[2*jp+1][1],
                        pBh + (uint32_t)(jp * 16) * ROWB + ko);
            }
            #pragma unroll
            for (int mt = 0; mt < 2; mt++)
                #pragma unroll
                for (int nt = 0; nt < 8; nt++) {
                    mma16816h(acc[mt][nt], afh[mt], bfh[nt]);
                    mma16816h(acc[mt][nt], afl[mt], bfh[nt]);
                }
        }
        __syncthreads();
    }

    #pragma unroll
    for (int mt = 0; mt < 2; mt++) {
        #pragma unroll
        for (int nt = 0; nt < 8; nt++) {
            int col = n0 + wn * 64 + nt * 8 + tig * 2;
            #pragma unroll
            for (int half = 0; half < 2; half++) {
                int row = m0 + wm * 32 + mt * 16 + group + half * 8;
                size_t o = (size_t)row * N + col;
                Cout[o]     = acc[mt][nt][half * 2 + 0];
                Cout[o + 1] = acc[mt][nt][half * 2 + 1];
            }
        }
    }
}

// ---------------------------------------------------------------------------
// Causal attention from fused QKV buffer (row stride 3*DD).
// One block = (b, h, 8 queries). Exact softmax. Split-bf16 output.
// ---------------------------------------------------------------------------
__global__ __launch_bounds__(128)
void attn_kernel(const float* __restrict__ QKV,
                 bf16* __restrict__ Oh, bf16* __restrict__ Ol) {
    const int NQB = SS / QT;
    int qt0 = (blockIdx.x % NQB) * QT;
    int bh  = blockIdx.x / NQB;
    int h   = bh % HH, b = bh / HH;
    int t   = threadIdx.x;

    __shared__ float qs[QT][DKK];
    __shared__ float Ks[64][DKK + 1];
    __shared__ float sc[QT][SS + 16];
    __shared__ float red[128];
    __shared__ float mx[QT], dn[QT];

    const float* Qp = QKV + h * DKK;            // q cols
    const float* Kp = QKV + DD + h * DKK;       // k cols
    const float* Vp = QKV + 2 * DD + h * DKK;   // v cols

    for (int i = t; i < QT * DKK; i += 128) {
        int qi = i >> 6, d = i & 63;
        qs[qi][d] = Qp[(size_t)(b * SS + qt0 + qi) * RS + d];
    }
    __syncthreads();

    const int nkmax = qt0 + QT;
    const float scale = 0.125f;

    for (int kt = 0; kt < nkmax; kt += 64) {
        int rows = min(64, nkmax - kt);
        for (int i = t; i < rows * DKK; i += 128) {
            int r = i >> 6, d = i & 63;
            Ks[r][d] = Kp[(size_t)(b * SS + kt + r) * RS + d];
        }
        __syncthreads();
        int j = t & 63, qh = t >> 6;
        if (j < rows) {
            int kglob = kt + j;
            for (int qi = qh; qi < QT; qi += 2) {
                float dot = 0.f;
                #pragma unroll
                for (int d = 0; d < DKK; d++) dot += qs[qi][d] * Ks[j][d];
                sc[qi][kglob] = (kglob <= qt0 + qi) ? dot * scale : -1e30f;
            }
        }
        __syncthreads();
    }

    int tq = t >> 4, r = t & 15;
    float m = -1e30f;
    for (int k = r; k < nkmax; k += 16) m = fmaxf(m, sc[tq][k]);
    red[t] = m;
    __syncthreads();
    for (int st = 8; st > 0; st >>= 1) {
        if (r < st) red[t] = fmaxf(red[t], red[t + st]);
        __syncthreads();
    }
    if (r == 0) mx[tq] = red[t];
    __syncthreads();
    float mval = mx[tq];
    float s = 0.f;
    for (int k = r; k < nkmax; k += 16) {
        float e = expf(sc[tq][k] - mval);
        sc[tq][k] = e;
        s += e;
    }
    red[t] = s;
    __syncthreads();
    for (int st = 8; st > 0; st >>= 1) {
        if (r < st) red[t] += red[t + st];
        __syncthreads();
    }
    if (r == 0) dn[tq] = red[t];
    __syncthreads();

    int d = t & 63, part = t >> 6;
    float acc[QT];
    #pragma unroll
    for (int qi = 0; qi < QT; qi++) acc[qi] = 0.f;
    for (int k = part; k < nkmax; k += 2) {
        float v = Vp[(size_t)(b * SS + k) * RS + d];
        #pragma unroll
        for (int qi = 0; qi < QT; qi++) acc[qi] += sc[qi][k] * v;
    }
    for (int qi = 0; qi < QT; qi++) {
        red[t] = acc[qi];
        __syncthreads();
        if (part == 0) {
            float o = (red[t] + red[t + 64]) / dn[qi];
            bf16 hh, ll; split2(o, hh, ll);
            size_t off = (size_t)(b * SS + qt0 + qi) * DD + h * DKK + d;
            Oh[off] = hh; Ol[off] = ll;
        }
        __syncthreads();
    }
}

// ---------------------------------------------------------------------------
// Launch
// ---------------------------------------------------------------------------
extern "C" void kernel_launch(void* const* d_in, const int* in_sizes, int n_in,
                              void* d_out, int out_size) {
    (void)in_sizes; (void)n_in; (void)out_size;

    const int*   ids  = (const int*)  d_in[0];
    const float* emb  = (const float*)d_in[1];
    const float* pe   = (const float*)d_in[2];
    const float* Wq   = (const float*)d_in[3];
    const float* Wk   = (const float*)d_in[4];
    const float* Wv   = (const float*)d_in[5];
    const float* Wo   = (const float*)d_in[6];
    const float* bo   = (const float*)d_in[7];
    const float* ln1s = (const float*)d_in[8];
    const float* ln1b = (const float*)d_in[9];
    const float* ln2s = (const float*)d_in[10];
    const float* ln2b = (const float*)d_in[11];
    const float* W1   = (const float*)d_in[12];
    const float* b1   = (const float*)d_in[13];
    const float* W2   = (const float*)d_in[14];
    const float* b2   = (const float*)d_in[15];
    const float* lnfs = (const float*)d_in[16];
    const float* lnfb = (const float*)d_in[17];
    float* out = (float*)d_out;

    float *x, *qkv;
    bf16 *hh, *hl, *ah, *al, *ffh, *ffl, *wth, *wtl;
    __half *hf, *lf, *ef;
    cudaGetSymbolAddress((void**)&x,   g_x);
    cudaGetSymbolAddress((void**)&qkv, g_qkv);
    cudaGetSymbolAddress((void**)&hh,  g_hh);
    cudaGetSymbolAddress((void**)&hl,  g_hl);
    cudaGetSymbolAddress((void**)&ah,  g_ah);
    cudaGetSymbolAddress((void**)&al,  g_al);
    cudaGetSymbolAddress((void**)&ffh, g_ffh);
    cudaGetSymbolAddress((void**)&ffl, g_ffl);
    cudaGetSymbolAddress((void**)&wth, g_wth);
    cudaGetSymbolAddress((void**)&wtl, g_wtl);
    cudaGetSymbolAddress((void**)&hf,  g_hf);
    cudaGetSymbolAddress((void**)&lf,  g_lf);
    cudaGetSymbolAddress((void**)&ef,  g_ef);

    cudaFuncSetAttribute(gemm_hmma<0>, cudaFuncAttributeMaxDynamicSharedMemorySize, SMEM_GEMM);
    cudaFuncSetAttribute(gemm_hmma<1>, cudaFuncAttributeMaxDynamicSharedMemorySize, SMEM_GEMM);
    cudaFuncSetAttribute(gemm_hmma<2>, cudaFuncAttributeMaxDynamicSharedMemorySize, SMEM_GEMM);
    cudaFuncSetAttribute(gemm_f16_head, cudaFuncAttributeMaxDynamicSharedMemorySize, SMEM_HEAD);

    dim3 tb32(32, 8);
    {
        dim3 gQ(DD / 32, DD / 32, LL * 4);
        wsplit_qkvo_kernel<<<gQ, tb32>>>(Wq, Wk, Wv, Wo, wth, wtl);
        dim3 g1(FFD / 32, DD / 32, LL);
        wsplit_ff_kernel<<<g1, tb32>>>(W1, wth, wtl, DD, FFD, (size_t)4 * DD * DD);
        dim3 g2(DD / 32, FFD / 32, LL);
        wsplit_ff_kernel<<<g2, tb32>>>(W2, wth, wtl, FFD, DD,
                                       (size_t)4 * DD * DD + (size_t)DD * FFD);
    }
    {
        int n4 = (VV * DD) / 4;
        ehalf_kernel<<<(n4 + 255) / 256, 256>>>(emb, ef, n4);
    }

    embed_kernel<<<NTOK, 256>>>(ids, emb, pe, x);

    dim3 gQKV(3 * DD / 128, NTOK / 128);  // 24 x 16 = 384 CTAs
    dim3 gD(DD / 128, NTOK / 128);        // 8 x 16
    dim3 gF(FFD / 128, NTOK / 128);       // 32 x 16
    dim3 gV(VV / 128, NTOK / 128);        // 250 x 16

    for (int l = 0; l < LL; l++) {
        size_t base = (size_t)l * WLAYER;
        bf16* wqkvh = wth + base;               bf16* wqkvl = wtl + base;   // [3*DD][DD]
        bf16* woh = wqkvh + 3 * DD * DD;        bf16* wol = wqkvl + 3 * DD * DD;
        bf16* w1h = woh + DD * DD;              bf16* w1l = wol + DD * DD;
        bf16* w2h = w1h + (size_t)DD * FFD;     bf16* w2l = w1l + (size_t)DD * FFD;

        ln_split_kernel<0><<<NTOK, 256>>>(x, ln1s + l * DD, ln1b + l * DD, hh, hl, nullptr, nullptr);
        gemm_hmma<0><<<gQKV, 256, SMEM_GEMM>>>(hh, hl, wqkvh, wqkvl, nullptr, nullptr, qkv, nullptr, nullptr, NTOK, 3 * DD, DD);
        attn_kernel<<<BB * HH * (SS / QT), 128>>>(qkv, ah, al);
        gemm_hmma<1><<<gD, 256, SMEM_GEMM>>>(ah, al, woh, wol, bo + l * DD, x, x, nullptr, nullptr, NTOK, DD, DD);

        ln_split_kernel<0><<<NTOK, 256>>>(x, ln2s + l * DD, ln2b + l * DD, hh, hl, nullptr, nullptr);
        gemm_hmma<2><<<gF, 256, SMEM_GEMM>>>(hh, hl, w1h, w1l, b1 + l * FFD, nullptr, nullptr, ffh, ffl, NTOK, FFD, DD);
        gemm_hmma<1><<<gD, 256, SMEM_GEMM>>>(ffh, ffl, w2h, w2l, b2 + l * DD, x, x, nullptr, nullptr, NTOK, DD, FFD);
    }

    ln_split_kernel<1><<<NTOK, 256>>>(x, lnfs, lnfb, nullptr, nullptr, hf, lf);
    gemm_f16_head<<<gV, 256, SMEM_HEAD>>>(hf, lf, ef, out, NTOK, VV, DD);
}

// round 7
// speedup vs baseline: 6.2925x; 1.1710x over previous
#include <cuda_runtime.h>
#include <cuda_bf16.h>
#include <cuda_fp16.h>
#include <math.h>
#include <stdint.h>

// Problem dims
#define BB   4
#define SS   512
#define DD   1024
#define HH   16
#define LL   6
#define FFD  4096
#define VV   32000
#define DKK  64
#define NTOK (BB*SS)   // 2048
#define QT   8         // queries per attention block
#define RS   (3*DD)    // fused qkv row stride

typedef __nv_bfloat16 bf16;

// ---------------------------------------------------------------------------
// Scratch (device globals — no runtime allocation allowed)
// ---------------------------------------------------------------------------
__device__ float g_x[NTOK*DD];
__device__ float g_qkv[NTOK*3*DD];
__device__ bf16  g_hh[NTOK*DD];        // ln1 out, bf16 split (QKV A operand)
__device__ bf16  g_hl[NTOK*DD];
__device__ bf16  g_ah[NTOK*DD];        // attention out, bf16 split (Wo A)
__device__ bf16  g_al[NTOK*DD];
__device__ __half g_ffh[NTOK*FFD];     // GELU out, fp16 split (W2 A)
__device__ __half g_ffl[NTOK*FFD];
__device__ __half g_hf[NTOK*DD];       // ln2 / lnf out, fp16 hi
__device__ __half g_lf[NTOK*DD];       // ln2 / lnf out, fp16 lo
__device__ __half g_ef[(size_t)VV*DD]; // emb as fp16 (head B)

#define WLAYER_B (4*DD*DD)             // bf16 split weights per layer (qkv+o)
#define WLAYER_F (2*DD*FFD)            // fp16 weights per layer (ff1+ff2)
__device__ bf16   g_wth[(size_t)LL*WLAYER_B];
__device__ bf16   g_wtl[(size_t)LL*WLAYER_B];
__device__ __half g_wf [(size_t)LL*WLAYER_F];

__device__ __forceinline__ void split2(float v, bf16& h, bf16& l) {
    h = __float2bfloat16(v);
    l = __float2bfloat16(v - __bfloat162float(h));
}
__device__ __forceinline__ void split2h(float v, __half& h, __half& l) {
    h = __float2half(v);
    l = __float2half(v - __half2float(h));
}

__device__ __forceinline__ uint32_t smem_u32(const void* p) {
    uint32_t a;
    asm("{ .reg .u64 tmp; cvta.to.shared.u64 tmp, %1; cvt.u32.u64 %0, tmp; }"
        : "=r"(a) : "l"(p));
    return a;
}

// cp.async helpers
__device__ __forceinline__ void cp_async16(uint32_t dst, const void* src) {
    asm volatile("cp.async.cg.shared.global [%0], [%1], 16;" :: "r"(dst), "l"(src) : "memory");
}
__device__ __forceinline__ void cp_commit() {
    asm volatile("cp.async.commit_group;" ::: "memory");
}
template <int N>
__device__ __forceinline__ void cp_wait() {
    asm volatile("cp.async.wait_group %0;" :: "n"(N) : "memory");
}

__device__ __forceinline__ void ldsm_x4(unsigned& r0, unsigned& r1, unsigned& r2,
                                        unsigned& r3, uint32_t a) {
    asm volatile("ldmatrix.sync.aligned.m8n8.x4.shared.b16 {%0,%1,%2,%3}, [%4];"
                 : "=r"(r0), "=r"(r1), "=r"(r2), "=r"(r3) : "r"(a));
}

__device__ __forceinline__ void mma16816(float* c, const unsigned* a, const unsigned* b) {
    asm volatile(
        "mma.sync.aligned.m16n8k16.row.col.f32.bf16.bf16.f32 "
        "{%0,%1,%2,%3}, {%4,%5,%6,%7}, {%8,%9}, {%0,%1,%2,%3};\n"
        : "+f"(c[0]), "+f"(c[1]), "+f"(c[2]), "+f"(c[3])
        : "r"(a[0]), "r"(a[1]), "r"(a[2]), "r"(a[3]), "r"(b[0]), "r"(b[1]));
}
__device__ __forceinline__ void mma16816h(float* c, const unsigned* a, const unsigned* b) {
    asm volatile(
        "mma.sync.aligned.m16n8k16.row.col.f32.f16.f16.f32 "
        "{%0,%1,%2,%3}, {%4,%5,%6,%7}, {%8,%9}, {%0,%1,%2,%3};\n"
        : "+f"(c[0]), "+f"(c[1]), "+f"(c[2]), "+f"(c[3])
        : "r"(a[0]), "r"(a[1]), "r"(a[2]), "r"(a[3]), "r"(b[0]), "r"(b[1]));
}

// ---------------------------------------------------------------------------
// Embedding + batch-indexed positional encoding (faithful to reference)
// ---------------------------------------------------------------------------
__global__ void embed_kernel(const int* __restrict__ ids,
                             const float* __restrict__ emb,
                             const float* __restrict__ pe,
                             float* __restrict__ x) {
    int row = blockIdx.x;
    int b   = row / SS;
    int id  = ids[row];
    const float4* er = (const float4*)(emb + (size_t)id * DD);
    const float4* pr = (const float4*)(pe  + (size_t)b  * DD);
    float4* xr = (float4*)(x + (size_t)row * DD);
    int i = threadIdx.x;
    float4 e = er[i], p = pr[i];
    xr[i] = make_float4(e.x + p.x, e.y + p.y, e.z + p.z, e.w + p.w);
}

// ---------------------------------------------------------------------------
// Weight conversion kernels
// ---------------------------------------------------------------------------
// transpose + bf16 hi/lo split (qkv + o weights)
__global__ void wsplit_qkvo_kernel(const float* __restrict__ Wq, const float* __restrict__ Wk,
                                   const float* __restrict__ Wv, const float* __restrict__ Wo,
                                   bf16* __restrict__ Th, bf16* __restrict__ Tl) {
    __shared__ float tile[32][33];
    int z = blockIdx.z, l = z >> 2, widx = z & 3;
    const float* W = (widx == 0 ? Wq : widx == 1 ? Wk : widx == 2 ? Wv : Wo)
                     + (size_t)l * DD * DD;
    size_t ob = (size_t)l * WLAYER_B + (size_t)widx * DD * DD;
    const int K = DD, N = DD;
    int n0 = blockIdx.x * 32, k0 = blockIdx.y * 32;
    int tx = threadIdx.x, ty = threadIdx.y;
    #pragma unroll
    for (int i = 0; i < 4; i++)
        tile[ty + i*8][tx] = W[(size_t)(k0 + ty + i*8) * N + n0 + tx];
    __syncthreads();
    #pragma unroll
    for (int i = 0; i < 4; i++) {
        float v = tile[tx][ty + i*8];
        size_t o = ob + (size_t)(n0 + ty + i*8) * K + k0 + tx;
        bf16 h, l2; split2(v, h, l2);
        Th[o] = h; Tl[o] = l2;
    }
}

// transpose + single fp16 (ff weights)
__global__ void whalf_ff_kernel(const float* __restrict__ W,
                                __half* __restrict__ T,
                                int K, int N, size_t obase) {
    __shared__ float tile[32][33];
    int l = blockIdx.z;
    const float* Wl = W + (size_t)l * K * N;
    size_t ob = (size_t)l * WLAYER_F + obase;
    int n0 = blockIdx.x * 32, k0 = blockIdx.y * 32;
    int tx = threadIdx.x, ty = threadIdx.y;
    #pragma unroll
    for (int i = 0; i < 4; i++)
        tile[ty + i*8][tx] = Wl[(size_t)(k0 + ty + i*8) * N + n0 + tx];
    __syncthreads();
    #pragma unroll
    for (int i = 0; i < 4; i++)
        T[ob + (size_t)(n0 + ty + i*8) * K + k0 + tx] = __float2half(tile[tx][ty + i*8]);
}

// emb -> fp16 (vectorized)
__global__ void ehalf_kernel(const float* __restrict__ X, __half* __restrict__ Y, int n4) {
    int i = blockIdx.x * 256 + threadIdx.x;
    if (i < n4) {
        float4 v = ((const float4*)X)[i];
        ((__half2*)Y)[i * 2]     = __floats2half2_rn(v.x, v.y);
        ((__half2*)Y)[i * 2 + 1] = __floats2half2_rn(v.z, v.w);
    }
}

// ---------------------------------------------------------------------------
// LayerNorm, fully vectorized (1 float4/thread), split output
// F16=0 -> bf16 pair, F16=1 -> fp16 pair
// ---------------------------------------------------------------------------
template <int F16>
__global__ void ln_split_kernel(const float* __restrict__ x,
                                const float* __restrict__ s,
                                const float* __restrict__ b,
                                bf16* __restrict__ yh, bf16* __restrict__ yl,
                                __half* __restrict__ fh, __half* __restrict__ fl) {
    int row = blockIdx.x;
    int t = threadIdx.x;
    float4 v = ((const float4*)(x + (size_t)row * DD))[t];
    float s1 = v.x + v.y + v.z + v.w;
    float s2 = v.x*v.x + v.y*v.y + v.z*v.z + v.w*v.w;
    __shared__ float r1[256], r2[256];
    r1[t] = s1; r2[t] = s2;
    __syncthreads();
    for (int st = 128; st > 0; st >>= 1) {
        if (t < st) { r1[t] += r1[t + st]; r2[t] += r2[t + st]; }
        __syncthreads();
    }
    __shared__ float sm_mean, sm_rstd;
    if (t == 0) {
        float mean = r1[0] * (1.0f / DD);
        float var  = r2[0] * (1.0f / DD) - mean * mean;
        sm_mean = mean;
        sm_rstd = rsqrtf(var + 1e-5f);
    }
    __syncthreads();
    float mean = sm_mean, rstd = sm_rstd;
    float4 sv = ((const float4*)s)[t];
    float4 bv = ((const float4*)b)[t];
    float y0 = (v.x - mean) * rstd * sv.x + bv.x;
    float y1 = (v.y - mean) * rstd * sv.y + bv.y;
    float y2 = (v.z - mean) * rstd * sv.z + bv.z;
    float y3 = (v.w - mean) * rstd * sv.w + bv.w;
    size_t o = (size_t)row * DD + t * 4;
    if (F16) {
        __half h0,l0,h1,l1,h2,l2,h3,l3;
        split2h(y0,h0,l0); split2h(y1,h1,l1); split2h(y2,h2,l2); split2h(y3,h3,l3);
        *(uint64_t*)&fh[o] = (uint64_t)__half_as_ushort(h0) | ((uint64_t)__half_as_ushort(h1)<<16)
                           | ((uint64_t)__half_as_ushort(h2)<<32) | ((uint64_t)__half_as_ushort(h3)<<48);
        *(uint64_t*)&fl[o] = (uint64_t)__half_as_ushort(l0) | ((uint64_t)__half_as_ushort(l1)<<16)
                           | ((uint64_t)__half_as_ushort(l2)<<32) | ((uint64_t)__half_as_ushort(l3)<<48);
    } else {
        bf16 h0,l0,h1,l1,h2,l2,h3,l3;
        split2(y0,h0,l0); split2(y1,h1,l1); split2(y2,h2,l2); split2(y3,h3,l3);
        *(uint64_t*)&yh[o] = (uint64_t)__bfloat16_as_ushort(h0) | ((uint64_t)__bfloat16_as_ushort(h1)<<16)
                           | ((uint64_t)__bfloat16_as_ushort(h2)<<32) | ((uint64_t)__bfloat16_as_ushort(h3)<<48);
        *(uint64_t*)&yl[o] = (uint64_t)__bfloat16_as_ushort(l0) | ((uint64_t)__bfloat16_as_ushort(l1)<<16)
                           | ((uint64_t)__bfloat16_as_ushort(l2)<<32) | ((uint64_t)__bfloat16_as_ushort(l3)<<48);
    }
}

// ---------------------------------------------------------------------------
// Shared GEMM geometry
// ---------------------------------------------------------------------------
#define ROWB 80
#define MATB (128 * ROWB)
#define STAGEB (4 * MATB)               // bf16 3-product: 4 tiles/stage
#define SMEM_GEMM (2 * STAGEB)
#define H_STAGEB (3 * MATB)             // fp16 2-product: 3 tiles/stage
#define SMEM_F16 (2 * H_STAGEB)

// ---------------------------------------------------------------------------
// Split-bf16 HMMA GEMM (NT), 3-product (hh + hl + lh)
// EPI 0: C = AB           -> fp32
// EPI 1: C = Cin + AB + b -> fp32 (residual)
// ---------------------------------------------------------------------------
template <int EPI>
__global__ __launch_bounds__(256, 2)
void gemm_hmma(const bf16* __restrict__ Ah, const bf16* __restrict__ Al,
               const bf16* __restrict__ Bh, const bf16* __restrict__ Bl,
               const float* __restrict__ bias, const float* __restrict__ Cin,
               float* __restrict__ Cout, int M, int N, int K) {
    extern __shared__ char smem[];
    uint32_t sb = smem_u32(smem);

    int t = threadIdx.x;
    int wid = t >> 5, lane = t & 31;
    int wm = wid >> 1, wn = wid & 1;
    int group = lane >> 2, tig = lane & 3;
    int m0 = blockIdx.y * 128, n0 = blockIdx.x * 128;

    float acc[2][8][4];
    #pragma unroll
    for (int i = 0; i < 2; i++)
        #pragma unroll
        for (int j = 0; j < 8; j++)
            #pragma unroll
            for (int kk = 0; kk < 4; kk++) acc[i][j][kk] = 0.f;

    const bf16* srcs[4] = { Ah, Al, Bh, Bl };

    auto load_stage = [&](int stage, int kt) {
        uint32_t base = sb + stage * STAGEB;
        int kofs = kt << 5;
        #pragma unroll
        for (int j = 0; j < 8; j++) {
            int lin = t + j * 256;
            int mtx = lin >> 9;
            int c   = lin & 511;
            int row = c >> 2, q = c & 3;
            int rbase = (mtx < 2) ? m0 : n0;
            const bf16* src = srcs[mtx] + (size_t)(rbase + row) * K + kofs + q * 8;
            cp_async16(base + mtx * MATB + row * ROWB + q * 16, src);
        }
        cp_commit();
    };

    uint32_t aRow = (uint32_t)(wm * 32 + (lane & 15)) * ROWB;
    uint32_t aCol = (uint32_t)((lane >> 4) << 3) * 2;
    uint32_t bRowBase = (uint32_t)(wn * 64 + (lane & 7) + ((lane >> 4) << 3)) * ROWB;
    uint32_t bCol = (uint32_t)(((lane >> 3) & 1) << 3) * 2;

    const int nk = K >> 5;

    load_stage(0, 0);

    for (int i = 0; i < nk; i++) {
        if (i + 1 < nk) { load_stage((i + 1) & 1, i + 1); cp_wait<1>(); }
        else            { cp_wait<0>(); }
        __syncthreads();

        uint32_t stb = sb + (i & 1) * STAGEB;
        uint32_t pAh = stb + aRow + aCol;
        uint32_t pAl = stb + MATB + aRow + aCol;
        uint32_t pBh = stb + 2 * MATB + bRowBase + bCol;
        uint32_t pBl = stb + 3 * MATB + bRowBase + bCol;

        #pragma unroll
        for (int ks = 0; ks < 2; ks++) {
            uint32_t ko = ks * 32;
            unsigned afh[2][4], afl[2][4], bfh[8][2], bfl[8][2];
            #pragma unroll
            for (int mt = 0; mt < 2; mt++) {
                ldsm_x4(afh[mt][0], afh[mt][1], afh[mt][2], afh[mt][3],
                        pAh + (uint32_t)(mt * 16) * ROWB + ko);
                ldsm_x4(afl[mt][0], afl[mt][1], afl[mt][2], afl[mt][3],
                        pAl + (uint32_t)(mt * 16) * ROWB + ko);
            }
            #pragma unroll
            for (int jp = 0; jp < 4; jp++) {
                ldsm_x4(bfh[2*jp][0], bfh[2*jp][1], bfh[2*jp+1][0], bfh[2*jp+1][1],
                        pBh + (uint32_t)(jp * 16) * ROWB + ko);
                ldsm_x4(bfl[2*jp][0], bfl[2*jp][1], bfl[2*jp+1][0], bfl[2*jp+1][1],
                        pBl + (uint32_t)(jp * 16) * ROWB + ko);
            }
            #pragma unroll
            for (int mt = 0; mt < 2; mt++)
                #pragma unroll
                for (int nt = 0; nt < 8; nt++) {
                    mma16816(acc[mt][nt], afh[mt], bfh[nt]);
                    mma16816(acc[mt][nt], afh[mt], bfl[nt]);
                    mma16816(acc[mt][nt], afl[mt], bfh[nt]);
                }
        }
        __syncthreads();
    }

    #pragma unroll
    for (int mt = 0; mt < 2; mt++) {
        #pragma unroll
        for (int nt = 0; nt < 8; nt++) {
            int col = n0 + wn * 64 + nt * 8 + tig * 2;
            float b0 = 0.f, b1v = 0.f;
            if (bias) { b0 = bias[col]; b1v = bias[col + 1]; }
            #pragma unroll
            for (int half = 0; half < 2; half++) {
                int row = m0 + wm * 32 + mt * 16 + group + half * 8;
                float v0 = acc[mt][nt][half * 2 + 0] + b0;
                float v1 = acc[mt][nt][half * 2 + 1] + b1v;
                size_t o = (size_t)row * N + col;
                if (EPI == 0) {
                    Cout[o] = v0; Cout[o + 1] = v1;
                } else {
                    Cout[o] = Cin[o] + v0; Cout[o + 1] = Cin[o + 1] + v1;
                }
            }
        }
    }
}

// ---------------------------------------------------------------------------
// fp16 2-product GEMM (NT): C = (Ah+Al)[M,K] @ Bh[N,K]^T  (= A @ Bh exactly)
// EPI 0: C = AB                    -> fp32 (head)
// EPI 1: C = Cin + AB + bias       -> fp32 (FF2 residual)
// EPI 2: gelu(AB + bias)           -> fp16 split (Oh, Ol)  (FF1)
// ---------------------------------------------------------------------------
template <int EPI>
__global__ __launch_bounds__(256, 2)
void gemm_f16(const __half* __restrict__ Ah, const __half* __restrict__ Al,
              const __half* __restrict__ Bh,
              const float* __restrict__ bias, const float* __restrict__ Cin,
              float* __restrict__ Cout, __half* __restrict__ Oh, __half* __restrict__ Ol,
              int M, int N, int K) {
    extern __shared__ char smem[];
    uint32_t sb = smem_u32(smem);

    int t = threadIdx.x;
    int wid = t >> 5, lane = t & 31;
    int wm = wid >> 1, wn = wid & 1;
    int group = lane >> 2, tig = lane & 3;
    int m0 = blockIdx.y * 128, n0 = blockIdx.x * 128;

    float acc[2][8][4];
    #pragma unroll
    for (int i = 0; i < 2; i++)
        #pragma unroll
        for (int j = 0; j < 8; j++)
            #pragma unroll
            for (int kk = 0; kk < 4; kk++) acc[i][j][kk] = 0.f;

    const __half* srcs[3] = { Ah, Al, Bh };

    auto load_stage = [&](int stage, int kt) {
        uint32_t base = sb + stage * H_STAGEB;
        int kofs = kt << 5;
        #pragma unroll
        for (int j = 0; j < 6; j++) {
            int lin = t + j * 256;
            int mtx = lin >> 9;
            int c   = lin & 511;
            int row = c >> 2, q = c & 3;
            int rbase = (mtx < 2) ? m0 : n0;
            const __half* src = srcs[mtx] + (size_t)(rbase + row) * K + kofs + q * 8;
            cp_async16(base + mtx * MATB + row * ROWB + q * 16, src);
        }
        cp_commit();
    };

    uint32_t aRow = (uint32_t)(wm * 32 + (lane & 15)) * ROWB;
    uint32_t aCol = (uint32_t)((lane >> 4) << 3) * 2;
    uint32_t bRowBase = (uint32_t)(wn * 64 + (lane & 7) + ((lane >> 4) << 3)) * ROWB;
    uint32_t bCol = (uint32_t)(((lane >> 3) & 1) << 3) * 2;

    const int nk = K >> 5;

    load_stage(0, 0);

    for (int i = 0; i < nk; i++) {
        if (i + 1 < nk) { load_stage((i + 1) & 1, i + 1); cp_wait<1>(); }
        else            { cp_wait<0>(); }
        __syncthreads();

        uint32_t stb = sb + (i & 1) * H_STAGEB;
        uint32_t pAh = stb + aRow + aCol;
        uint32_t pAl = stb + MATB + aRow + aCol;
        uint32_t pBh = stb + 2 * MATB + bRowBase + bCol;

        #pragma unroll
        for (int ks = 0; ks < 2; ks++) {
            uint32_t ko = ks * 32;
            unsigned afh[2][4], afl[2][4], bfh[8][2];
            #pragma unroll
            for (int mt = 0; mt < 2; mt++) {
                ldsm_x4(afh[mt][0], afh[mt][1], afh[mt][2], afh[mt][3],
                        pAh + (uint32_t)(mt * 16) * ROWB + ko);
                ldsm_x4(afl[mt][0], afl[mt][1], afl[mt][2], afl[mt][3],
                        pAl + (uint32_t)(mt * 16) * ROWB + ko);
            }
            #pragma unroll
            for (int jp = 0; jp < 4; jp++) {
                ldsm_x4(bfh[2*jp][0], bfh[2*jp][1], bfh[2*jp+1][0], bfh[2*jp+1][1],
                        pBh + (uint32_t)(jp * 16) * ROWB + ko);
            }
            #pragma unroll
            for (int mt = 0; mt < 2; mt++)
                #pragma unroll
                for (int nt = 0; nt < 8; nt++) {
                    mma16816h(acc[mt][nt], afh[mt], bfh[nt]);
                    mma16816h(acc[mt][nt], afl[mt], bfh[nt]);
                }
        }
        __syncthreads();
    }

    #pragma unroll
    for (int mt = 0; mt < 2; mt++) {
        #pragma unroll
        for (int nt = 0; nt < 8; nt++) {
            int col = n0 + wn * 64 + nt * 8 + tig * 2;
            float b0 = 0.f, b1v = 0.f;
            if (EPI != 0 && bias) { b0 = bias[col]; b1v = bias[col + 1]; }
            #pragma unroll
            for (int half = 0; half < 2; half++) {
                int row = m0 + wm * 32 + mt * 16 + group + half * 8;
                float v0 = acc[mt][nt][half * 2 + 0] + b0;
                float v1 = acc[mt][nt][half * 2 + 1] + b1v;
                size_t o = (size_t)row * N + col;
                if (EPI == 0) {
                    Cout[o] = v0; Cout[o + 1] = v1;
                } else if (EPI == 1) {
                    Cout[o] = Cin[o] + v0; Cout[o + 1] = Cin[o + 1] + v1;
                } else {
                    float g0 = 0.5f * v0 * (1.0f + erff(v0 * 0.70710678118654752f));
                    float g1 = 0.5f * v1 * (1.0f + erff(v1 * 0.70710678118654752f));
                    __half h0, l0, h1, l1;
                    split2h(g0, h0, l0); split2h(g1, h1, l1);
                    *(uint32_t*)&Oh[o] = (uint32_t)__half_as_ushort(h0) | ((uint32_t)__half_as_ushort(h1) << 16);
                    *(uint32_t*)&Ol[o] = (uint32_t)__half_as_ushort(l0) | ((uint32_t)__half_as_ushort(l1) << 16);
                }
            }
        }
    }
}

// ---------------------------------------------------------------------------
// Causal attention from fused QKV buffer (row stride 3*DD).
// One block = (b, h, 8 queries). Exact softmax. Split-bf16 output.
// ---------------------------------------------------------------------------
__global__ __launch_bounds__(128)
void attn_kernel(const float* __restrict__ QKV,
                 bf16* __restrict__ Oh, bf16* __restrict__ Ol) {
    const int NQB = SS / QT;
    int qt0 = (blockIdx.x % NQB) * QT;
    int bh  = blockIdx.x / NQB;
    int h   = bh % HH, b = bh / HH;
    int t   = threadIdx.x;

    __shared__ float qs[QT][DKK];
    __shared__ float Ks[64][DKK + 1];
    __shared__ float sc[QT][SS + 16];
    __shared__ float red[128];
    __shared__ float mx[QT], dn[QT];

    const float* Qp = QKV + h * DKK;
    const float* Kp = QKV + DD + h * DKK;
    const float* Vp = QKV + 2 * DD + h * DKK;

    for (int i = t; i < QT * DKK; i += 128) {
        int qi = i >> 6, d = i & 63;
        qs[qi][d] = Qp[(size_t)(b * SS + qt0 + qi) * RS + d];
    }
    __syncthreads();

    const int nkmax = qt0 + QT;
    const float scale = 0.125f;

    for (int kt = 0; kt < nkmax; kt += 64) {
        int rows = min(64, nkmax - kt);
        for (int i = t; i < rows * DKK; i += 128) {
            int r = i >> 6, d = i & 63;
            Ks[r][d] = Kp[(size_t)(b * SS + kt + r) * RS + d];
        }
        __syncthreads();
        int j = t & 63, qh = t >> 6;
        if (j < rows) {
            int kglob = kt + j;
            for (int qi = qh; qi < QT; qi += 2) {
                float dot = 0.f;
                #pragma unroll
                for (int d = 0; d < DKK; d++) dot += qs[qi][d] * Ks[j][d];
                sc[qi][kglob] = (kglob <= qt0 + qi) ? dot * scale : -1e30f;
            }
        }
        __syncthreads();
    }

    int tq = t >> 4, r = t & 15;
    float m = -1e30f;
    for (int k = r; k < nkmax; k += 16) m = fmaxf(m, sc[tq][k]);
    red[t] = m;
    __syncthreads();
    for (int st = 8; st > 0; st >>= 1) {
        if (r < st) red[t] = fmaxf(red[t], red[t + st]);
        __syncthreads();
    }
    if (r == 0) mx[tq] = red[t];
    __syncthreads();
    float mval = mx[tq];
    float s = 0.f;
    for (int k = r; k < nkmax; k += 16) {
        float e = expf(sc[tq][k] - mval);
        sc[tq][k] = e;
        s += e;
    }
    red[t] = s;
    __syncthreads();
    for (int st = 8; st > 0; st >>= 1) {
        if (r < st) red[t] += red[t + st];
        __syncthreads();
    }
    if (r == 0) dn[tq] = red[t];
    __syncthreads();

    int d = t & 63, part = t >> 6;
    float acc[QT];
    #pragma unroll
    for (int qi = 0; qi < QT; qi++) acc[qi] = 0.f;
    for (int k = part; k < nkmax; k += 2) {
        float v = Vp[(size_t)(b * SS + k) * RS + d];
        #pragma unroll
        for (int qi = 0; qi < QT; qi++) acc[qi] += sc[qi][k] * v;
    }
    for (int qi = 0; qi < QT; qi++) {
        red[t] = acc[qi];
        __syncthreads();
        if (part == 0) {
            float o = (red[t] + red[t + 64]) / dn[qi];
            bf16 hh, ll; split2(o, hh, ll);
            size_t off = (size_t)(b * SS + qt0 + qi) * DD + h * DKK + d;
            Oh[off] = hh; Ol[off] = ll;
        }
        __syncthreads();
    }
}

// ---------------------------------------------------------------------------
// Launch
// ---------------------------------------------------------------------------
extern "C" void kernel_launch(void* const* d_in, const int* in_sizes, int n_in,
                              void* d_out, int out_size) {
    (void)in_sizes; (void)n_in; (void)out_size;

    const int*   ids  = (const int*)  d_in[0];
    const float* emb  = (const float*)d_in[1];
    const float* pe   = (const float*)d_in[2];
    const float* Wq   = (const float*)d_in[3];
    const float* Wk   = (const float*)d_in[4];
    const float* Wv   = (const float*)d_in[5];
    const float* Wo   = (const float*)d_in[6];
    const float* bo   = (const float*)d_in[7];
    const float* ln1s = (const float*)d_in[8];
    const float* ln1b = (const float*)d_in[9];
    const float* ln2s = (const float*)d_in[10];
    const float* ln2b = (const float*)d_in[11];
    const float* W1   = (const float*)d_in[12];
    const float* b1   = (const float*)d_in[13];
    const float* W2   = (const float*)d_in[14];
    const float* b2   = (const float*)d_in[15];
    const float* lnfs = (const float*)d_in[16];
    const float* lnfb = (const float*)d_in[17];
    float* out = (float*)d_out;

    float *x, *qkv;
    bf16 *hh, *hl, *ah, *al, *wth, *wtl;
    __half *ffh, *ffl, *hf, *lf, *ef, *wf;
    cudaGetSymbolAddress((void**)&x,   g_x);
    cudaGetSymbolAddress((void**)&qkv, g_qkv);
    cudaGetSymbolAddress((void**)&hh,  g_hh);
    cudaGetSymbolAddress((void**)&hl,  g_hl);
    cudaGetSymbolAddress((void**)&ah,  g_ah);
    cudaGetSymbolAddress((void**)&al,  g_al);
    cudaGetSymbolAddress((void**)&ffh, g_ffh);
    cudaGetSymbolAddress((void**)&ffl, g_ffl);
    cudaGetSymbolAddress((void**)&hf,  g_hf);
    cudaGetSymbolAddress((void**)&lf,  g_lf);
    cudaGetSymbolAddress((void**)&ef,  g_ef);
    cudaGetSymbolAddress((void**)&wth, g_wth);
    cudaGetSymbolAddress((void**)&wtl, g_wtl);
    cudaGetSymbolAddress((void**)&wf,  g_wf);

    cudaFuncSetAttribute(gemm_hmma<0>, cudaFuncAttributeMaxDynamicSharedMemorySize, SMEM_GEMM);
    cudaFuncSetAttribute(gemm_hmma<1>, cudaFuncAttributeMaxDynamicSharedMemorySize, SMEM_GEMM);
    cudaFuncSetAttribute(gemm_f16<0>, cudaFuncAttributeMaxDynamicSharedMemorySize, SMEM_F16);
    cudaFuncSetAttribute(gemm_f16<1>, cudaFuncAttributeMaxDynamicSharedMemorySize, SMEM_F16);
    cudaFuncSetAttribute(gemm_f16<2>, cudaFuncAttributeMaxDynamicSharedMemorySize, SMEM_F16);

    dim3 tb32(32, 8);
    {
        dim3 gQ(DD / 32, DD / 32, LL * 4);
        wsplit_qkvo_kernel<<<gQ, tb32>>>(Wq, Wk, Wv, Wo, wth, wtl);
        dim3 g1(FFD / 32, DD / 32, LL);
        whalf_ff_kernel<<<g1, tb32>>>(W1, wf, DD, FFD, 0);
        dim3 g2(DD / 32, FFD / 32, LL);
        whalf_ff_kernel<<<g2, tb32>>>(W2, wf, FFD, DD, (size_t)DD * FFD);
    }
    {
        int n4 = (VV * DD) / 4;
        ehalf_kernel<<<(n4 + 255) / 256, 256>>>(emb, ef, n4);
    }

    embed_kernel<<<NTOK, 256>>>(ids, emb, pe, x);

    dim3 gQKV(3 * DD / 128, NTOK / 128);  // 24 x 16
    dim3 gD(DD / 128, NTOK / 128);        // 8 x 16
    dim3 gF(FFD / 128, NTOK / 128);       // 32 x 16
    dim3 gV(VV / 128, NTOK / 128);        // 250 x 16

    for (int l = 0; l < LL; l++) {
        bf16* wqkvh = wth + (size_t)l * WLAYER_B;   bf16* wqkvl = wtl + (size_t)l * WLAYER_B;
        bf16* woh = wqkvh + 3 * DD * DD;            bf16* wol = wqkvl + 3 * DD * DD;
        __half* w1f = wf + (size_t)l * WLAYER_F;
        __half* w2f = w1f + (size_t)DD * FFD;

        ln_split_kernel<0><<<NTOK, 256>>>(x, ln1s + l * DD, ln1b + l * DD, hh, hl, nullptr, nullptr);
        gemm_hmma<0><<<gQKV, 256, SMEM_GEMM>>>(hh, hl, wqkvh, wqkvl, nullptr, nullptr, qkv, NTOK, 3 * DD, DD);
        attn_kernel<<<BB * HH * (SS / QT), 128>>>(qkv, ah, al);
        gemm_hmma<1><<<gD, 256, SMEM_GEMM>>>(ah, al, woh, wol, bo + l * DD, x, x, NTOK, DD, DD);

        ln_split_kernel<1><<<NTOK, 256>>>(x, ln2s + l * DD, ln2b + l * DD, nullptr, nullptr, hf, lf);
        gemm_f16<2><<<gF, 256, SMEM_F16>>>(hf, lf, w1f, b1 + l * FFD, nullptr, nullptr, ffh, ffl, NTOK, FFD, DD);
        gemm_f16<1><<<gD, 256, SMEM_F16>>>(ffh, ffl, w2f, b2 + l * DD, x, x, nullptr, nullptr, NTOK, DD, FFD);
    }

    ln_split_kernel<1><<<NTOK, 256>>>(x, lnfs, lnfb, nullptr, nullptr, hf, lf);
    gemm_f16<0><<<gV, 256, SMEM_F16>>>(hf, lf, ef, nullptr, nullptr, out, nullptr, nullptr, NTOK, VV, DD);
}

// round 8
// speedup vs baseline: 6.7443x; 1.0718x over previous
#include <cuda_runtime.h>
#include <cuda_fp16.h>
#include <math.h>
#include <stdint.h>

// Problem dims
#define BB   4
#define SS   512
#define DD   1024
#define HH   16
#define LL   6
#define FFD  4096
#define VV   32000
#define DKK  64
#define NTOK (BB*SS)   // 2048
#define QT   8         // queries per attention block
#define RS   (3*DD)    // fused qkv row stride

// ---------------------------------------------------------------------------
// Scratch (device globals — no runtime allocation allowed)
// ---------------------------------------------------------------------------
__device__ float g_x[NTOK*DD];
__device__ float g_qkv[NTOK*3*DD];
__device__ __half g_hf[NTOK*DD];       // LN out, fp16 hi
__device__ __half g_lf[NTOK*DD];       // LN out, fp16 lo
__device__ __half g_ah[NTOK*DD];       // attention out, fp16 hi
__device__ __half g_al[NTOK*DD];       // attention out, fp16 lo
__device__ __half g_ffh[NTOK*FFD];     // GELU out, fp16 hi
__device__ __half g_ffl[NTOK*FFD];     // GELU out, fp16 lo
__device__ __half g_ef[(size_t)VV*DD]; // emb as fp16 (head B)

#define WLAYER (4*DD*DD + 2*DD*FFD)    // fp16 weights per layer (qkv,o,ff1,ff2)
__device__ __half g_wf[(size_t)LL*WLAYER];

__device__ __forceinline__ void split2h(float v, __half& h, __half& l) {
    h = __float2half(v);
    l = __float2half(v - __half2float(h));
}

__device__ __forceinline__ uint32_t smem_u32(const void* p) {
    uint32_t a;
    asm("{ .reg .u64 tmp; cvta.to.shared.u64 tmp, %1; cvt.u32.u64 %0, tmp; }"
        : "=r"(a) : "l"(p));
    return a;
}

// cp.async helpers
__device__ __forceinline__ void cp_async16(uint32_t dst, const void* src) {
    asm volatile("cp.async.cg.shared.global [%0], [%1], 16;" :: "r"(dst), "l"(src) : "memory");
}
__device__ __forceinline__ void cp_commit() {
    asm volatile("cp.async.commit_group;" ::: "memory");
}
template <int N>
__device__ __forceinline__ void cp_wait() {
    asm volatile("cp.async.wait_group %0;" :: "n"(N) : "memory");
}

__device__ __forceinline__ void ldsm_x4(unsigned& r0, unsigned& r1, unsigned& r2,
                                        unsigned& r3, uint32_t a) {
    asm volatile("ldmatrix.sync.aligned.m8n8.x4.shared.b16 {%0,%1,%2,%3}, [%4];"
                 : "=r"(r0), "=r"(r1), "=r"(r2), "=r"(r3) : "r"(a));
}

__device__ __forceinline__ void mma16816h(float* c, const unsigned* a, const unsigned* b) {
    asm volatile(
        "mma.sync.aligned.m16n8k16.row.col.f32.f16.f16.f32 "
        "{%0,%1,%2,%3}, {%4,%5,%6,%7}, {%8,%9}, {%0,%1,%2,%3};\n"
        : "+f"(c[0]), "+f"(c[1]), "+f"(c[2]), "+f"(c[3])
        : "r"(a[0]), "r"(a[1]), "r"(a[2]), "r"(a[3]), "r"(b[0]), "r"(b[1]));
}

// ---------------------------------------------------------------------------
// Embedding + batch-indexed positional encoding (faithful to reference)
// ---------------------------------------------------------------------------
__global__ void embed_kernel(const int* __restrict__ ids,
                             const float* __restrict__ emb,
                             const float* __restrict__ pe,
                             float* __restrict__ x) {
    int row = blockIdx.x;
    int b   = row / SS;
    int id  = ids[row];
    const float4* er = (const float4*)(emb + (size_t)id * DD);
    const float4* pr = (const float4*)(pe  + (size_t)b  * DD);
    float4* xr = (float4*)(x + (size_t)row * DD);
    int i = threadIdx.x;
    float4 e = er[i], p = pr[i];
    xr[i] = make_float4(e.x + p.x, e.y + p.y, e.z + p.z, e.w + p.w);
}

// ---------------------------------------------------------------------------
// Weight conversion: transpose + fp16, merged over layers
// ---------------------------------------------------------------------------
__device__ __forceinline__ void whalf_body(const float* __restrict__ W,
                                           __half* __restrict__ T, int K, int N) {
    __shared__ float tile[32][33];
    int n0 = blockIdx.x * 32, k0 = blockIdx.y * 32;
    int tx = threadIdx.x, ty = threadIdx.y;   // 32 x 8
    #pragma unroll
    for (int i = 0; i < 4; i++)
        tile[ty + i*8][tx] = W[(size_t)(k0 + ty + i*8) * N + n0 + tx];
    __syncthreads();
    #pragma unroll
    for (int i = 0; i < 4; i++)
        T[(size_t)(n0 + ty + i*8) * K + k0 + tx] = __float2half(tile[tx][ty + i*8]);
}

__global__ void whalf_qkvo_kernel(const float* __restrict__ Wq, const float* __restrict__ Wk,
                                  const float* __restrict__ Wv, const float* __restrict__ Wo,
                                  __half* __restrict__ T) {
    int z = blockIdx.z, l = z >> 2, widx = z & 3;
    const float* W = (widx == 0 ? Wq : widx == 1 ? Wk : widx == 2 ? Wv : Wo)
                     + (size_t)l * DD * DD;
    whalf_body(W, T + (size_t)l * WLAYER + (size_t)widx * DD * DD, DD, DD);
}

__global__ void whalf_ff_kernel(const float* __restrict__ W, __half* __restrict__ T,
                                int K, int N, size_t obase) {
    int l = blockIdx.z;
    whalf_body(W + (size_t)l * K * N, T + (size_t)l * WLAYER + obase, K, N);
}

// emb -> fp16 (vectorized)
__global__ void ehalf_kernel(const float* __restrict__ X, __half* __restrict__ Y, int n4) {
    int i = blockIdx.x * 256 + threadIdx.x;
    if (i < n4) {
        float4 v = ((const float4*)X)[i];
        ((__half2*)Y)[i * 2]     = __floats2half2_rn(v.x, v.y);
        ((__half2*)Y)[i * 2 + 1] = __floats2half2_rn(v.z, v.w);
    }
}

// ---------------------------------------------------------------------------
// LayerNorm, vectorized (1 float4/thread), fp16 hi/lo split output
// ---------------------------------------------------------------------------
__global__ void ln_split_kernel(const float* __restrict__ x,
                                const float* __restrict__ s,
                                const float* __restrict__ b,
                                __half* __restrict__ fh, __half* __restrict__ fl) {
    int row = blockIdx.x;
    int t = threadIdx.x;
    float4 v = ((const float4*)(x + (size_t)row * DD))[t];
    float s1 = v.x + v.y + v.z + v.w;
    float s2 = v.x*v.x + v.y*v.y + v.z*v.z + v.w*v.w;
    __shared__ float r1[256], r2[256];
    r1[t] = s1; r2[t] = s2;
    __syncthreads();
    for (int st = 128; st > 0; st >>= 1) {
        if (t < st) { r1[t] += r1[t + st]; r2[t] += r2[t + st]; }
        __syncthreads();
    }
    __shared__ float sm_mean, sm_rstd;
    if (t == 0) {
        float mean = r1[0] * (1.0f / DD);
        float var  = r2[0] * (1.0f / DD) - mean * mean;
        sm_mean = mean;
        sm_rstd = rsqrtf(var + 1e-5f);
    }
    __syncthreads();
    float mean = sm_mean, rstd = sm_rstd;
    float4 sv = ((const float4*)s)[t];
    float4 bv = ((const float4*)b)[t];
    float y0 = (v.x - mean) * rstd * sv.x + bv.x;
    float y1 = (v.y - mean) * rstd * sv.y + bv.y;
    float y2 = (v.z - mean) * rstd * sv.z + bv.z;
    float y3 = (v.w - mean) * rstd * sv.w + bv.w;
    size_t o = (size_t)row * DD + t * 4;
    __half h0,l0,h1,l1,h2,l2,h3,l3;
    split2h(y0,h0,l0); split2h(y1,h1,l1); split2h(y2,h2,l2); split2h(y3,h3,l3);
    *(uint64_t*)&fh[o] = (uint64_t)__half_as_ushort(h0) | ((uint64_t)__half_as_ushort(h1)<<16)
                       | ((uint64_t)__half_as_ushort(h2)<<32) | ((uint64_t)__half_as_ushort(h3)<<48);
    *(uint64_t*)&fl[o] = (uint64_t)__half_as_ushort(l0) | ((uint64_t)__half_as_ushort(l1)<<16)
                       | ((uint64_t)__half_as_ushort(l2)<<32) | ((uint64_t)__half_as_ushort(l3)<<48);
}

// ---------------------------------------------------------------------------
// fp16 2-product GEMM (NT): C = (Ah+Al)[M,K] @ Bh[N,K]^T  (= A @ Bh exactly)
// 128x128 CTA tile, BK=32, 256 threads, cp.async double-buffer + ldmatrix.
// EPI 0: C = AB (+bias if non-null)  -> fp32  (QKV, head)
// EPI 1: C = Cin + AB + bias         -> fp32  (Wo, FF2 residual)
// EPI 2: gelu(AB + bias)             -> fp16 split (Oh, Ol)  (FF1)
// ---------------------------------------------------------------------------
#define ROWB 80
#define MATB (128 * ROWB)
#define H_STAGEB (3 * MATB)             // 3 tiles/stage (Ah, Al, Bh)
#define SMEM_F16 (2 * H_STAGEB)         // 61440 bytes

template <int EPI>
__global__ __launch_bounds__(256, 2)
void gemm_f16(const __half* __restrict__ Ah, const __half* __restrict__ Al,
              const __half* __restrict__ Bh,
              const float* __restrict__ bias, const float* __restrict__ Cin,
              float* __restrict__ Cout, __half* __restrict__ Oh, __half* __restrict__ Ol,
              int M, int N, int K) {
    extern __shared__ char smem[];
    uint32_t sb = smem_u32(smem);

    int t = threadIdx.x;
    int wid = t >> 5, lane = t & 31;
    int wm = wid >> 1, wn = wid & 1;
    int group = lane >> 2, tig = lane & 3;
    int m0 = blockIdx.y * 128, n0 = blockIdx.x * 128;

    float acc[2][8][4];
    #pragma unroll
    for (int i = 0; i < 2; i++)
        #pragma unroll
        for (int j = 0; j < 8; j++)
            #pragma unroll
            for (int kk = 0; kk < 4; kk++) acc[i][j][kk] = 0.f;

    const __half* srcs[3] = { Ah, Al, Bh };

    auto load_stage = [&](int stage, int kt) {
        uint32_t base = sb + stage * H_STAGEB;
        int kofs = kt << 5;
        #pragma unroll
        for (int j = 0; j < 6; j++) {
            int lin = t + j * 256;
            int mtx = lin >> 9;
            int c   = lin & 511;
            int row = c >> 2, q = c & 3;
            int rbase = (mtx < 2) ? m0 : n0;
            const __half* src = srcs[mtx] + (size_t)(rbase + row) * K + kofs + q * 8;
            cp_async16(base + mtx * MATB + row * ROWB + q * 16, src);
        }
        cp_commit();
    };

    uint32_t aRow = (uint32_t)(wm * 32 + (lane & 15)) * ROWB;
    uint32_t aCol = (uint32_t)((lane >> 4) << 3) * 2;
    uint32_t bRowBase = (uint32_t)(wn * 64 + (lane & 7) + ((lane >> 4) << 3)) * ROWB;
    uint32_t bCol = (uint32_t)(((lane >> 3) & 1) << 3) * 2;

    const int nk = K >> 5;

    load_stage(0, 0);

    for (int i = 0; i < nk; i++) {
        if (i + 1 < nk) { load_stage((i + 1) & 1, i + 1); cp_wait<1>(); }
        else            { cp_wait<0>(); }
        __syncthreads();

        uint32_t stb = sb + (i & 1) * H_STAGEB;
        uint32_t pAh = stb + aRow + aCol;
        uint32_t pAl = stb + MATB + aRow + aCol;
        uint32_t pBh = stb + 2 * MATB + bRowBase + bCol;

        #pragma unroll
        for (int ks = 0; ks < 2; ks++) {
            uint32_t ko = ks * 32;
            unsigned afh[2][4], afl[2][4], bfh[8][2];
            #pragma unroll
            for (int mt = 0; mt < 2; mt++) {
                ldsm_x4(afh[mt][0], afh[mt][1], afh[mt][2], afh[mt][3],
                        pAh + (uint32_t)(mt * 16) * ROWB + ko);
                ldsm_x4(afl[mt][0], afl[mt][1], afl[mt][2], afl[mt][3],
                        pAl + (uint32_t)(mt * 16) * ROWB + ko);
            }
            #pragma unroll
            for (int jp = 0; jp < 4; jp++) {
                ldsm_x4(bfh[2*jp][0], bfh[2*jp][1], bfh[2*jp+1][0], bfh[2*jp+1][1],
                        pBh + (uint32_t)(jp * 16) * ROWB + ko);
            }
            #pragma unroll
            for (int mt = 0; mt < 2; mt++)
                #pragma unroll
                for (int nt = 0; nt < 8; nt++) {
                    mma16816h(acc[mt][nt], afh[mt], bfh[nt]);
                    mma16816h(acc[mt][nt], afl[mt], bfh[nt]);
                }
        }
        __syncthreads();
    }

    #pragma unroll
    for (int mt = 0; mt < 2; mt++) {
        #pragma unroll
        for (int nt = 0; nt < 8; nt++) {
            int col = n0 + wn * 64 + nt * 8 + tig * 2;
            float b0 = 0.f, b1v = 0.f;
            if (bias) { b0 = bias[col]; b1v = bias[col + 1]; }
            #pragma unroll
            for (int half = 0; half < 2; half++) {
                int row = m0 + wm * 32 + mt * 16 + group + half * 8;
                float v0 = acc[mt][nt][half * 2 + 0] + b0;
                float v1 = acc[mt][nt][half * 2 + 1] + b1v;
                size_t o = (size_t)row * N + col;
                if (EPI == 0) {
                    Cout[o] = v0; Cout[o + 1] = v1;
                } else if (EPI == 1) {
                    Cout[o] = Cin[o] + v0; Cout[o + 1] = Cin[o + 1] + v1;
                } else {
                    float g0 = 0.5f * v0 * (1.0f + erff(v0 * 0.70710678118654752f));
                    float g1 = 0.5f * v1 * (1.0f + erff(v1 * 0.70710678118654752f));
                    __half h0, l0, h1, l1;
                    split2h(g0, h0, l0); split2h(g1, h1, l1);
                    *(uint32_t*)&Oh[o] = (uint32_t)__half_as_ushort(h0) | ((uint32_t)__half_as_ushort(h1) << 16);
                    *(uint32_t*)&Ol[o] = (uint32_t)__half_as_ushort(l0) | ((uint32_t)__half_as_ushort(l1) << 16);
                }
            }
        }
    }
}

// ---------------------------------------------------------------------------
// Causal attention from fused QKV buffer (row stride 3*DD).
// One block = (b, h, 8 queries). Exact softmax. fp16 hi/lo split output.
// ---------------------------------------------------------------------------
__global__ __launch_bounds__(128)
void attn_kernel(const float* __restrict__ QKV,
                 __half* __restrict__ Oh, __half* __restrict__ Ol) {
    const int NQB = SS / QT;
    int qt0 = (blockIdx.x % NQB) * QT;
    int bh  = blockIdx.x / NQB;
    int h   = bh % HH, b = bh / HH;
    int t   = threadIdx.x;

    __shared__ float qs[QT][DKK];
    __shared__ float Ks[64][DKK + 1];
    __shared__ float sc[QT][SS + 16];
    __shared__ float red[128];
    __shared__ float mx[QT], dn[QT];

    const float* Qp = QKV + h * DKK;
    const float* Kp = QKV + DD + h * DKK;
    const float* Vp = QKV + 2 * DD + h * DKK;

    for (int i = t; i < QT * DKK; i += 128) {
        int qi = i >> 6, d = i & 63;
        qs[qi][d] = Qp[(size_t)(b * SS + qt0 + qi) * RS + d];
    }
    __syncthreads();

    const int nkmax = qt0 + QT;
    const float scale = 0.125f;

    for (int kt = 0; kt < nkmax; kt += 64) {
        int rows = min(64, nkmax - kt);
        for (int i = t; i < rows * DKK; i += 128) {
            int r = i >> 6, d = i & 63;
            Ks[r][d] = Kp[(size_t)(b * SS + kt + r) * RS + d];
        }
        __syncthreads();
        int j = t & 63, qh = t >> 6;
        if (j < rows) {
            int kglob = kt + j;
            for (int qi = qh; qi < QT; qi += 2) {
                float dot = 0.f;
                #pragma unroll
                for (int d = 0; d < DKK; d++) dot += qs[qi][d] * Ks[j][d];
                sc[qi][kglob] = (kglob <= qt0 + qi) ? dot * scale : -1e30f;
            }
        }
        __syncthreads();
    }

    int tq = t >> 4, r = t & 15;
    float m = -1e30f;
    for (int k = r; k < nkmax; k += 16) m = fmaxf(m, sc[tq][k]);
    red[t] = m;
    __syncthreads();
    for (int st = 8; st > 0; st >>= 1) {
        if (r < st) red[t] = fmaxf(red[t], red[t + st]);
        __syncthreads();
    }
    if (r == 0) mx[tq] = red[t];
    __syncthreads();
    float mval = mx[tq];
    float s = 0.f;
    for (int k = r; k < nkmax; k += 16) {
        float e = expf(sc[tq][k] - mval);
        sc[tq][k] = e;
        s += e;
    }
    red[t] = s;
    __syncthreads();
    for (int st = 8; st > 0; st >>= 1) {
        if (r < st) red[t] += red[t + st];
        __syncthreads();
    }
    if (r == 0) dn[tq] = red[t];
    __syncthreads();

    int d = t & 63, part = t >> 6;
    float acc[QT];
    #pragma unroll
    for (int qi = 0; qi < QT; qi++) acc[qi] = 0.f;
    for (int k = part; k < nkmax; k += 2) {
        float v = Vp[(size_t)(b * SS + k) * RS + d];
        #pragma unroll
        for (int qi = 0; qi < QT; qi++) acc[qi] += sc[qi][k] * v;
    }
    for (int qi = 0; qi < QT; qi++) {
        red[t] = acc[qi];
        __syncthreads();
        if (part == 0) {
            float o = (red[t] + red[t + 64]) / dn[qi];
            __half hh, ll; split2h(o, hh, ll);
            size_t off = (size_t)(b * SS + qt0 + qi) * DD + h * DKK + d;
            Oh[off] = hh; Ol[off] = ll;
        }
        __syncthreads();
    }
}

// ---------------------------------------------------------------------------
// Launch
// ---------------------------------------------------------------------------
extern "C" void kernel_launch(void* const* d_in, const int* in_sizes, int n_in,
                              void* d_out, int out_size) {
    (void)in_sizes; (void)n_in; (void)out_size;

    const int*   ids  = (const int*)  d_in[0];
    const float* emb  = (const float*)d_in[1];
    const float* pe   = (const float*)d_in[2];
    const float* Wq   = (const float*)d_in[3];
    const float* Wk   = (const float*)d_in[4];
    const float* Wv   = (const float*)d_in[5];
    const float* Wo   = (const float*)d_in[6];
    const float* bo   = (const float*)d_in[7];
    const float* ln1s = (const float*)d_in[8];
    const float* ln1b = (const float*)d_in[9];
    const float* ln2s = (const float*)d_in[10];
    const float* ln2b = (const float*)d_in[11];
    const float* W1   = (const float*)d_in[12];
    const float* b1   = (const float*)d_in[13];
    const float* W2   = (const float*)d_in[14];
    const float* b2   = (const float*)d_in[15];
    const float* lnfs = (const float*)d_in[16];
    const float* lnfb = (const float*)d_in[17];
    float* out = (float*)d_out;

    float *x, *qkv;
    __half *hf, *lf, *ah, *al, *ffh, *ffl, *ef, *wf;
    cudaGetSymbolAddress((void**)&x,   g_x);
    cudaGetSymbolAddress((void**)&qkv, g_qkv);
    cudaGetSymbolAddress((void**)&hf,  g_hf);
    cudaGetSymbolAddress((void**)&lf,  g_lf);
    cudaGetSymbolAddress((void**)&ah,  g_ah);
    cudaGetSymbolAddress((void**)&al,  g_al);
    cudaGetSymbolAddress((void**)&ffh, g_ffh);
    cudaGetSymbolAddress((void**)&ffl, g_ffl);
    cudaGetSymbolAddress((void**)&ef,  g_ef);
    cudaGetSymbolAddress((void**)&wf,  g_wf);

    cudaFuncSetAttribute(gemm_f16<0>, cudaFuncAttributeMaxDynamicSharedMemorySize, SMEM_F16);
    cudaFuncSetAttribute(gemm_f16<1>, cudaFuncAttributeMaxDynamicSharedMemorySize, SMEM_F16);
    cudaFuncSetAttribute(gemm_f16<2>, cudaFuncAttributeMaxDynamicSharedMemorySize, SMEM_F16);

    dim3 tb32(32, 8);
    {
        dim3 gQ(DD / 32, DD / 32, LL * 4);
        whalf_qkvo_kernel<<<gQ, tb32>>>(Wq, Wk, Wv, Wo, wf);
        dim3 g1(FFD / 32, DD / 32, LL);
        whalf_ff_kernel<<<g1, tb32>>>(W1, wf, DD, FFD, (size_t)4 * DD * DD);
        dim3 g2(DD / 32, FFD / 32, LL);
        whalf_ff_kernel<<<g2, tb32>>>(W2, wf, FFD, DD, (size_t)4 * DD * DD + (size_t)DD * FFD);
    }
    {
        int n4 = (VV * DD) / 4;
        ehalf_kernel<<<(n4 + 255) / 256, 256>>>(emb, ef, n4);
    }

    embed_kernel<<<NTOK, 256>>>(ids, emb, pe, x);

    dim3 gQKV(3 * DD / 128, NTOK / 128);  // 24 x 16
    dim3 gD(DD / 128, NTOK / 128);        // 8 x 16
    dim3 gF(FFD / 128, NTOK / 128);       // 32 x 16
    dim3 gV(VV / 128, NTOK / 128);        // 250 x 16

    for (int l = 0; l < LL; l++) {
        __half* wqkv = wf + (size_t)l * WLAYER;         // [3*DD][DD]
        __half* wo   = wqkv + 3 * DD * DD;              // [DD][DD]
        __half* w1   = wo + DD * DD;                    // [FFD][DD]
        __half* w2   = w1 + (size_t)DD * FFD;           // [DD][FFD]

        ln_split_kernel<<<NTOK, 256>>>(x, ln1s + l * DD, ln1b + l * DD, hf, lf);
        gemm_f16<0><<<gQKV, 256, SMEM_F16>>>(hf, lf, wqkv, nullptr, nullptr, qkv, nullptr, nullptr, NTOK, 3 * DD, DD);
        attn_kernel<<<BB * HH * (SS / QT), 128>>>(qkv, ah, al);
        gemm_f16<1><<<gD, 256, SMEM_F16>>>(ah, al, wo, bo + l * DD, x, x, nullptr, nullptr, NTOK, DD, DD);

        ln_split_kernel<<<NTOK, 256>>>(x, ln2s + l * DD, ln2b + l * DD, hf, lf);
        gemm_f16<2><<<gF, 256, SMEM_F16>>>(hf, lf, w1, b1 + l * FFD, nullptr, nullptr, ffh, ffl, NTOK, FFD, DD);
        gemm_f16<1><<<gD, 256, SMEM_F16>>>(ffh, ffl, w2, b2 + l * DD, x, x, nullptr, nullptr, NTOK, DD, FFD);
    }

    ln_split_kernel<<<NTOK, 256>>>(x, lnfs, lnfb, hf, lf);
    gemm_f16<0><<<gV, 256, SMEM_F16>>>(hf, lf, ef, nullptr, nullptr, out, nullptr, nullptr, NTOK, VV, DD);
}

// round 9
// speedup vs baseline: 8.9126x; 1.3215x over previous
#include <cuda_runtime.h>
#include <cuda_fp16.h>
#include <math.h>
#include <stdint.h>

// Problem dims
#define BB   4
#define SS   512
#define DD   1024
#define HH   16
#define LL   6
#define FFD  4096
#define VV   32000
#define DKK  64
#define NTOK (BB*SS)   // 2048
#define QT   8         // queries per attention block
#define RS   (3*DD)    // fused qkv row stride

// ---------------------------------------------------------------------------
// Scratch (device globals — no runtime allocation allowed)
// ---------------------------------------------------------------------------
__device__ float g_x[NTOK*DD];
__device__ float g_qkv[NTOK*3*DD];
__device__ __half g_hf[NTOK*DD];       // LN out, fp16
__device__ __half g_af[NTOK*DD];       // attention out, fp16
__device__ __half g_ff[NTOK*FFD];      // GELU out, fp16
__device__ __half g_ef[(size_t)VV*DD]; // emb as fp16 (head B)

#define WLAYER (4*DD*DD + 2*DD*FFD)    // fp16 weights per layer (qkv,o,ff1,ff2)
__device__ __half g_wf[(size_t)LL*WLAYER];

__device__ __forceinline__ uint32_t smem_u32(const void* p) {
    uint32_t a;
    asm("{ .reg .u64 tmp; cvta.to.shared.u64 tmp, %1; cvt.u32.u64 %0, tmp; }"
        : "=r"(a) : "l"(p));
    return a;
}

// cp.async helpers
__device__ __forceinline__ void cp_async16(uint32_t dst, const void* src) {
    asm volatile("cp.async.cg.shared.global [%0], [%1], 16;" :: "r"(dst), "l"(src) : "memory");
}
__device__ __forceinline__ void cp_commit() {
    asm volatile("cp.async.commit_group;" ::: "memory");
}
template <int N>
__device__ __forceinline__ void cp_wait() {
    asm volatile("cp.async.wait_group %0;" :: "n"(N) : "memory");
}

__device__ __forceinline__ void ldsm_x4(unsigned& r0, unsigned& r1, unsigned& r2,
                                        unsigned& r3, uint32_t a) {
    asm volatile("ldmatrix.sync.aligned.m8n8.x4.shared.b16 {%0,%1,%2,%3}, [%4];"
                 : "=r"(r0), "=r"(r1), "=r"(r2), "=r"(r3) : "r"(a));
}

__device__ __forceinline__ void mma16816h(float* c, const unsigned* a, const unsigned* b) {
    asm volatile(
        "mma.sync.aligned.m16n8k16.row.col.f32.f16.f16.f32 "
        "{%0,%1,%2,%3}, {%4,%5,%6,%7}, {%8,%9}, {%0,%1,%2,%3};\n"
        : "+f"(c[0]), "+f"(c[1]), "+f"(c[2]), "+f"(c[3])
        : "r"(a[0]), "r"(a[1]), "r"(a[2]), "r"(a[3]), "r"(b[0]), "r"(b[1]));
}

// ---------------------------------------------------------------------------
// Embedding + batch-indexed positional encoding (faithful to reference)
// ---------------------------------------------------------------------------
__global__ void embed_kernel(const int* __restrict__ ids,
                             const float* __restrict__ emb,
                             const float* __restrict__ pe,
                             float* __restrict__ x) {
    int row = blockIdx.x;
    int b   = row / SS;
    int id  = ids[row];
    const float4* er = (const float4*)(emb + (size_t)id * DD);
    const float4* pr = (const float4*)(pe  + (size_t)b  * DD);
    float4* xr = (float4*)(x + (size_t)row * DD);
    int i = threadIdx.x;
    float4 e = er[i], p = pr[i];
    xr[i] = make_float4(e.x + p.x, e.y + p.y, e.z + p.z, e.w + p.w);
}

// ---------------------------------------------------------------------------
// Weight conversion: transpose + fp16, merged over layers
// ---------------------------------------------------------------------------
__device__ __forceinline__ void whalf_body(const float* __restrict__ W,
                                           __half* __restrict__ T, int K, int N) {
    __shared__ float tile[32][33];
    int n0 = blockIdx.x * 32, k0 = blockIdx.y * 32;
    int tx = threadIdx.x, ty = threadIdx.y;   // 32 x 8
    #pragma unroll
    for (int i = 0; i < 4; i++)
        tile[ty + i*8][tx] = W[(size_t)(k0 + ty + i*8) * N + n0 + tx];
    __syncthreads();
    #pragma unroll
    for (int i = 0; i < 4; i++)
        T[(size_t)(n0 + ty + i*8) * K + k0 + tx] = __float2half(tile[tx][ty + i*8]);
}

__global__ void whalf_qkvo_kernel(const float* __restrict__ Wq, const float* __restrict__ Wk,
                                  const float* __restrict__ Wv, const float* __restrict__ Wo,
                                  __half* __restrict__ T) {
    int z = blockIdx.z, l = z >> 2, widx = z & 3;
    const float* W = (widx == 0 ? Wq : widx == 1 ? Wk : widx == 2 ? Wv : Wo)
                     + (size_t)l * DD * DD;
    whalf_body(W, T + (size_t)l * WLAYER + (size_t)widx * DD * DD, DD, DD);
}

__global__ void whalf_ff_kernel(const float* __restrict__ W, __half* __restrict__ T,
                                int K, int N, size_t obase) {
    int l = blockIdx.z;
    whalf_body(W + (size_t)l * K * N, T + (size_t)l * WLAYER + obase, K, N);
}

// emb -> fp16 (vectorized)
__global__ void ehalf_kernel(const float* __restrict__ X, __half* __restrict__ Y, int n4) {
    int i = blockIdx.x * 256 + threadIdx.x;
    if (i < n4) {
        float4 v = ((const float4*)X)[i];
        ((__half2*)Y)[i * 2]     = __floats2half2_rn(v.x, v.y);
        ((__half2*)Y)[i * 2 + 1] = __floats2half2_rn(v.z, v.w);
    }
}

// ---------------------------------------------------------------------------
// LayerNorm, vectorized (1 float4/thread), fp16 output
// ---------------------------------------------------------------------------
__global__ void ln_f16_kernel(const float* __restrict__ x,
                              const float* __restrict__ s,
                              const float* __restrict__ b,
                              __half* __restrict__ y) {
    int row = blockIdx.x;
    int t = threadIdx.x;
    float4 v = ((const float4*)(x + (size_t)row * DD))[t];
    float s1 = v.x + v.y + v.z + v.w;
    float s2 = v.x*v.x + v.y*v.y + v.z*v.z + v.w*v.w;
    __shared__ float r1[256], r2[256];
    r1[t] = s1; r2[t] = s2;
    __syncthreads();
    for (int st = 128; st > 0; st >>= 1) {
        if (t < st) { r1[t] += r1[t + st]; r2[t] += r2[t + st]; }
        __syncthreads();
    }
    __shared__ float sm_mean, sm_rstd;
    if (t == 0) {
        float mean = r1[0] * (1.0f / DD);
        float var  = r2[0] * (1.0f / DD) - mean * mean;
        sm_mean = mean;
        sm_rstd = rsqrtf(var + 1e-5f);
    }
    __syncthreads();
    float mean = sm_mean, rstd = sm_rstd;
    float4 sv = ((const float4*)s)[t];
    float4 bv = ((const float4*)b)[t];
    __half2 p0 = __floats2half2_rn((v.x - mean) * rstd * sv.x + bv.x,
                                   (v.y - mean) * rstd * sv.y + bv.y);
    __half2 p1 = __floats2half2_rn((v.z - mean) * rstd * sv.z + bv.z,
                                   (v.w - mean) * rstd * sv.w + bv.w);
    size_t o = (size_t)row * DD + t * 4;
    *(uint32_t*)&y[o]     = *(uint32_t*)&p0;
    *(uint32_t*)&y[o + 2] = *(uint32_t*)&p1;
}

// ---------------------------------------------------------------------------
// fp16 GEMM (NT): C = A[M,K] @ B[N,K]^T
// 128x128 CTA tile, BK=32, 256 threads, cp.async double-buffer + ldmatrix.
// EPI 0: C = AB (+bias if non-null)  -> fp32  (QKV, head)
// EPI 1: C = Cin + AB + bias         -> fp32  (Wo, FF2 residual)
// EPI 2: gelu(AB + bias)             -> fp16  (FF1)
// ---------------------------------------------------------------------------
#define ROWB 80
#define MATB (128 * ROWB)
#define H_STAGEB (2 * MATB)             // 2 tiles/stage (A, B)
#define SMEM_F16 (2 * H_STAGEB)         // 40960 bytes

template <int EPI>
__global__ __launch_bounds__(256, 2)
void gemm_f16(const __half* __restrict__ A, const __half* __restrict__ B,
              const float* __restrict__ bias, const float* __restrict__ Cin,
              float* __restrict__ Cout, __half* __restrict__ Oh,
              int M, int N, int K) {
    extern __shared__ char smem[];
    uint32_t sb = smem_u32(smem);

    int t = threadIdx.x;
    int wid = t >> 5, lane = t & 31;
    int wm = wid >> 1, wn = wid & 1;
    int group = lane >> 2, tig = lane & 3;
    int m0 = blockIdx.y * 128, n0 = blockIdx.x * 128;

    float acc[2][8][4];
    #pragma unroll
    for (int i = 0; i < 2; i++)
        #pragma unroll
        for (int j = 0; j < 8; j++)
            #pragma unroll
            for (int kk = 0; kk < 4; kk++) acc[i][j][kk] = 0.f;

    const __half* srcs[2] = { A, B };

    auto load_stage = [&](int stage, int kt) {
        uint32_t base = sb + stage * H_STAGEB;
        int kofs = kt << 5;
        #pragma unroll
        for (int j = 0; j < 4; j++) {
            int lin = t + j * 256;           // 0..1023
            int mtx = lin >> 9;
            int c   = lin & 511;
            int row = c >> 2, q = c & 3;
            int rbase = (mtx == 0) ? m0 : n0;
            const __half* src = srcs[mtx] + (size_t)(rbase + row) * K + kofs + q * 8;
            cp_async16(base + mtx * MATB + row * ROWB + q * 16, src);
        }
        cp_commit();
    };

    uint32_t aRow = (uint32_t)(wm * 32 + (lane & 15)) * ROWB;
    uint32_t aCol = (uint32_t)((lane >> 4) << 3) * 2;
    uint32_t bRowBase = (uint32_t)(wn * 64 + (lane & 7) + ((lane >> 4) << 3)) * ROWB;
    uint32_t bCol = (uint32_t)(((lane >> 3) & 1) << 3) * 2;

    const int nk = K >> 5;

    load_stage(0, 0);

    for (int i = 0; i < nk; i++) {
        if (i + 1 < nk) { load_stage((i + 1) & 1, i + 1); cp_wait<1>(); }
        else            { cp_wait<0>(); }
        __syncthreads();

        uint32_t stb = sb + (i & 1) * H_STAGEB;
        uint32_t pA = stb + aRow + aCol;
        uint32_t pB = stb + MATB + bRowBase + bCol;

        #pragma unroll
        for (int ks = 0; ks < 2; ks++) {
            uint32_t ko = ks * 32;
            unsigned af[2][4], bf[8][2];
            #pragma unroll
            for (int mt = 0; mt < 2; mt++) {
                ldsm_x4(af[mt][0], af[mt][1], af[mt][2], af[mt][3],
                        pA + (uint32_t)(mt * 16) * ROWB + ko);
            }
            #pragma unroll
            for (int jp = 0; jp < 4; jp++) {
                ldsm_x4(bf[2*jp][0], bf[2*jp][1], bf[2*jp+1][0], bf[2*jp+1][1],
                        pB + (uint32_t)(jp * 16) * ROWB + ko);
            }
            #pragma unroll
            for (int mt = 0; mt < 2; mt++)
                #pragma unroll
                for (int nt = 0; nt < 8; nt++)
                    mma16816h(acc[mt][nt], af[mt], bf[nt]);
        }
        __syncthreads();
    }

    #pragma unroll
    for (int mt = 0; mt < 2; mt++) {
        #pragma unroll
        for (int nt = 0; nt < 8; nt++) {
            int col = n0 + wn * 64 + nt * 8 + tig * 2;
            float b0 = 0.f, b1v = 0.f;
            if (bias) { b0 = bias[col]; b1v = bias[col + 1]; }
            #pragma unroll
            for (int half = 0; half < 2; half++) {
                int row = m0 + wm * 32 + mt * 16 + group + half * 8;
                float v0 = acc[mt][nt][half * 2 + 0] + b0;
                float v1 = acc[mt][nt][half * 2 + 1] + b1v;
                size_t o = (size_t)row * N + col;
                if (EPI == 0) {
                    Cout[o] = v0; Cout[o + 1] = v1;
                } else if (EPI == 1) {
                    Cout[o] = Cin[o] + v0; Cout[o + 1] = Cin[o + 1] + v1;
                } else {
                    float g0 = 0.5f * v0 * (1.0f + erff(v0 * 0.70710678118654752f));
                    float g1 = 0.5f * v1 * (1.0f + erff(v1 * 0.70710678118654752f));
                    __half2 p = __floats2half2_rn(g0, g1);
                    *(uint32_t*)&Oh[o] = *(uint32_t*)&p;
                }
            }
        }
    }
}

// ---------------------------------------------------------------------------
// Causal attention from fused QKV buffer (row stride 3*DD).
// One block = (b, h, 8 queries). Exact softmax. fp16 output.
// ---------------------------------------------------------------------------
__global__ __launch_bounds__(128)
void attn_kernel(const float* __restrict__ QKV, __half* __restrict__ O) {
    const int NQB = SS / QT;
    int qt0 = (blockIdx.x % NQB) * QT;
    int bh  = blockIdx.x / NQB;
    int h   = bh % HH, b = bh / HH;
    int t   = threadIdx.x;

    __shared__ float qs[QT][DKK];
    __shared__ float Ks[64][DKK + 1];
    __shared__ float sc[QT][SS + 16];
    __shared__ float red[128];
    __shared__ float mx[QT], dn[QT];

    const float* Qp = QKV + h * DKK;
    const float* Kp = QKV + DD + h * DKK;
    const float* Vp = QKV + 2 * DD + h * DKK;

    for (int i = t; i < QT * DKK; i += 128) {
        int qi = i >> 6, d = i & 63;
        qs[qi][d] = Qp[(size_t)(b * SS + qt0 + qi) * RS + d];
    }
    __syncthreads();

    const int nkmax = qt0 + QT;
    const float scale = 0.125f;

    for (int kt = 0; kt < nkmax; kt += 64) {
        int rows = min(64, nkmax - kt);
        for (int i = t; i < rows * DKK; i += 128) {
            int r = i >> 6, d = i & 63;
            Ks[r][d] = Kp[(size_t)(b * SS + kt + r) * RS + d];
        }
        __syncthreads();
        int j = t & 63, qh = t >> 6;
        if (j < rows) {
            int kglob = kt + j;
            for (int qi = qh; qi < QT; qi += 2) {
                float dot = 0.f;
                #pragma unroll
                for (int d = 0; d < DKK; d++) dot += qs[qi][d] * Ks[j][d];
                sc[qi][kglob] = (kglob <= qt0 + qi) ? dot * scale : -1e30f;
            }
        }
        __syncthreads();
    }

    int tq = t >> 4, r = t & 15;
    float m = -1e30f;
    for (int k = r; k < nkmax; k += 16) m = fmaxf(m, sc[tq][k]);
    red[t] = m;
    __syncthreads();
    for (int st = 8; st > 0; st >>= 1) {
        if (r < st) red[t] = fmaxf(red[t], red[t + st]);
        __syncthreads();
    }
    if (r == 0) mx[tq] = red[t];
    __syncthreads();
    float mval = mx[tq];
    float s = 0.f;
    for (int k = r; k < nkmax; k += 16) {
        float e = expf(sc[tq][k] - mval);
        sc[tq][k] = e;
        s += e;
    }
    red[t] = s;
    __syncthreads();
    for (int st = 8; st > 0; st >>= 1) {
        if (r < st) red[t] += red[t + st];
        __syncthreads();
    }
    if (r == 0) dn[tq] = red[t];
    __syncthreads();

    int d = t & 63, part = t >> 6;
    float acc[QT];
    #pragma unroll
    for (int qi = 0; qi < QT; qi++) acc[qi] = 0.f;
    for (int k = part; k < nkmax; k += 2) {
        float v = Vp[(size_t)(b * SS + k) * RS + d];
        #pragma unroll
        for (int qi = 0; qi < QT; qi++) acc[qi] += sc[qi][k] * v;
    }
    for (int qi = 0; qi < QT; qi++) {
        red[t] = acc[qi];
        __syncthreads();
        if (part == 0) {
            float o = (red[t] + red[t + 64]) / dn[qi];
            size_t off = (size_t)(b * SS + qt0 + qi) * DD + h * DKK + d;
            O[off] = __float2half(o);
        }
        __syncthreads();
    }
}

// ---------------------------------------------------------------------------
// Launch
// ---------------------------------------------------------------------------
extern "C" void kernel_launch(void* const* d_in, const int* in_sizes, int n_in,
                              void* d_out, int out_size) {
    (void)in_sizes; (void)n_in; (void)out_size;

    const int*   ids  = (const int*)  d_in[0];
    const float* emb  = (const float*)d_in[1];
    const float* pe   = (const float*)d_in[2];
    const float* Wq   = (const float*)d_in[3];
    const float* Wk   = (const float*)d_in[4];
    const float* Wv   = (const float*)d_in[5];
    const float* Wo   = (const float*)d_in[6];
    const float* bo   = (const float*)d_in[7];
    const float* ln1s = (const float*)d_in[8];
    const float* ln1b = (const float*)d_in[9];
    const float* ln2s = (const float*)d_in[10];
    const float* ln2b = (const float*)d_in[11];
    const float* W1   = (const float*)d_in[12];
    const float* b1   = (const float*)d_in[13];
    const float* W2   = (const float*)d_in[14];
    const float* b2   = (const float*)d_in[15];
    const float* lnfs = (const float*)d_in[16];
    const float* lnfb = (const float*)d_in[17];
    float* out = (float*)d_out;

    float *x, *qkv;
    __half *hf, *af, *ff, *ef, *wf;
    cudaGetSymbolAddress((void**)&x,   g_x);
    cudaGetSymbolAddress((void**)&qkv, g_qkv);
    cudaGetSymbolAddress((void**)&hf,  g_hf);
    cudaGetSymbolAddress((void**)&af,  g_af);
    cudaGetSymbolAddress((void**)&ff,  g_ff);
    cudaGetSymbolAddress((void**)&ef,  g_ef);
    cudaGetSymbolAddress((void**)&wf,  g_wf);

    cudaFuncSetAttribute(gemm_f16<0>, cudaFuncAttributeMaxDynamicSharedMemorySize, SMEM_F16);
    cudaFuncSetAttribute(gemm_f16<1>, cudaFuncAttributeMaxDynamicSharedMemorySize, SMEM_F16);
    cudaFuncSetAttribute(gemm_f16<2>, cudaFuncAttributeMaxDynamicSharedMemorySize, SMEM_F16);

    dim3 tb32(32, 8);
    {
        dim3 gQ(DD / 32, DD / 32, LL * 4);
        whalf_qkvo_kernel<<<gQ, tb32>>>(Wq, Wk, Wv, Wo, wf);
        dim3 g1(FFD / 32, DD / 32, LL);
        whalf_ff_kernel<<<g1, tb32>>>(W1, wf, DD, FFD, (size_t)4 * DD * DD);
        dim3 g2(DD / 32, FFD / 32, LL);
        whalf_ff_kernel<<<g2, tb32>>>(W2, wf, FFD, DD, (size_t)4 * DD * DD + (size_t)DD * FFD);
    }
    {
        int n4 = (VV * DD) / 4;
        ehalf_kernel<<<(n4 + 255) / 256, 256>>>(emb, ef, n4);
    }

    embed_kernel<<<NTOK, 256>>>(ids, emb, pe, x);

    dim3 gQKV(3 * DD / 128, NTOK / 128);  // 24 x 16
    dim3 gD(DD / 128, NTOK / 128);        // 8 x 16
    dim3 gF(FFD / 128, NTOK / 128);       // 32 x 16
    dim3 gV(VV / 128, NTOK / 128);        // 250 x 16

    for (int l = 0; l < LL; l++) {
        __half* wqkv = wf + (size_t)l * WLAYER;         // [3*DD][DD]
        __half* wo   = wqkv + 3 * DD * DD;              // [DD][DD]
        __half* w1   = wo + DD * DD;                    // [FFD][DD]
        __half* w2   = w1 + (size_t)DD * FFD;           // [DD][FFD]

        ln_f16_kernel<<<NTOK, 256>>>(x, ln1s + l * DD, ln1b + l * DD, hf);
        gemm_f16<0><<<gQKV, 256, SMEM_F16>>>(hf, wqkv, nullptr, nullptr, qkv, nullptr, NTOK, 3 * DD, DD);
        attn_kernel<<<BB * HH * (SS / QT), 128>>>(qkv, af);
        gemm_f16<1><<<gD, 256, SMEM_F16>>>(af, wo, bo + l * DD, x, x, nullptr, NTOK, DD, DD);

        ln_f16_kernel<<<NTOK, 256>>>(x, ln2s + l * DD, ln2b + l * DD, hf);
        gemm_f16<2><<<gF, 256, SMEM_F16>>>(hf, w1, b1 + l * FFD, nullptr, nullptr, ff, NTOK, FFD, DD);
        gemm_f16<1><<<gD, 256, SMEM_F16>>>(ff, w2, b2 + l * DD, x, x, nullptr, NTOK, DD, FFD);
    }

    ln_f16_kernel<<<NTOK, 256>>>(x, lnfs, lnfb, hf);
    gemm_f16<0><<<gV, 256, SMEM_F16>>>(hf, ef, nullptr, nullptr, out, nullptr, NTOK, VV, DD);
}

// round 11
// speedup vs baseline: 12.8993x; 1.4473x over previous
#include <cuda_runtime.h>
#include <cuda_fp16.h>
#include <math.h>
#include <stdint.h>

// Problem dims
#define BB   4
#define SS   512
#define DD   1024
#define HH   16
#define LL   6
#define FFD  4096
#define VV   32000
#define DKK  64
#define NTOK (BB*SS)   // 2048
#define RS   (3*DD)    // fused qkv row stride (halves)

// ---------------------------------------------------------------------------
// Scratch (device globals — no runtime allocation allowed)
// ---------------------------------------------------------------------------
__device__ float  g_x[NTOK*DD];
__device__ __half g_qkv[NTOK*3*DD];    // fused qkv, fp16
__device__ __half g_hf[NTOK*DD];       // LN out, fp16
__device__ __half g_af[NTOK*DD];       // attention out, fp16
__device__ __half g_ff[NTOK*FFD];      // GELU out, fp16
__device__ __half g_ef[(size_t)VV*DD]; // emb as fp16 (head B)

#define WLAYER (4*DD*DD + 2*DD*FFD)    // fp16 weights per layer (qkv,o,ff1,ff2)
__device__ __half g_wf[(size_t)LL*WLAYER];

__device__ __forceinline__ uint32_t smem_u32(const void* p) {
    uint32_t a;
    asm("{ .reg .u64 tmp; cvta.to.shared.u64 tmp, %1; cvt.u32.u64 %0, tmp; }"
        : "=r"(a) : "l"(p));
    return a;
}

// cp.async helpers
__device__ __forceinline__ void cp_async16(uint32_t dst, const void* src) {
    asm volatile("cp.async.cg.shared.global [%0], [%1], 16;" :: "r"(dst), "l"(src) : "memory");
}
__device__ __forceinline__ void cp_commit() {
    asm volatile("cp.async.commit_group;" ::: "memory");
}
template <int N>
__device__ __forceinline__ void cp_wait() {
    asm volatile("cp.async.wait_group %0;" :: "n"(N) : "memory");
}

__device__ __forceinline__ void ldsm_x4(unsigned& r0, unsigned& r1, unsigned& r2,
                                        unsigned& r3, uint32_t a) {
    asm volatile("ldmatrix.sync.aligned.m8n8.x4.shared.b16 {%0,%1,%2,%3}, [%4];"
                 : "=r"(r0), "=r"(r1), "=r"(r2), "=r"(r3) : "r"(a));
}
__device__ __forceinline__ void ldsm_x4_t(unsigned& r0, unsigned& r1, unsigned& r2,
                                          unsigned& r3, uint32_t a) {
    asm volatile("ldmatrix.sync.aligned.m8n8.x4.trans.shared.b16 {%0,%1,%2,%3}, [%4];"
                 : "=r"(r0), "=r"(r1), "=r"(r2), "=r"(r3) : "r"(a));
}

__device__ __forceinline__ void mma16816h(float* c, const unsigned* a, const unsigned* b) {
    asm volatile(
        "mma.sync.aligned.m16n8k16.row.col.f32.f16.f16.f32 "
        "{%0,%1,%2,%3}, {%4,%5,%6,%7}, {%8,%9}, {%0,%1,%2,%3};\n"
        : "+f"(c[0]), "+f"(c[1]), "+f"(c[2]), "+f"(c[3])
        : "r"(a[0]), "r"(a[1]), "r"(a[2]), "r"(a[3]), "r"(b[0]), "r"(b[1]));
}

// ---------------------------------------------------------------------------
// Embedding + batch-indexed positional encoding (faithful to reference)
// ---------------------------------------------------------------------------
__global__ void embed_kernel(const int* __restrict__ ids,
                             const float* __restrict__ emb,
                             const float* __restrict__ pe,
                             float* __restrict__ x) {
    int row = blockIdx.x;
    int b   = row / SS;
    int id  = ids[row];
    const float4* er = (const float4*)(emb + (size_t)id * DD);
    const float4* pr = (const float4*)(pe  + (size_t)b  * DD);
    float4* xr = (float4*)(x + (size_t)row * DD);
    int i = threadIdx.x;
    float4 e = er[i], p = pr[i];
    xr[i] = make_float4(e.x + p.x, e.y + p.y, e.z + p.z, e.w + p.w);
}

// ---------------------------------------------------------------------------
// Weight conversion: transpose + fp16, merged over layers
// ---------------------------------------------------------------------------
__device__ __forceinline__ void whalf_body(const float* __restrict__ W,
                                           __half* __restrict__ T, int K, int N) {
    __shared__ float tile[32][33];
    int n0 = blockIdx.x * 32, k0 = blockIdx.y * 32;
    int tx = threadIdx.x, ty = threadIdx.y;   // 32 x 8
    #pragma unroll
    for (int i = 0; i < 4; i++)
        tile[ty + i*8][tx] = W[(size_t)(k0 + ty + i*8) * N + n0 + tx];
    __syncthreads();
    #pragma unroll
    for (int i = 0; i < 4; i++)
        T[(size_t)(n0 + ty + i*8) * K + k0 + tx] = __float2half(tile[tx][ty + i*8]);
}

__global__ void whalf_qkvo_kernel(const float* __restrict__ Wq, const float* __restrict__ Wk,
                                  const float* __restrict__ Wv, const float* __restrict__ Wo,
                                  __half* __restrict__ T) {
    int z = blockIdx.z, l = z >> 2, widx = z & 3;
    const float* W = (widx == 0 ? Wq : widx == 1 ? Wk : widx == 2 ? Wv : Wo)
                     + (size_t)l * DD * DD;
    whalf_body(W, T + (size_t)l * WLAYER + (size_t)widx * DD * DD, DD, DD);
}

__global__ void whalf_ff_kernel(const float* __restrict__ W, __half* __restrict__ T,
                                int K, int N, size_t obase) {
    int l = blockIdx.z;
    whalf_body(W + (size_t)l * K * N, T + (size_t)l * WLAYER + obase, K, N);
}

// emb -> fp16 (vectorized)
__global__ void ehalf_kernel(const float* __restrict__ X, __half* __restrict__ Y, int n4) {
    int i = blockIdx.x * 256 + threadIdx.x;
    if (i < n4) {
        float4 v = ((const float4*)X)[i];
        ((__half2*)Y)[i * 2]     = __floats2half2_rn(v.x, v.y);
        ((__half2*)Y)[i * 2 + 1] = __floats2half2_rn(v.z, v.w);
    }
}

// ---------------------------------------------------------------------------
// LayerNorm, vectorized (1 float4/thread), fp16 output
// ---------------------------------------------------------------------------
__global__ void ln_f16_kernel(const float* __restrict__ x,
                              const float* __restrict__ s,
                              const float* __restrict__ b,
                              __half* __restrict__ y) {
    int row = blockIdx.x;
    int t = threadIdx.x;
    float4 v = ((const float4*)(x + (size_t)row * DD))[t];
    float s1 = v.x + v.y + v.z + v.w;
    float s2 = v.x*v.x + v.y*v.y + v.z*v.z + v.w*v.w;
    __shared__ float r1[256], r2[256];
    r1[t] = s1; r2[t] = s2;
    __syncthreads();
    for (int st = 128; st > 0; st >>= 1) {
        if (t < st) { r1[t] += r1[t + st]; r2[t] += r2[t + st]; }
        __syncthreads();
    }
    __shared__ float sm_mean, sm_rstd;
    if (t == 0) {
        float mean = r1[0] * (1.0f / DD);
        float var  = r2[0] * (1.0f / DD) - mean * mean;
        sm_mean = mean;
        sm_rstd = rsqrtf(var + 1e-5f);
    }
    __syncthreads();
    float mean = sm_mean, rstd = sm_rstd;
    float4 sv = ((const float4*)s)[t];
    float4 bv = ((const float4*)b)[t];
    __half2 p0 = __floats2half2_rn((v.x - mean) * rstd * sv.x + bv.x,
                                   (v.y - mean) * rstd * sv.y + bv.y);
    __half2 p1 = __floats2half2_rn((v.z - mean) * rstd * sv.z + bv.z,
                                   (v.w - mean) * rstd * sv.w + bv.w);
    size_t o = (size_t)row * DD + t * 4;
    *(uint32_t*)&y[o]     = *(uint32_t*)&p0;
    *(uint32_t*)&y[o + 2] = *(uint32_t*)&p1;
}

// ---------------------------------------------------------------------------
// fp16 GEMM (NT): C = A[M,K] @ B[N,K]^T
// EPI 0: C = AB (+bias)        -> fp32  (head)
// EPI 1: C = Cin + AB + bias   -> fp32  (Wo, FF2 residual)
// EPI 2: gelu(AB + bias)       -> fp16  (FF1)
// EPI 3: C = AB                -> fp16  (QKV)
// ---------------------------------------------------------------------------
#define ROWB 80
#define MATB (128 * ROWB)
#define H_STAGEB (2 * MATB)
#define SMEM_F16 (2 * H_STAGEB)         // 40960 bytes

template <int EPI>
__global__ __launch_bounds__(256, 2)
void gemm_f16(const __half* __restrict__ A, const __half* __restrict__ B,
              const float* __restrict__ bias, const float* __restrict__ Cin,
              float* __restrict__ Cout, __half* __restrict__ Oh,
              int M, int N, int K) {
    extern __shared__ char smem[];
    uint32_t sb = smem_u32(smem);

    int t = threadIdx.x;
    int wid = t >> 5, lane = t & 31;
    int wm = wid >> 1, wn = wid & 1;
    int group = lane >> 2, tig = lane & 3;
    int m0 = blockIdx.y * 128, n0 = blockIdx.x * 128;

    float acc[2][8][4];
    #pragma unroll
    for (int i = 0; i < 2; i++)
        #pragma unroll
        for (int j = 0; j < 8; j++)
            #pragma unroll
            for (int kk = 0; kk < 4; kk++) acc[i][j][kk] = 0.f;

    const __half* srcs[2] = { A, B };

    auto load_stage = [&](int stage, int kt) {
        uint32_t base = sb + stage * H_STAGEB;
        int kofs = kt << 5;
        #pragma unroll
        for (int j = 0; j < 4; j++) {
            int lin = t + j * 256;
            int mtx = lin >> 9;
            int c   = lin & 511;
            int row = c >> 2, q = c & 3;
            int rbase = (mtx == 0) ? m0 : n0;
            const __half* src = srcs[mtx] + (size_t)(rbase + row) * K + kofs + q * 8;
            cp_async16(base + mtx * MATB + row * ROWB + q * 16, src);
        }
        cp_commit();
    };

    uint32_t aRow = (uint32_t)(wm * 32 + (lane & 15)) * ROWB;
    uint32_t aCol = (uint32_t)((lane >> 4) << 3) * 2;
    uint32_t bRowBase = (uint32_t)(wn * 64 + (lane & 7) + ((lane >> 4) << 3)) * ROWB;
    uint32_t bCol = (uint32_t)(((lane >> 3) & 1) << 3) * 2;

    const int nk = K >> 5;

    load_stage(0, 0);

    for (int i = 0; i < nk; i++) {
        if (i + 1 < nk) { load_stage((i + 1) & 1, i + 1); cp_wait<1>(); }
        else            { cp_wait<0>(); }
        __syncthreads();

        uint32_t stb = sb + (i & 1) * H_STAGEB;
        uint32_t pA = stb + aRow + aCol;
        uint32_t pB = stb + MATB + bRowBase + bCol;

        #pragma unroll
        for (int ks = 0; ks < 2; ks++) {
            uint32_t ko = ks * 32;
            unsigned af[2][4], bf[8][2];
            #pragma unroll
            for (int mt = 0; mt < 2; mt++) {
                ldsm_x4(af[mt][0], af[mt][1], af[mt][2], af[mt][3],
                        pA + (uint32_t)(mt * 16) * ROWB + ko);
            }
            #pragma unroll
            for (int jp = 0; jp < 4; jp++) {
                ldsm_x4(bf[2*jp][0], bf[2*jp][1], bf[2*jp+1][0], bf[2*jp+1][1],
                        pB + (uint32_t)(jp * 16) * ROWB + ko);
            }
            #pragma unroll
            for (int mt = 0; mt < 2; mt++)
                #pragma unroll
                for (int nt = 0; nt < 8; nt++)
                    mma16816h(acc[mt][nt], af[mt], bf[nt]);
        }
        __syncthreads();
    }

    #pragma unroll
    for (int mt = 0; mt < 2; mt++) {
        #pragma unroll
        for (int nt = 0; nt < 8; nt++) {
            int col = n0 + wn * 64 + nt * 8 + tig * 2;
            float b0 = 0.f, b1v = 0.f;
            if (EPI != 3 && bias) { b0 = bias[col]; b1v = bias[col + 1]; }
            #pragma unroll
            for (int half = 0; half < 2; half++) {
                int row = m0 + wm * 32 + mt * 16 + group + half * 8;
                float v0 = acc[mt][nt][half * 2 + 0] + b0;
                float v1 = acc[mt][nt][half * 2 + 1] + b1v;
                size_t o = (size_t)row * N + col;
                if (EPI == 0) {
                    Cout[o] = v0; Cout[o + 1] = v1;
                } else if (EPI == 1) {
                    Cout[o] = Cin[o] + v0; Cout[o + 1] = Cin[o + 1] + v1;
                } else if (EPI == 2) {
                    float g0 = 0.5f * v0 * (1.0f + erff(v0 * 0.70710678118654752f));
                    float g1 = 0.5f * v1 * (1.0f + erff(v1 * 0.70710678118654752f));
                    __half2 p = __floats2half2_rn(g0, g1);
                    *(uint32_t*)&Oh[o] = *(uint32_t*)&p;
                } else {
                    __half2 p = __floats2half2_rn(v0, v1);
                    *(uint32_t*)&Oh[o] = *(uint32_t*)&p;
                }
            }
        }
    }
}

// ---------------------------------------------------------------------------
// Flash-style HMMA attention. CTA = (64-query tile, b, h); 4 warps x 16 rows.
// K/V tiles of 64 keys, cp.async double-buffered. Online softmax in regs.
// Rows are 64 halves = 128 data bytes; AROWB = 144 (128 + 16 pad).
// ---------------------------------------------------------------------------
#define AROWB 144
#define A_QOFF 0
#define A_TILE (64 * AROWB)            // 9216 bytes per matrix tile
#define A_STG  (2 * A_TILE)            // K+V per stage
#define A_KOFF(s) (A_TILE + (s) * A_STG)
#define A_VOFF(s) (A_TILE + (s) * A_STG + A_TILE)
#define A_SMEM (A_TILE + 2 * A_STG)    // 46080 bytes

__global__ __launch_bounds__(128)
void fattn_kernel(const __half* __restrict__ QKV, __half* __restrict__ O) {
    __shared__ char smem[A_SMEM];
    uint32_t sb = smem_u32(smem);

    int qt = blockIdx.x;               // 0..7 (64-query tiles)
    int bh = blockIdx.y;
    int b  = bh >> 4, h = bh & 15;
    int t  = threadIdx.x;
    int w  = t >> 5, lane = t & 31;
    int group = lane >> 2, tig = lane & 3;

    size_t tokbase = (size_t)(b * SS + qt * 64);

    // ---- prologue: load Q tile + K/V tile 0
    {
        #pragma unroll
        for (int j = 0; j < 4; j++) {      // Q: 512 chunks (64 rows x 8 x 16B)
            int lin = t + j * 128;
            int row = lin >> 3, q = lin & 7;
            const __half* src = QKV + (tokbase + row) * RS + h * DKK + q * 8;
            cp_async16(sb + A_QOFF + row * AROWB + q * 16, src);
        }
        #pragma unroll
        for (int j = 0; j < 8; j++) {      // K,V tile 0: 1024 chunks
            int lin = t + j * 128;
            int mtx = lin >> 9;
            int c   = lin & 511;
            int row = c >> 3, q = c & 7;
            const __half* src = QKV + (size_t)(b * SS + row) * RS + (1 + mtx) * DD + h * DKK + q * 8;
            cp_async16(sb + (mtx == 0 ? A_KOFF(0) : A_VOFF(0)) + row * AROWB + q * 16, src);
        }
        cp_commit();
    }

    // fragment addresses
    uint32_t qAddr = sb + A_QOFF + (uint32_t)(w * 16 + (lane & 15)) * AROWB
                   + (uint32_t)((lane >> 4) << 3) * 2;
    uint32_t kRowSel = (uint32_t)((lane & 7) + ((lane >> 4) << 3)) * AROWB
                     + (uint32_t)(((lane >> 3) & 1) << 3) * 2;
    uint32_t vRowSel = (uint32_t)((lane & 7) + (((lane >> 3) & 1) << 3)) * AROWB
                     + (uint32_t)((lane >> 4) << 3) * 2;

    float oc[8][4];
    #pragma unroll
    for (int i = 0; i < 8; i++)
        #pragma unroll
        for (int j = 0; j < 4; j++) oc[i][j] = 0.f;
    float m0 = -1e30f, m1 = -1e30f, l0 = 0.f, l1 = 0.f;

    const float scale = 0.125f;

    for (int kt = 0; kt <= qt; kt++) {
        if (kt < qt) {
            int s = (kt + 1) & 1;
            #pragma unroll
            for (int j = 0; j < 8; j++) {
                int lin = t + j * 128;
                int mtx = lin >> 9;
                int c   = lin & 511;
                int row = c >> 3, q = c & 7;
                const __half* src = QKV + (size_t)(b * SS + (kt + 1) * 64 + row) * RS
                                  + (1 + mtx) * DD + h * DKK + q * 8;
                cp_async16(sb + (mtx == 0 ? A_KOFF(s) : A_VOFF(s)) + row * AROWB + q * 16, src);
            }
            cp_commit();
            cp_wait<1>();
        } else {
            cp_wait<0>();
        }
        __syncthreads();

        int s = kt & 1;
        uint32_t kBase = sb + A_KOFF(s) + kRowSel;
        uint32_t vBase = sb + A_VOFF(s) + vRowSel;

        // ---- S = Q @ K^T  (16 rows x 64 keys per warp)
        float sc[8][4];
        #pragma unroll
        for (int i = 0; i < 8; i++)
            #pragma unroll
            for (int j = 0; j < 4; j++) sc[i][j] = 0.f;

        unsigned qf[4][4];
        #pragma unroll
        for (int ks = 0; ks < 4; ks++)
            ldsm_x4(qf[ks][0], qf[ks][1], qf[ks][2], qf[ks][3], qAddr + ks * 32);

        #pragma unroll
        for (int jp = 0; jp < 4; jp++) {
            #pragma unroll
            for (int ks = 0; ks < 4; ks++) {
                unsigned b0, b1, b2, b3;
                ldsm_x4(b0, b1, b2, b3, kBase + (uint32_t)(jp * 16) * AROWB + ks * 32);
                unsigned bb0[2] = { b0, b1 }, bb1[2] = { b2, b3 };
                mma16816h(sc[2*jp],     qf[ks], bb0);
                mma16816h(sc[2*jp + 1], qf[ks], bb1);
            }
        }

        // scale + causal mask (diagonal tile only)
        #pragma unroll
        for (int i = 0; i < 8; i++)
            #pragma unroll
            for (int e = 0; e < 4; e++) sc[i][e] *= scale;
        if (kt == qt) {
            #pragma unroll
            for (int i = 0; i < 8; i++) {
                #pragma unroll
                for (int e = 0; e < 4; e++) {
                    int key = i * 8 + 2 * tig + (e & 1);
                    int row = w * 16 + group + ((e >> 1) << 3);
                    if (key > row) sc[i][e] = -1e30f;
                }
            }
        }

        // online softmax (rows group / group+8; reduce over tig lanes)
        float rm0 = -1e30f, rm1 = -1e30f;
        #pragma unroll
        for (int i = 0; i < 8; i++) {
            rm0 = fmaxf(rm0, fmaxf(sc[i][0], sc[i][1]));
            rm1 = fmaxf(rm1, fmaxf(sc[i][2], sc[i][3]));
        }
        rm0 = fmaxf(rm0, __shfl_xor_sync(0xffffffff, rm0, 1));
        rm0 = fmaxf(rm0, __shfl_xor_sync(0xffffffff, rm0, 2));
        rm1 = fmaxf(rm1, __shfl_xor_sync(0xffffffff, rm1, 1));
        rm1 = fmaxf(rm1, __shfl_xor_sync(0xffffffff, rm1, 2));

        float mn0 = fmaxf(m0, rm0), mn1 = fmaxf(m1, rm1);
        float al0 = __expf(m0 - mn0), al1 = __expf(m1 - mn1);

        float rs0 = 0.f, rs1 = 0.f;
        unsigned pa[4][4];
        #pragma unroll
        for (int j = 0; j < 4; j++) {
            float p00 = __expf(sc[2*j][0] - mn0);
            float p01 = __expf(sc[2*j][1] - mn0);
            float p10 = __expf(sc[2*j][2] - mn1);
            float p11 = __expf(sc[2*j][3] - mn1);
            float q00 = __expf(sc[2*j+1][0] - mn0);
            float q01 = __expf(sc[2*j+1][1] - mn0);
            float q10 = __expf(sc[2*j+1][2] - mn1);
            float q11 = __expf(sc[2*j+1][3] - mn1);
            rs0 += p00 + p01 + q00 + q01;
            rs1 += p10 + p11 + q10 + q11;
            __half2 h0 = __floats2half2_rn(p00, p01);
            __half2 h1 = __floats2half2_rn(p10, p11);
            __half2 h2 = __floats2half2_rn(q00, q01);
            __half2 h3 = __floats2half2_rn(q10, q11);
            pa[j][0] = *(unsigned*)&h0;
            pa[j][1] = *(unsigned*)&h1;
            pa[j][2] = *(unsigned*)&h2;
            pa[j][3] = *(unsigned*)&h3;
        }
        rs0 += __shfl_xor_sync(0xffffffff, rs0, 1);
        rs0 += __shfl_xor_sync(0xffffffff, rs0, 2);
        rs1 += __shfl_xor_sync(0xffffffff, rs1, 1);
        rs1 += __shfl_xor_sync(0xffffffff, rs1, 2);

        l0 = l0 * al0 + rs0;
        l1 = l1 * al1 + rs1;
        m0 = mn0; m1 = mn1;

        #pragma unroll
        for (int i = 0; i < 8; i++) {
            oc[i][0] *= al0; oc[i][1] *= al0;
            oc[i][2] *= al1; oc[i][3] *= al1;
        }

        // ---- O += P @ V   (V^T fragments via ldmatrix.trans)
        #pragma unroll
        for (int j = 0; j < 4; j++) {
            #pragma unroll
            for (int np = 0; np < 4; np++) {
                unsigned v0, v1, v2, v3;
                ldsm_x4_t(v0, v1, v2, v3,
                          vBase + (uint32_t)(j * 16) * AROWB + (uint32_t)(np * 16) * 2);
                unsigned vv0[2] = { v0, v1 }, vv1[2] = { v2, v3 };
                mma16816h(oc[2*np],     pa[j], vv0);
                mma16816h(oc[2*np + 1], pa[j], vv1);
            }
        }
        __syncthreads();
    }

    // ---- write output (fp16)
    float inv0 = 1.0f / l0, inv1 = 1.0f / l1;
    size_t r0 = (tokbase + w * 16 + group) * DD + h * DKK;
    size_t r1 = r0 + 8 * DD;
    #pragma unroll
    for (int i = 0; i < 8; i++) {
        int col = i * 8 + 2 * tig;
        __half2 o0 = __floats2half2_rn(oc[i][0] * inv0, oc[i][1] * inv0);
        __half2 o1 = __floats2half2_rn(oc[i][2] * inv1, oc[i][3] * inv1);
        *(uint32_t*)&O[r0 + col] = *(uint32_t*)&o0;
        *(uint32_t*)&O[r1 + col] = *(uint32_t*)&o1;
    }
}

// ---------------------------------------------------------------------------
// Launch
// ---------------------------------------------------------------------------
extern "C" void kernel_launch(void* const* d_in, const int* in_sizes, int n_in,
                              void* d_out, int out_size) {
    (void)in_sizes; (void)n_in; (void)out_size;

    const int*   ids  = (const int*)  d_in[0];
    const float* emb  = (const float*)d_in[1];
    const float* pe   = (const float*)d_in[2];
    const float* Wq   = (const float*)d_in[3];
    const float* Wk   = (const float*)d_in[4];
    const float* Wv   = (const float*)d_in[5];
    const float* Wo   = (const float*)d_in[6];
    const float* bo   = (const float*)d_in[7];
    const float* ln1s = (const float*)d_in[8];
    const float* ln1b = (const float*)d_in[9];
    const float* ln2s = (const float*)d_in[10];
    const float* ln2b = (const float*)d_in[11];
    const float* W1   = (const float*)d_in[12];
    const float* b1   = (const float*)d_in[13];
    const float* W2   = (const float*)d_in[14];
    const float* b2   = (const float*)d_in[15];
    const float* lnfs = (const float*)d_in[16];
    const float* lnfb = (const float*)d_in[17];
    float* out = (float*)d_out;

    float *x;
    __half *qkv, *hf, *af, *ff, *ef, *wf;
    cudaGetSymbolAddress((void**)&x,   g_x);
    cudaGetSymbolAddress((void**)&qkv, g_qkv);
    cudaGetSymbolAddress((void**)&hf,  g_hf);
    cudaGetSymbolAddress((void**)&af,  g_af);
    cudaGetSymbolAddress((void**)&ff,  g_ff);
    cudaGetSymbolAddress((void**)&ef,  g_ef);
    cudaGetSymbolAddress((void**)&wf,  g_wf);

    cudaFuncSetAttribute(gemm_f16<0>, cudaFuncAttributeMaxDynamicSharedMemorySize, SMEM_F16);
    cudaFuncSetAttribute(gemm_f16<1>, cudaFuncAttributeMaxDynamicSharedMemorySize, SMEM_F16);
    cudaFuncSetAttribute(gemm_f16<2>, cudaFuncAttributeMaxDynamicSharedMemorySize, SMEM_F16);
    cudaFuncSetAttribute(gemm_f16<3>, cudaFuncAttributeMaxDynamicSharedMemorySize, SMEM_F16);

    dim3 tb32(32, 8);
    {
        dim3 gQ(DD / 32, DD / 32, LL * 4);
        whalf_qkvo_kernel<<<gQ, tb32>>>(Wq, Wk, Wv, Wo, wf);
        dim3 g1(FFD / 32, DD / 32, LL);
        whalf_ff_kernel<<<g1, tb32>>>(W1, wf, DD, FFD, (size_t)4 * DD * DD);
        dim3 g2(DD / 32, FFD / 32, LL);
        whalf_ff_kernel<<<g2, tb32>>>(W2, wf, FFD, DD, (size_t)4 * DD * DD + (size_t)DD * FFD);
    }
    {
        int n4 = (VV * DD) / 4;
        ehalf_kernel<<<(n4 + 255) / 256, 256>>>(emb, ef, n4);
    }

    embed_kernel<<<NTOK, 256>>>(ids, emb, pe, x);

    dim3 gQKV(3 * DD / 128, NTOK / 128);  // 24 x 16
    dim3 gD(DD / 128, NTOK / 128);        // 8 x 16
    dim3 gF(FFD / 128, NTOK / 128);       // 32 x 16
    dim3 gV(VV / 128, NTOK / 128);        // 250 x 16
    dim3 gA(SS / 64, BB * HH);            // 8 x 64

    for (int l = 0; l < LL; l++) {
        __half* wqkv = wf + (size_t)l * WLAYER;         // [3*DD][DD]
        __half* wo   = wqkv + 3 * DD * DD;              // [DD][DD]
        __half* w1   = wo + DD * DD;                    // [FFD][DD]
        __half* w2   = w1 + (size_t)DD * FFD;           // [DD][FFD]

        ln_f16_kernel<<<NTOK, 256>>>(x, ln1s + l * DD, ln1b + l * DD, hf);
        gemm_f16<3><<<gQKV, 256, SMEM_F16>>>(hf, wqkv, nullptr, nullptr, nullptr, qkv, NTOK, 3 * DD, DD);
        fattn_kernel<<<gA, 128>>>(qkv, af);
        gemm_f16<1><<<gD, 256, SMEM_F16>>>(af, wo, bo + l * DD, x, x, nullptr, NTOK, DD, DD);

        ln_f16_kernel<<<NTOK, 256>>>(x, ln2s + l * DD, ln2b + l * DD, hf);
        gemm_f16<2><<<gF, 256, SMEM_F16>>>(hf, w1, b1 + l * FFD, nullptr, nullptr, ff, NTOK, FFD, DD);
        gemm_f16<1><<<gD, 256, SMEM_F16>>>(ff, w2, b2 + l * DD, x, x, nullptr, NTOK, DD, FFD);
    }

    ln_f16_kernel<<<NTOK, 256>>>(x, lnfs, lnfb, hf);
    gemm_f16<0><<<gV, 256, SMEM_F16>>>(hf, ef, nullptr, nullptr, out, nullptr, NTOK, VV, DD);
}

// round 12
// speedup vs baseline: 15.3026x; 1.1863x over previous
#include <cuda_runtime.h>
#include <cuda_fp16.h>
#include <math.h>
#include <stdint.h>

// Problem dims
#define BB   4
#define SS   512
#define DD   1024
#define HH   16
#define LL   6
#define FFD  4096
#define VV   32000
#define DKK  64
#define NTOK (BB*SS)   // 2048
#define RS   (3*DD)    // fused qkv row stride (halves)

// ---------------------------------------------------------------------------
// Scratch (device globals — no runtime allocation allowed)
// ---------------------------------------------------------------------------
__device__ float  g_x[NTOK*DD];
__device__ __half g_qkv[NTOK*3*DD];    // fused qkv, fp16
__device__ __half g_hf[NTOK*DD];       // LN out, fp16
__device__ __half g_af[NTOK*DD];       // attention out, fp16
__device__ __half g_ff[NTOK*FFD];      // GELU out, fp16
__device__ __half g_ef[(size_t)VV*DD]; // emb as fp16 (head B)

#define WLAYER (4*DD*DD + 2*DD*FFD)    // fp16 weights per layer (qkv,o,ff1,ff2)
__device__ __half g_wf[(size_t)LL*WLAYER];

__device__ __forceinline__ uint32_t smem_u32(const void* p) {
    uint32_t a;
    asm("{ .reg .u64 tmp; cvta.to.shared.u64 tmp, %1; cvt.u32.u64 %0, tmp; }"
        : "=r"(a) : "l"(p));
    return a;
}

// cp.async helpers
__device__ __forceinline__ void cp_async16(uint32_t dst, const void* src) {
    asm volatile("cp.async.cg.shared.global [%0], [%1], 16;" :: "r"(dst), "l"(src) : "memory");
}
__device__ __forceinline__ void cp_commit() {
    asm volatile("cp.async.commit_group;" ::: "memory");
}
template <int N>
__device__ __forceinline__ void cp_wait() {
    asm volatile("cp.async.wait_group %0;" :: "n"(N) : "memory");
}

__device__ __forceinline__ void ldsm_x4(unsigned& r0, unsigned& r1, unsigned& r2,
                                        unsigned& r3, uint32_t a) {
    asm volatile("ldmatrix.sync.aligned.m8n8.x4.shared.b16 {%0,%1,%2,%3}, [%4];"
                 : "=r"(r0), "=r"(r1), "=r"(r2), "=r"(r3) : "r"(a));
}
__device__ __forceinline__ void ldsm_x4_t(unsigned& r0, unsigned& r1, unsigned& r2,
                                          unsigned& r3, uint32_t a) {
    asm volatile("ldmatrix.sync.aligned.m8n8.x4.trans.shared.b16 {%0,%1,%2,%3}, [%4];"
                 : "=r"(r0), "=r"(r1), "=r"(r2), "=r"(r3) : "r"(a));
}

__device__ __forceinline__ void mma16816h(float* c, const unsigned* a, const unsigned* b) {
    asm volatile(
        "mma.sync.aligned.m16n8k16.row.col.f32.f16.f16.f32 "
        "{%0,%1,%2,%3}, {%4,%5,%6,%7}, {%8,%9}, {%0,%1,%2,%3};\n"
        : "+f"(c[0]), "+f"(c[1]), "+f"(c[2]), "+f"(c[3])
        : "r"(a[0]), "r"(a[1]), "r"(a[2]), "r"(a[3]), "r"(b[0]), "r"(b[1]));
}

// ---------------------------------------------------------------------------
// Embedding + batch-indexed positional encoding (faithful to reference)
// ---------------------------------------------------------------------------
__global__ void embed_kernel(const int* __restrict__ ids,
                             const float* __restrict__ emb,
                             const float* __restrict__ pe,
                             float* __restrict__ x) {
    int row = blockIdx.x;
    int b   = row / SS;
    int id  = ids[row];
    const float4* er = (const float4*)(emb + (size_t)id * DD);
    const float4* pr = (const float4*)(pe  + (size_t)b  * DD);
    float4* xr = (float4*)(x + (size_t)row * DD);
    int i = threadIdx.x;
    float4 e = er[i], p = pr[i];
    xr[i] = make_float4(e.x + p.x, e.y + p.y, e.z + p.z, e.w + p.w);
}

// ---------------------------------------------------------------------------
// Weight conversion: transpose + fp16 (half2 stores), merged over layers
// ---------------------------------------------------------------------------
__device__ __forceinline__ void whalf_body(const float* __restrict__ W,
                                           __half* __restrict__ T, int K, int N) {
    __shared__ float tile[32][33];
    int n0 = blockIdx.x * 32, k0 = blockIdx.y * 32;
    int tx = threadIdx.x, ty = threadIdx.y;   // 32 x 8
    #pragma unroll
    for (int i = 0; i < 4; i++)
        tile[ty + i*8][tx] = W[(size_t)(k0 + ty + i*8) * N + n0 + tx];
    __syncthreads();
    int lin = tx + (ty << 5);
    #pragma unroll
    for (int rep = 0; rep < 2; rep++) {
        int idx = lin + rep * 256;
        int n  = idx >> 4;
        int kk = (idx & 15) << 1;
        __half2 p = __floats2half2_rn(tile[kk][n], tile[kk + 1][n]);
        *(__half2*)&T[(size_t)(n0 + n) * K + k0 + kk] = p;
    }
}

__global__ void whalf_qkvo_kernel(const float* __restrict__ Wq, const float* __restrict__ Wk,
                                  const float* __restrict__ Wv, const float* __restrict__ Wo,
                                  __half* __restrict__ T) {
    int z = blockIdx.z, l = z >> 2, widx = z & 3;
    const float* W = (widx == 0 ? Wq : widx == 1 ? Wk : widx == 2 ? Wv : Wo)
                     + (size_t)l * DD * DD;
    whalf_body(W, T + (size_t)l * WLAYER + (size_t)widx * DD * DD, DD, DD);
}

__global__ void whalf_ff_kernel(const float* __restrict__ W, __half* __restrict__ T,
                                int K, int N, size_t obase) {
    int l = blockIdx.z;
    whalf_body(W + (size_t)l * K * N, T + (size_t)l * WLAYER + obase, K, N);
}

// emb -> fp16 (vectorized)
__global__ void ehalf_kernel(const float* __restrict__ X, __half* __restrict__ Y, int n4) {
    int i = blockIdx.x * 256 + threadIdx.x;
    if (i < n4) {
        float4 v = ((const float4*)X)[i];
        ((__half2*)Y)[i * 2]     = __floats2half2_rn(v.x, v.y);
        ((__half2*)Y)[i * 2 + 1] = __floats2half2_rn(v.z, v.w);
    }
}

// ---------------------------------------------------------------------------
// LayerNorm: 1 float4/thread, warp-shuffle reduce (single barrier), fp16 out
// ---------------------------------------------------------------------------
__global__ void ln_f16_kernel(const float* __restrict__ x,
                              const float* __restrict__ s,
                              const float* __restrict__ b,
                              __half* __restrict__ y) {
    int row = blockIdx.x;
    int t = threadIdx.x;
    float4 v = ((const float4*)(x + (size_t)row * DD))[t];
    float s1 = v.x + v.y + v.z + v.w;
    float s2 = v.x*v.x + v.y*v.y + v.z*v.z + v.w*v.w;
    #pragma unroll
    for (int o = 16; o > 0; o >>= 1) {
        s1 += __shfl_xor_sync(0xffffffff, s1, o);
        s2 += __shfl_xor_sync(0xffffffff, s2, o);
    }
    __shared__ float a1[8], a2[8];
    if ((t & 31) == 0) { a1[t >> 5] = s1; a2[t >> 5] = s2; }
    __syncthreads();
    float m1 = 0.f, m2 = 0.f;
    #pragma unroll
    for (int i = 0; i < 8; i++) { m1 += a1[i]; m2 += a2[i]; }
    float mean = m1 * (1.0f / DD);
    float var  = m2 * (1.0f / DD) - mean * mean;
    float rstd = rsqrtf(var + 1e-5f);

    float4 sv = ((const float4*)s)[t];
    float4 bv = ((const float4*)b)[t];
    __half2 p0 = __floats2half2_rn((v.x - mean) * rstd * sv.x + bv.x,
                                   (v.y - mean) * rstd * sv.y + bv.y);
    __half2 p1 = __floats2half2_rn((v.z - mean) * rstd * sv.z + bv.z,
                                   (v.w - mean) * rstd * sv.w + bv.w);
    size_t o = (size_t)row * DD + t * 4;
    *(uint32_t*)&y[o]     = *(uint32_t*)&p0;
    *(uint32_t*)&y[o + 2] = *(uint32_t*)&p1;
}

// ---------------------------------------------------------------------------
// fp16 GEMM (NT): C = A[M,K] @ B[N,K]^T
// 128x128 CTA tile, BK=64 (ROWB=144: 128B data + 16 pad), 256 threads,
// cp.async double-buffer + ldmatrix. K must be a multiple of 64.
// EPI 0: C = AB (+bias)        -> fp32  (head)
// EPI 1: C = Cin + AB + bias   -> fp32  (Wo, FF2 residual)
// EPI 2: gelu(AB + bias)       -> fp16  (FF1)
// EPI 3: C = AB                -> fp16  (QKV)
// ---------------------------------------------------------------------------
#define ROWB 144
#define MATB (128 * ROWB)               // 18432
#define H_STAGEB (2 * MATB)             // 36864
#define SMEM_F16 (2 * H_STAGEB)         // 73728 bytes

template <int EPI>
__global__ __launch_bounds__(256, 2)
void gemm_f16(const __half* __restrict__ A, const __half* __restrict__ B,
              const float* __restrict__ bias, const float* __restrict__ Cin,
              float* __restrict__ Cout, __half* __restrict__ Oh,
              int M, int N, int K) {
    extern __shared__ char smem[];
    uint32_t sb = smem_u32(smem);

    int t = threadIdx.x;
    int wid = t >> 5, lane = t & 31;
    int wm = wid >> 1, wn = wid & 1;
    int group = lane >> 2, tig = lane & 3;
    int m0 = blockIdx.y * 128, n0 = blockIdx.x * 128;

    float acc[2][8][4];
    #pragma unroll
    for (int i = 0; i < 2; i++)
        #pragma unroll
        for (int j = 0; j < 8; j++)
            #pragma unroll
            for (int kk = 0; kk < 4; kk++) acc[i][j][kk] = 0.f;

    const __half* srcs[2] = { A, B };

    auto load_stage = [&](int stage, int kt) {
        uint32_t base = sb + stage * H_STAGEB;
        int kofs = kt << 6;
        #pragma unroll
        for (int j = 0; j < 8; j++) {
            int lin = t + j * 256;           // 0..2047
            int mtx = lin >> 10;
            int c   = lin & 1023;
            int row = c >> 3, q = c & 7;
            int rbase = (mtx == 0) ? m0 : n0;
            const __half* src = srcs[mtx] + (size_t)(rbase + row) * K + kofs + q * 8;
            cp_async16(base + mtx * MATB + row * ROWB + q * 16, src);
        }
        cp_commit();
    };

    uint32_t aRow = (uint32_t)(wm * 32 + (lane & 15)) * ROWB;
    uint32_t aCol = (uint32_t)((lane >> 4) << 3) * 2;
    uint32_t bRowBase = (uint32_t)(wn * 64 + (lane & 7) + ((lane >> 4) << 3)) * ROWB;
    uint32_t bCol = (uint32_t)(((lane >> 3) & 1) << 3) * 2;

    const int nk = K >> 6;   // K-tiles of 64

    load_stage(0, 0);

    for (int i = 0; i < nk; i++) {
        if (i + 1 < nk) { load_stage((i + 1) & 1, i + 1); cp_wait<1>(); }
        else            { cp_wait<0>(); }
        __syncthreads();

        uint32_t stb = sb + (i & 1) * H_STAGEB;
        uint32_t pA = stb + aRow + aCol;
        uint32_t pB = stb + MATB + bRowBase + bCol;

        #pragma unroll
        for (int ks = 0; ks < 4; ks++) {
            uint32_t ko = ks * 32;          // 16 halves = 32 bytes per k-step
            unsigned af[2][4], bf[8][2];
            #pragma unroll
            for (int mt = 0; mt < 2; mt++) {
                ldsm_x4(af[mt][0], af[mt][1], af[mt][2], af[mt][3],
                        pA + (uint32_t)(mt * 16) * ROWB + ko);
            }
            #pragma unroll
            for (int jp = 0; jp < 4; jp++) {
                ldsm_x4(bf[2*jp][0], bf[2*jp][1], bf[2*jp+1][0], bf[2*jp+1][1],
                        pB + (uint32_t)(jp * 16) * ROWB + ko);
            }
            #pragma unroll
            for (int mt = 0; mt < 2; mt++)
                #pragma unroll
                for (int nt = 0; nt < 8; nt++)
                    mma16816h(acc[mt][nt], af[mt], bf[nt]);
        }
        __syncthreads();
    }

    #pragma unroll
    for (int mt = 0; mt < 2; mt++) {
        #pragma unroll
        for (int nt = 0; nt < 8; nt++) {
            int col = n0 + wn * 64 + nt * 8 + tig * 2;
            float b0 = 0.f, b1v = 0.f;
            if (EPI != 3 && bias) { b0 = bias[col]; b1v = bias[col + 1]; }
            #pragma unroll
            for (int half = 0; half < 2; half++) {
                int row = m0 + wm * 32 + mt * 16 + group + half * 8;
                float v0 = acc[mt][nt][half * 2 + 0] + b0;
                float v1 = acc[mt][nt][half * 2 + 1] + b1v;
                size_t o = (size_t)row * N + col;
                if (EPI == 0) {
                    Cout[o] = v0; Cout[o + 1] = v1;
                } else if (EPI == 1) {
                    Cout[o] = Cin[o] + v0; Cout[o + 1] = Cin[o + 1] + v1;
                } else if (EPI == 2) {
                    float g0 = 0.5f * v0 * (1.0f + erff(v0 * 0.70710678118654752f));
                    float g1 = 0.5f * v1 * (1.0f + erff(v1 * 0.70710678118654752f));
                    __half2 p = __floats2half2_rn(g0, g1);
                    *(uint32_t*)&Oh[o] = *(uint32_t*)&p;
                } else {
                    __half2 p = __floats2half2_rn(v0, v1);
                    *(uint32_t*)&Oh[o] = *(uint32_t*)&p;
                }
            }
        }
    }
}

// ---------------------------------------------------------------------------
// Flash-style HMMA attention. CTA = (64-query tile, b, h); 4 warps x 16 rows.
// K/V tiles of 64 keys, cp.async double-buffered. Online softmax in regs.
// Rows are 64 halves = 128 data bytes; AROWB = 144 (128 + 16 pad).
// ---------------------------------------------------------------------------
#define AROWB 144
#define A_QOFF 0
#define A_TILE (64 * AROWB)            // 9216 bytes per matrix tile
#define A_STG  (2 * A_TILE)            // K+V per stage
#define A_KOFF(s) (A_TILE + (s) * A_STG)
#define A_VOFF(s) (A_TILE + (s) * A_STG + A_TILE)
#define A_SMEM (A_TILE + 2 * A_STG)    // 46080 bytes

__global__ __launch_bounds__(128)
void fattn_kernel(const __half* __restrict__ QKV, __half* __restrict__ O) {
    __shared__ char smem[A_SMEM];
    uint32_t sb = smem_u32(smem);

    int qt = blockIdx.x;               // 0..7 (64-query tiles)
    int bh = blockIdx.y;
    int b  = bh >> 4, h = bh & 15;
    int t  = threadIdx.x;
    int w  = t >> 5, lane = t & 31;
    int group = lane >> 2, tig = lane & 3;

    size_t tokbase = (size_t)(b * SS + qt * 64);

    // ---- prologue: load Q tile + K/V tile 0
    {
        #pragma unroll
        for (int j = 0; j < 4; j++) {      // Q: 512 chunks (64 rows x 8 x 16B)
            int lin = t + j * 128;
            int row = lin >> 3, q = lin & 7;
            const __half* src = QKV + (tokbase + row) * RS + h * DKK + q * 8;
            cp_async16(sb + A_QOFF + row * AROWB + q * 16, src);
        }
        #pragma unroll
        for (int j = 0; j < 8; j++) {      // K,V tile 0: 1024 chunks
            int lin = t + j * 128;
            int mtx = lin >> 9;
            int c   = lin & 511;
            int row = c >> 3, q = c & 7;
            const __half* src = QKV + (size_t)(b * SS + row) * RS + (1 + mtx) * DD + h * DKK + q * 8;
            cp_async16(sb + (mtx == 0 ? A_KOFF(0) : A_VOFF(0)) + row * AROWB + q * 16, src);
        }
        cp_commit();
    }

    // fragment addresses
    uint32_t qAddr = sb + A_QOFF + (uint32_t)(w * 16 + (lane & 15)) * AROWB
                   + (uint32_t)((lane >> 4) << 3) * 2;
    uint32_t kRowSel = (uint32_t)((lane & 7) + ((lane >> 4) << 3)) * AROWB
                     + (uint32_t)(((lane >> 3) & 1) << 3) * 2;
    uint32_t vRowSel = (uint32_t)((lane & 7) + (((lane >> 3) & 1) << 3)) * AROWB
                     + (uint32_t)((lane >> 4) << 3) * 2;

    float oc[8][4];
    #pragma unroll
    for (int i = 0; i < 8; i++)
        #pragma unroll
        for (int j = 0; j < 4; j++) oc[i][j] = 0.f;
    float m0 = -1e30f, m1 = -1e30f, l0 = 0.f, l1 = 0.f;

    const float scale = 0.125f;

    for (int kt = 0; kt <= qt; kt++) {
        if (kt < qt) {
            int s = (kt + 1) & 1;
            #pragma unroll
            for (int j = 0; j < 8; j++) {
                int lin = t + j * 128;
                int mtx = lin >> 9;
                int c   = lin & 511;
                int row = c >> 3, q = c & 7;
                const __half* src = QKV + (size_t)(b * SS + (kt + 1) * 64 + row) * RS
                                  + (1 + mtx) * DD + h * DKK + q * 8;
                cp_async16(sb + (mtx == 0 ? A_KOFF(s) : A_VOFF(s)) + row * AROWB + q * 16, src);
            }
            cp_commit();
            cp_wait<1>();
        } else {
            cp_wait<0>();
        }
        __syncthreads();

        int s = kt & 1;
        uint32_t kBase = sb + A_KOFF(s) + kRowSel;
        uint32_t vBase = sb + A_VOFF(s) + vRowSel;

        // ---- S = Q @ K^T  (16 rows x 64 keys per warp)
        float sc[8][4];
        #pragma unroll
        for (int i = 0; i < 8; i++)
            #pragma unroll
            for (int j = 0; j < 4; j++) sc[i][j] = 0.f;

        unsigned qf[4][4];
        #pragma unroll
        for (int ks = 0; ks < 4; ks++)
            ldsm_x4(qf[ks][0], qf[ks][1], qf[ks][2], qf[ks][3], qAddr + ks * 32);

        #pragma unroll
        for (int jp = 0; jp < 4; jp++) {
            #pragma unroll
            for (int ks = 0; ks < 4; ks++) {
                unsigned b0, b1, b2, b3;
                ldsm_x4(b0, b1, b2, b3, kBase + (uint32_t)(jp * 16) * AROWB + ks * 32);
                unsigned bb0[2] = { b0, b1 }, bb1[2] = { b2, b3 };
                mma16816h(sc[2*jp],     qf[ks], bb0);
                mma16816h(sc[2*jp + 1], qf[ks], bb1);
            }
        }

        // scale + causal mask (diagonal tile only)
        #pragma unroll
        for (int i = 0; i < 8; i++)
            #pragma unroll
            for (int e = 0; e < 4; e++) sc[i][e] *= scale;
        if (kt == qt) {
            #pragma unroll
            for (int i = 0; i < 8; i++) {
                #pragma unroll
                for (int e = 0; e < 4; e++) {
                    int key = i * 8 + 2 * tig + (e & 1);
                    int row = w * 16 + group + ((e >> 1) << 3);
                    if (key > row) sc[i][e] = -1e30f;
                }
            }
        }

        // online softmax (rows group / group+8; reduce over tig lanes)
        float rm0 = -1e30f, rm1 = -1e30f;
        #pragma unroll
        for (int i = 0; i < 8; i++) {
            rm0 = fmaxf(rm0, fmaxf(sc[i][0], sc[i][1]));
            rm1 = fmaxf(rm1, fmaxf(sc[i][2], sc[i][3]));
        }
        rm0 = fmaxf(rm0, __shfl_xor_sync(0xffffffff, rm0, 1));
        rm0 = fmaxf(rm0, __shfl_xor_sync(0xffffffff, rm0, 2));
        rm1 = fmaxf(rm1, __shfl_xor_sync(0xffffffff, rm1, 1));
        rm1 = fmaxf(rm1, __shfl_xor_sync(0xffffffff, rm1, 2));

        float mn0 = fmaxf(m0, rm0), mn1 = fmaxf(m1, rm1);
        float al0 = __expf(m0 - mn0), al1 = __expf(m1 - mn1);

        float rs0 = 0.f, rs1 = 0.f;
        unsigned pa[4][4];
        #pragma unroll
        for (int j = 0; j < 4; j++) {
            float p00 = __expf(sc[2*j][0] - mn0);
            float p01 = __expf(sc[2*j][1] - mn0);
            float p10 = __expf(sc[2*j][2] - mn1);
            float p11 = __expf(sc[2*j][3] - mn1);
            float q00 = __expf(sc[2*j+1][0] - mn0);
            float q01 = __expf(sc[2*j+1][1] - mn0);
            float q10 = __expf(sc[2*j+1][2] - mn1);
            float q11 = __expf(sc[2*j+1][3] - mn1);
            rs0 += p00 + p01 + q00 + q01;
            rs1 += p10 + p11 + q10 + q11;
            __half2 h0 = __floats2half2_rn(p00, p01);
            __half2 h1 = __floats2half2_rn(p10, p11);
            __half2 h2 = __floats2half2_rn(q00, q01);
            __half2 h3 = __floats2half2_rn(q10, q11);
            pa[j][0] = *(unsigned*)&h0;
            pa[j][1] = *(unsigned*)&h1;
            pa[j][2] = *(unsigned*)&h2;
            pa[j][3] = *(unsigned*)&h3;
        }
        rs0 += __shfl_xor_sync(0xffffffff, rs0, 1);
        rs0 += __shfl_xor_sync(0xffffffff, rs0, 2);
        rs1 += __shfl_xor_sync(0xffffffff, rs1, 1);
        rs1 += __shfl_xor_sync(0xffffffff, rs1, 2);

        l0 = l0 * al0 + rs0;
        l1 = l1 * al1 + rs1;
        m0 = mn0; m1 = mn1;

        #pragma unroll
        for (int i = 0; i < 8; i++) {
            oc[i][0] *= al0; oc[i][1] *= al0;
            oc[i][2] *= al1; oc[i][3] *= al1;
        }

        // ---- O += P @ V   (V^T fragments via ldmatrix.trans)
        #pragma unroll
        for (int j = 0; j < 4; j++) {
            #pragma unroll
            for (int np = 0; np < 4; np++) {
                unsigned v0, v1, v2, v3;
                ldsm_x4_t(v0, v1, v2, v3,
                          vBase + (uint32_t)(j * 16) * AROWB + (uint32_t)(np * 16) * 2);
                unsigned vv0[2] = { v0, v1 }, vv1[2] = { v2, v3 };
                mma16816h(oc[2*np],     pa[j], vv0);
                mma16816h(oc[2*np + 1], pa[j], vv1);
            }
        }
        __syncthreads();
    }

    // ---- write output (fp16)
    float inv0 = 1.0f / l0, inv1 = 1.0f / l1;
    size_t r0 = (tokbase + w * 16 + group) * DD + h * DKK;
    size_t r1 = r0 + 8 * DD;
    #pragma unroll
    for (int i = 0; i < 8; i++) {
        int col = i * 8 + 2 * tig;
        __half2 o0 = __floats2half2_rn(oc[i][0] * inv0, oc[i][1] * inv0);
        __half2 o1 = __floats2half2_rn(oc[i][2] * inv1, oc[i][3] * inv1);
        *(uint32_t*)&O[r0 + col] = *(uint32_t*)&o0;
        *(uint32_t*)&O[r1 + col] = *(uint32_t*)&o1;
    }
}

// ---------------------------------------------------------------------------
// Launch
// ---------------------------------------------------------------------------
extern "C" void kernel_launch(void* const* d_in, const int* in_sizes, int n_in,
                              void* d_out, int out_size) {
    (void)in_sizes; (void)n_in; (void)out_size;

    const int*   ids  = (const int*)  d_in[0];
    const float* emb  = (const float*)d_in[1];
    const float* pe   = (const float*)d_in[2];
    const float* Wq   = (const float*)d_in[3];
    const float* Wk   = (const float*)d_in[4];
    const float* Wv   = (const float*)d_in[5];
    const float* Wo   = (const float*)d_in[6];
    const float* bo   = (const float*)d_in[7];
    const float* ln1s = (const float*)d_in[8];
    const float* ln1b = (const float*)d_in[9];
    const float* ln2s = (const float*)d_in[10];
    const float* ln2b = (const float*)d_in[11];
    const float* W1   = (const float*)d_in[12];
    const float* b1   = (const float*)d_in[13];
    const float* W2   = (const float*)d_in[14];
    const float* b2   = (const float*)d_in[15];
    const float* lnfs = (const float*)d_in[16];
    const float* lnfb = (const float*)d_in[17];
    float* out = (float*)d_out;

    float *x;
    __half *qkv, *hf, *af, *ff, *ef, *wf;
    cudaGetSymbolAddress((void**)&x,   g_x);
    cudaGetSymbolAddress((void**)&qkv, g_qkv);
    cudaGetSymbolAddress((void**)&hf,  g_hf);
    cudaGetSymbolAddress((void**)&af,  g_af);
    cudaGetSymbolAddress((void**)&ff,  g_ff);
    cudaGetSymbolAddress((void**)&ef,  g_ef);
    cudaGetSymbolAddress((void**)&wf,  g_wf);

    cudaFuncSetAttribute(gemm_f16<0>, cudaFuncAttributeMaxDynamicSharedMemorySize, SMEM_F16);
    cudaFuncSetAttribute(gemm_f16<1>, cudaFuncAttributeMaxDynamicSharedMemorySize, SMEM_F16);
    cudaFuncSetAttribute(gemm_f16<2>, cudaFuncAttributeMaxDynamicSharedMemorySize, SMEM_F16);
    cudaFuncSetAttribute(gemm_f16<3>, cudaFuncAttributeMaxDynamicSharedMemorySize, SMEM_F16);

    dim3 tb32(32, 8);
    {
        dim3 gQ(DD / 32, DD / 32, LL * 4);
        whalf_qkvo_kernel<<<gQ, tb32>>>(Wq, Wk, Wv, Wo, wf);
        dim3 g1(FFD / 32, DD / 32, LL);
        whalf_ff_kernel<<<g1, tb32>>>(W1, wf, DD, FFD, (size_t)4 * DD * DD);
        dim3 g2(DD / 32, FFD / 32, LL);
        whalf_ff_kernel<<<g2, tb32>>>(W2, wf, FFD, DD, (size_t)4 * DD * DD + (size_t)DD * FFD);
    }
    {
        int n4 = (VV * DD) / 4;
        ehalf_kernel<<<(n4 + 255) / 256, 256>>>(emb, ef, n4);
    }

    embed_kernel<<<NTOK, 256>>>(ids, emb, pe, x);

    dim3 gQKV(3 * DD / 128, NTOK / 128);  // 24 x 16
    dim3 gD(DD / 128, NTOK / 128);        // 8 x 16
    dim3 gF(FFD / 128, NTOK / 128);       // 32 x 16
    dim3 gV(VV / 128, NTOK / 128);        // 250 x 16
    dim3 gA(SS / 64, BB * HH);            // 8 x 64

    for (int l = 0; l < LL; l++) {
        __half* wqkv = wf + (size_t)l * WLAYER;         // [3*DD][DD]
        __half* wo   = wqkv + 3 * DD * DD;              // [DD][DD]
        __half* w1   = wo + DD * DD;                    // [FFD][DD]
        __half* w2   = w1 + (size_t)DD * FFD;           // [DD][FFD]

        ln_f16_kernel<<<NTOK, 256>>>(x, ln1s + l * DD, ln1b + l * DD, hf);
        gemm_f16<3><<<gQKV, 256, SMEM_F16>>>(hf, wqkv, nullptr, nullptr, nullptr, qkv, NTOK, 3 * DD, DD);
        fattn_kernel<<<gA, 128>>>(qkv, af);
        gemm_f16<1><<<gD, 256, SMEM_F16>>>(af, wo, bo + l * DD, x, x, nullptr, NTOK, DD, DD);

        ln_f16_kernel<<<NTOK, 256>>>(x, ln2s + l * DD, ln2b + l * DD, hf);
        gemm_f16<2><<<gF, 256, SMEM_F16>>>(hf, w1, b1 + l * FFD, nullptr, nullptr, ff, NTOK, FFD, DD);
        gemm_f16<1><<<gD, 256, SMEM_F16>>>(ff, w2, b2 + l * DD, x, x, nullptr, NTOK, DD, FFD);
    }

    ln_f16_kernel<<<NTOK, 256>>>(x, lnfs, lnfb, hf);
    gemm_f16<0><<<gV, 256, SMEM_F16>>>(hf, ef, nullptr, nullptr, out, nullptr, NTOK, VV, DD);
}